// round 1
// baseline (speedup 1.0000x reference)
#include <cuda_runtime.h>

#define NB 512

// ---------------- device scratch (no allocations allowed) ----------------
__device__ float g_wt1[81 * 256];              // conv1 w: [tap][oc]
__device__ float g_wt2[256 * 81 * 256];        // conv2 w: [ic][tap][oc]
__device__ float g_d2t[512 * 1024];            // d2_w^T: [j][k]
__device__ float g_d3t[1024 * 784];            // d3_w^T: [k][r]
__device__ float g_c1[(size_t)NB * 256 * 400]; // conv1 out (b, oc, 20, 20)
__device__ float g_pose[(size_t)NB * 9216];    // conv2 out flat (b, oc*36+s)
__device__ float g_u[(size_t)NB * 9216];       // squashed capsules (b, 1152, 8)
__device__ float g_v[(size_t)NB * 160];        // routed v (b, 10, 16)

// ---------------- weight re-layout ----------------
__global__ void k_prep(const float* __restrict__ w1, const float* __restrict__ w2,
                       const float* __restrict__ d2w, const float* __restrict__ d3w) {
    int i = blockIdx.x * blockDim.x + threadIdx.x;
    if (i < 81 * 256) {
        int k = i / 256, oc = i % 256;
        g_wt1[i] = w1[oc * 81 + k];
    }
    if (i < 256 * 81 * 256) {
        int oc = i % 256;
        int rest = i / 256;
        int k = rest % 81;
        int ic = rest / 81;
        g_wt2[i] = w2[(oc * 256 + ic) * 81 + k];
    }
    if (i < 512 * 1024) {
        int k = i % 1024, j = i / 1024;
        g_d2t[i] = d2w[k * 512 + j];
    }
    if (i < 1024 * 784) {
        int r = i % 784, k = i / 784;
        g_d3t[i] = d3w[r * 1024 + k];
    }
}

// ---------------- conv1: (B,1,28,28) -> relu((B,256,20,20)+b) ----------------
// block = (oy, b), 256 threads = oc
__global__ __launch_bounds__(256) void k_conv1(const float* __restrict__ x,
                                               const float* __restrict__ b1) {
    __shared__ float xs[784];
    __shared__ float sout[256 * 21];  // pad 21 to kill bank conflicts
    int b = blockIdx.y, oy = blockIdx.x, oc = threadIdx.x;
    const float* xp = x + (size_t)b * 784;
    for (int i = oc; i < 784; i += 256) xs[i] = xp[i];
    __syncthreads();

    float acc[20];
#pragma unroll
    for (int i = 0; i < 20; i++) acc[i] = 0.f;

#pragma unroll
    for (int ky = 0; ky < 9; ky++) {
        float w[9];
#pragma unroll
        for (int kx = 0; kx < 9; kx++) w[kx] = g_wt1[(ky * 9 + kx) * 256 + oc];
        const float* row = &xs[(oy + ky) * 28];
        float in[28];
#pragma unroll
        for (int i = 0; i < 28; i++) in[i] = row[i];
#pragma unroll
        for (int kx = 0; kx < 9; kx++)
#pragma unroll
            for (int ox = 0; ox < 20; ox++) acc[ox] += in[ox + kx] * w[kx];
    }
    float bias = b1[oc];
#pragma unroll
    for (int ox = 0; ox < 20; ox++) {
        float v = acc[ox] + bias;
        sout[oc * 21 + ox] = v > 0.f ? v : 0.f;
    }
    __syncthreads();
    // coalesced-ish staged write: (b, oc, oy, ox)
    float* dst = g_c1 + (size_t)b * 102400 + oy * 20;
    for (int l = oc; l < 5120; l += 256) {
        int o = l / 20, xo = l % 20;
        dst[o * 400 + xo] = sout[o * 21 + xo];
    }
}

// ---------------- conv2: (B,256,20,20) -> (B,256,6,6)+b, stride 2 ----------------
// block = (oc_tile of 64, b); 384 threads = 64 oc x 6 oy; each thread 6 outputs (ox)
#define ICC 8
__global__ __launch_bounds__(384) void k_conv2(const float* __restrict__ b2) {
    __shared__ float ins[ICC * 400];
    __shared__ float sout[2304];
    int b = blockIdx.y;
    int ocb = blockIdx.x * 64;
    int tid = threadIdx.x;
    int ocl = tid & 63, oy = tid >> 6;
    float acc[6] = {0.f, 0.f, 0.f, 0.f, 0.f, 0.f};
    const float* src = g_c1 + (size_t)b * 102400;

    for (int ic0 = 0; ic0 < 256; ic0 += ICC) {
        __syncthreads();
        const float4* s4 = (const float4*)(src + ic0 * 400);
        float4* d4 = (float4*)ins;
        for (int l = tid; l < ICC * 100; l += 384) d4[l] = s4[l];
        __syncthreads();
        for (int icl = 0; icl < ICC; icl++) {
            const float* wrow = g_wt2 + ((ic0 + icl) * 81) * 256 + ocb + ocl;
            const float* irow = ins + icl * 400 + oy * 40;
#pragma unroll
            for (int ky = 0; ky < 9; ky++) {
                float w[9];
#pragma unroll
                for (int kx = 0; kx < 9; kx++) w[kx] = wrow[(ky * 9 + kx) * 256];
                const float* r = irow + ky * 20;
                float in[19];
#pragma unroll
                for (int i = 0; i < 19; i++) in[i] = r[i];
#pragma unroll
                for (int kx = 0; kx < 9; kx++)
#pragma unroll
                    for (int ox = 0; ox < 6; ox++) acc[ox] += in[2 * ox + kx] * w[kx];
            }
        }
    }
    float bias = b2[ocb + ocl];
#pragma unroll
    for (int ox = 0; ox < 6; ox++) sout[ocl * 36 + oy * 6 + ox] = acc[ox] + bias;
    __syncthreads();
    float4* dst = (float4*)(g_pose + (size_t)b * 9216 + ocb * 36);
    const float4* s = (const float4*)sout;
    for (int l = tid; l < 576; l += 384) dst[l] = s[l];
}

// ---------------- squash over d=8 ----------------
__global__ void k_squash() {
    int i = blockIdx.x * blockDim.x + threadIdx.x;
    if (i >= NB * 1152) return;
    const float4* p = ((const float4*)g_pose) + (size_t)i * 2;
    float4 a = p[0], c = p[1];
    float sq = a.x * a.x + a.y * a.y + a.z * a.z + a.w * a.w +
               c.x * c.x + c.y * c.y + c.z * c.z + c.w * c.w;
    float sc = sq / ((1.f + sq) * sqrtf(sq + 1e-8f));
    a.x *= sc; a.y *= sc; a.z *= sc; a.w *= sc;
    c.x *= sc; c.y *= sc; c.z *= sc; c.w *= sc;
    float4* o = ((float4*)g_u) + (size_t)i * 2;
    o[0] = a; o[1] = c;
}

// ---------------- dynamic routing: one block per (b, class) ----------------
// smem: u(9216) + u_hat(18432) + b(1152) + c(1152) + scratch = 121088 B
__global__ __launch_bounds__(256) void k_route(const float* __restrict__ W) {
    extern __shared__ float sm[];
    float* u_s = sm;             // 9216
    float* uh  = sm + 9216;      // 18432
    float* bl  = uh + 18432;     // 1152
    float* cl  = bl + 1152;      // 1152
    float* sp  = cl + 1152;      // 256
    float* red = sp + 256;       // 32
    float* sv  = red + 32;       // 16
    float* vs  = sv + 16;        // 16
    int tid = threadIdx.x;
    int c = blockIdx.x, b = blockIdx.y;
    int lane = tid & 31, wid = tid >> 5;

    const float4* usrc = (const float4*)(g_u + (size_t)b * 9216);
    float4* ud = (float4*)u_s;
    for (int l = tid; l < 2304; l += 256) ud[l] = usrc[l];
    for (int n = tid; n < 1152; n += 256) bl[n] = 0.f;
    __syncthreads();

    // u_hat[n][e] = sum_d u[n][d] * W[c][n][d][e]  (float4 over e)
    float4* uh4 = (float4*)uh;
    const float4* Wb = (const float4*)(W + (size_t)c * 1152 * 128);
    for (int q = tid; q < 4608; q += 256) {
        int n = q >> 2, e4 = q & 3;
        const float4* Wn = Wb + n * 32 + e4;
        const float* un = u_s + n * 8;
        float4 a = {0.f, 0.f, 0.f, 0.f};
#pragma unroll
        for (int d = 0; d < 8; d++) {
            float4 wv = Wn[d * 4];
            float uu = un[d];
            a.x += uu * wv.x; a.y += uu * wv.y; a.z += uu * wv.z; a.w += uu * wv.w;
        }
        uh4[q] = a;
    }
    __syncthreads();

    for (int it = 0; it < 3; it++) {
        // softmax over n of bl (unnormalized exps in cl; fold 1/S into s)
        float m = -1e30f;
        for (int n = tid; n < 1152; n += 256) m = fmaxf(m, bl[n]);
#pragma unroll
        for (int o = 16; o > 0; o >>= 1) m = fmaxf(m, __shfl_xor_sync(0xffffffffu, m, o));
        if (lane == 0) red[wid] = m;
        __syncthreads();
        if (tid == 0) {
            float t = red[0];
            for (int i = 1; i < 8; i++) t = fmaxf(t, red[i]);
            red[16] = t;
        }
        __syncthreads();
        m = red[16];
        float ps = 0.f;
        for (int n = tid; n < 1152; n += 256) {
            float e = expf(bl[n] - m);
            cl[n] = e;
            ps += e;
        }
#pragma unroll
        for (int o = 16; o > 0; o >>= 1) ps += __shfl_xor_sync(0xffffffffu, ps, o);
        if (lane == 0) red[wid] = ps;
        __syncthreads();
        if (tid == 0) {
            float t = 0.f;
            for (int i = 0; i < 8; i++) t += red[i];
            red[17] = t;
        }
        __syncthreads();
        float invS = 1.f / red[17];

        // s[e] = (1/S) * sum_n cl[n] * uh[n][e]
        int e = tid & 15, g = tid >> 4;
        float part = 0.f;
        for (int n = g; n < 1152; n += 16) part += cl[n] * uh[n * 16 + e];
        sp[tid] = part;
        __syncthreads();
        if (tid < 16) {
            float t = 0.f;
            for (int gg = 0; gg < 16; gg++) t += sp[gg * 16 + tid];
            sv[tid] = t * invS;
        }
        __syncthreads();
        if (tid == 0) {
            float sq = 0.f;
            for (int i = 0; i < 16; i++) sq += sv[i] * sv[i];
            red[18] = sq / ((1.f + sq) * sqrtf(sq + 1e-8f));
        }
        __syncthreads();
        if (tid < 16) vs[tid] = sv[tid] * red[18];
        __syncthreads();

        if (it < 2) {
            const float4* vv = (const float4*)vs;
            float4 v0 = vv[0], v1 = vv[1], v2 = vv[2], v3 = vv[3];
            for (int n = tid; n < 1152; n += 256) {
                const float4* u4 = uh4 + n * 4;
                float4 a = u4[0], bq = u4[1], cq = u4[2], dq = u4[3];
                float dot = a.x * v0.x + a.y * v0.y + a.z * v0.z + a.w * v0.w +
                            bq.x * v1.x + bq.y * v1.y + bq.z * v1.z + bq.w * v1.w +
                            cq.x * v2.x + cq.y * v2.y + cq.z * v2.z + cq.w * v2.w +
                            dq.x * v3.x + dq.y * v3.y + dq.z * v3.z + dq.w * v3.w;
                bl[n] += dot;
            }
            __syncthreads();
        }
    }
    if (tid < 16) g_v[((size_t)b * 10 + c) * 16 + tid] = vs[tid];
}

// ---------------- class probs + masked decoder, 4 batches per block ----------------
__global__ __launch_bounds__(256) void k_dec(const float* __restrict__ d1w,
                                             const float* __restrict__ d1b,
                                             const float* __restrict__ d2b,
                                             const float* __restrict__ d3b,
                                             float* __restrict__ out) {
    __shared__ __align__(16) float v_s[4][160];
    __shared__ __align__(16) float h1s[4][512];
    __shared__ __align__(16) float h2s[4][1024];
    __shared__ float nrm[4][10];
    __shared__ float cps[4][10];
    __shared__ int args[4];
    int tid = threadIdx.x;
    int b0 = blockIdx.x * 4;

    for (int bb = 0; bb < 4; bb++)
        for (int i = tid; i < 160; i += 256) v_s[bb][i] = g_v[(size_t)(b0 + bb) * 160 + i];
    __syncthreads();

    if (tid < 40) {
        int bb = tid / 10, c = tid % 10;
        float s = 0.f;
#pragma unroll
        for (int e = 0; e < 16; e++) {
            float t = v_s[bb][c * 16 + e];
            s += t * t;
        }
        nrm[bb][c] = sqrtf(s);
    }
    __syncthreads();
    if (tid < 4) {
        int bb = tid;
        float m = -1e30f;
        int a = 0;
        for (int c = 0; c < 10; c++)
            if (nrm[bb][c] > m) { m = nrm[bb][c]; a = c; }
        args[bb] = a;
        float ex[10], s = 0.f;
        for (int c = 0; c < 10; c++) { ex[c] = expf(nrm[bb][c] - m); s += ex[c]; }
        for (int c = 0; c < 10; c++) cps[bb][c] = ex[c] / s;
    }
    __syncthreads();
    if (tid < 40) {
        int bb = tid / 10, c = tid % 10;
        out[(size_t)(b0 + bb) * 10 + c] = cps[bb][c];
    }

    // h1 = relu(masked @ d1_w^T + d1_b): only 16 nonzero inputs (argmax class)
    for (int bb = 0; bb < 4; bb++) {
        int a = args[bb];
        const float* vp = &v_s[bb][a * 16];
        for (int j = tid; j < 512; j += 256) {
            const float* wp = d1w + (size_t)j * 160 + a * 16;
            float acc = d1b[j];
#pragma unroll
            for (int e = 0; e < 16; e++) acc += vp[e] * wp[e];
            h1s[bb][j] = fmaxf(acc, 0.f);
        }
    }
    __syncthreads();

    int w = tid >> 5, lane = tid & 31;
    // h2 = relu(h1 @ d2_w^T + d2_b); lanes own 4 consecutive k, warp covers 128 k
    {
        int k0 = w * 128 + lane * 4;
        float acc[4][4];
#pragma unroll
        for (int bb = 0; bb < 4; bb++)
#pragma unroll
            for (int kk = 0; kk < 4; kk++) acc[bb][kk] = 0.f;
        for (int j = 0; j < 512; j += 4) {
            float4 w0 = *(const float4*)(g_d2t + (size_t)(j + 0) * 1024 + k0);
            float4 w1 = *(const float4*)(g_d2t + (size_t)(j + 1) * 1024 + k0);
            float4 w2 = *(const float4*)(g_d2t + (size_t)(j + 2) * 1024 + k0);
            float4 w3 = *(const float4*)(g_d2t + (size_t)(j + 3) * 1024 + k0);
#pragma unroll
            for (int bb = 0; bb < 4; bb++) {
                float4 hv = *(const float4*)&h1s[bb][j];
                acc[bb][0] += hv.x * w0.x + hv.y * w1.x + hv.z * w2.x + hv.w * w3.x;
                acc[bb][1] += hv.x * w0.y + hv.y * w1.y + hv.z * w2.y + hv.w * w3.y;
                acc[bb][2] += hv.x * w0.z + hv.y * w1.z + hv.z * w2.z + hv.w * w3.z;
                acc[bb][3] += hv.x * w0.w + hv.y * w1.w + hv.z * w2.w + hv.w * w3.w;
            }
        }
        float bk0 = d2b[k0], bk1 = d2b[k0 + 1], bk2 = d2b[k0 + 2], bk3 = d2b[k0 + 3];
#pragma unroll
        for (int bb = 0; bb < 4; bb++) {
            h2s[bb][k0 + 0] = fmaxf(acc[bb][0] + bk0, 0.f);
            h2s[bb][k0 + 1] = fmaxf(acc[bb][1] + bk1, 0.f);
            h2s[bb][k0 + 2] = fmaxf(acc[bb][2] + bk2, 0.f);
            h2s[bb][k0 + 3] = fmaxf(acc[bb][3] + bk3, 0.f);
        }
    }
    __syncthreads();

    // recons = sigmoid(h2 @ d3_w^T + d3_b)
    {
        int r0 = w * 128 + lane * 4;
        if (r0 < 784) {
            float acc[4][4];
#pragma unroll
            for (int bb = 0; bb < 4; bb++)
#pragma unroll
                for (int kk = 0; kk < 4; kk++) acc[bb][kk] = 0.f;
            for (int k = 0; k < 1024; k += 4) {
                float4 w0 = *(const float4*)(g_d3t + (size_t)(k + 0) * 784 + r0);
                float4 w1 = *(const float4*)(g_d3t + (size_t)(k + 1) * 784 + r0);
                float4 w2 = *(const float4*)(g_d3t + (size_t)(k + 2) * 784 + r0);
                float4 w3 = *(const float4*)(g_d3t + (size_t)(k + 3) * 784 + r0);
#pragma unroll
                for (int bb = 0; bb < 4; bb++) {
                    float4 hv = *(const float4*)&h2s[bb][k];
                    acc[bb][0] += hv.x * w0.x + hv.y * w1.x + hv.z * w2.x + hv.w * w3.x;
                    acc[bb][1] += hv.x * w0.y + hv.y * w1.y + hv.z * w2.y + hv.w * w3.y;
                    acc[bb][2] += hv.x * w0.z + hv.y * w1.z + hv.z * w2.z + hv.w * w3.z;
                    acc[bb][3] += hv.x * w0.w + hv.y * w1.w + hv.z * w2.w + hv.w * w3.w;
                }
            }
            float b0r = d3b[r0], b1r = d3b[r0 + 1], b2r = d3b[r0 + 2], b3r = d3b[r0 + 3];
#pragma unroll
            for (int bb = 0; bb < 4; bb++) {
                float4 o;
                o.x = 1.f / (1.f + expf(-(acc[bb][0] + b0r)));
                o.y = 1.f / (1.f + expf(-(acc[bb][1] + b1r)));
                o.z = 1.f / (1.f + expf(-(acc[bb][2] + b2r)));
                o.w = 1.f / (1.f + expf(-(acc[bb][3] + b3r)));
                *(float4*)(out + 5120 + (size_t)(b0 + bb) * 784 + r0) = o;
            }
        }
    }
}

// ---------------- launch ----------------
extern "C" void kernel_launch(void* const* d_in, const int* in_sizes, int n_in,
                              void* d_out, int out_size) {
    const float* x   = (const float*)d_in[0];
    const float* w1  = (const float*)d_in[1];
    const float* b1  = (const float*)d_in[2];
    const float* w2  = (const float*)d_in[3];
    const float* b2  = (const float*)d_in[4];
    const float* W   = (const float*)d_in[5];
    const float* d1w = (const float*)d_in[6];
    const float* d1b = (const float*)d_in[7];
    const float* d2b = (const float*)d_in[9];
    const float* d3b = (const float*)d_in[11];
    float* out = (float*)d_out;
    (void)in_sizes; (void)n_in; (void)out_size;

    const int route_smem = 30272 * 4;  // 121088 B
    cudaFuncSetAttribute(k_route, cudaFuncAttributeMaxDynamicSharedMemorySize, route_smem);

    k_prep<<<20736, 256>>>(w1, w2, (const float*)d_in[8], (const float*)d_in[10]);
    k_conv1<<<dim3(20, 512), 256>>>(x, b1);
    k_conv2<<<dim3(4, 512), 384>>>(b2);
    k_squash<<<2304, 256>>>();
    k_route<<<dim3(10, 512), 256, route_smem>>>(W);
    k_dec<<<128, 256>>>(d1w, d1b, d2b, d3b, out);
}

// round 3
// speedup vs baseline: 2.4689x; 2.4689x over previous
#include <cuda_runtime.h>
#include <cuda_bf16.h>
#include <cstdint>

#define NB 512

// ---------------- device scratch ----------------
__device__ float g_wt1[81 * 256];                              // conv1 w: [tap][oc]
__device__ __align__(128) __nv_bfloat16 g_w2h[256 * 81 * 256]; // conv2 w hi: [oc][tap][ic]
__device__ __align__(128) __nv_bfloat16 g_w2l[256 * 81 * 256]; // conv2 w lo
__device__ float g_d2t[512 * 1024];                            // d2_w^T
__device__ float g_d3t[1024 * 784];                            // d3_w^T
__device__ __align__(128) __nv_bfloat16 g_c1h[(size_t)400 * 512 * 256]; // conv1 out hi: [pix][b][ic]
__device__ __align__(128) __nv_bfloat16 g_c1l[(size_t)400 * 512 * 256]; // conv1 out lo
__device__ float g_pose2[(size_t)9216 * 512];                  // conv2 out: [oc*36+s][b]
__device__ float g_u[(size_t)NB * 9216];                       // squashed: [b][n][d]
__device__ float g_uhat[(size_t)10 * 512 * 18432];             // [c][b][n*16+e]
__device__ float g_v[(size_t)NB * 160];                        // [b][c][e]

// ---------------- helpers ----------------
__device__ __forceinline__ uint32_t smem_u32(const void* p) {
    uint32_t a;
    asm("{ .reg .u64 t; cvta.to.shared.u64 t, %1; cvt.u32.u64 %0, t; }" : "=r"(a) : "l"(p));
    return a;
}
__device__ __forceinline__ void cpa16(uint32_t dst, const __nv_bfloat16* src) {
    asm volatile("cp.async.cg.shared.global [%0], [%1], 16;" :: "r"(dst), "l"(__cvta_generic_to_global(src)));
}
#define CP_COMMIT() asm volatile("cp.async.commit_group;" ::: "memory")
#define CP_WAIT2()  asm volatile("cp.async.wait_group 2;" ::: "memory")

__device__ __forceinline__ void ldm4(uint32_t* r, uint32_t addr) {
    asm volatile("ldmatrix.sync.aligned.m8n8.x4.shared.b16 {%0,%1,%2,%3}, [%4];"
                 : "=r"(r[0]), "=r"(r[1]), "=r"(r[2]), "=r"(r[3]) : "r"(addr));
}
__device__ __forceinline__ void mma_bf16(float* c, const uint32_t* a, const uint32_t* b) {
    asm volatile("mma.sync.aligned.m16n8k16.row.col.f32.bf16.bf16.f32 "
                 "{%0,%1,%2,%3}, {%4,%5,%6,%7}, {%8,%9}, {%0,%1,%2,%3};"
                 : "+f"(c[0]), "+f"(c[1]), "+f"(c[2]), "+f"(c[3])
                 : "r"(a[0]), "r"(a[1]), "r"(a[2]), "r"(a[3]), "r"(b[0]), "r"(b[1]));
}

// ---------------- weight re-layout + hi/lo split ----------------
__global__ void k_prep(const float* __restrict__ w1, const float* __restrict__ w2,
                       const float* __restrict__ d2w, const float* __restrict__ d3w) {
    int i = blockIdx.x * blockDim.x + threadIdx.x;
    if (i < 81 * 256) {
        int k = i / 256, oc = i % 256;
        g_wt1[i] = w1[oc * 81 + k];
    }
    if (i < 256 * 81 * 256) {
        int ic = i % 256;
        int tap = (i / 256) % 81;
        int oc = i / (256 * 81);
        float v = w2[((size_t)oc * 256 + ic) * 81 + tap];
        __nv_bfloat16 h = __float2bfloat16(v);
        g_w2h[i] = h;
        g_w2l[i] = __float2bfloat16(v - __bfloat162float(h));
    }
    if (i < 512 * 1024) {
        int k = i % 1024, j = i / 1024;
        g_d2t[i] = d2w[k * 512 + j];
    }
    if (i < 1024 * 784) {
        int r = i % 784, k = i / 784;
        g_d3t[i] = d3w[r * 1024 + k];
    }
}

// ---------------- conv1: (B,1,28,28) -> relu -> bf16 hi/lo [pix][b][oc] ----------------
__global__ __launch_bounds__(256) void k_conv1(const float* __restrict__ x,
                                               const float* __restrict__ b1) {
    __shared__ float xs[784];
    int b = blockIdx.y, oy = blockIdx.x, oc = threadIdx.x;
    const float* xp = x + (size_t)b * 784;
    for (int i = oc; i < 784; i += 256) xs[i] = xp[i];
    __syncthreads();

    float acc[20];
#pragma unroll
    for (int i = 0; i < 20; i++) acc[i] = 0.f;
#pragma unroll
    for (int ky = 0; ky < 9; ky++) {
        float w[9];
#pragma unroll
        for (int kx = 0; kx < 9; kx++) w[kx] = g_wt1[(ky * 9 + kx) * 256 + oc];
        const float* row = &xs[(oy + ky) * 28];
        float in[28];
#pragma unroll
        for (int i = 0; i < 28; i++) in[i] = row[i];
#pragma unroll
        for (int kx = 0; kx < 9; kx++)
#pragma unroll
            for (int ox = 0; ox < 20; ox++) acc[ox] += in[ox + kx] * w[kx];
    }
    float bias = b1[oc];
#pragma unroll
    for (int ox = 0; ox < 20; ox++) {
        float v = acc[ox] + bias;
        v = v > 0.f ? v : 0.f;
        __nv_bfloat16 h = __float2bfloat16(v);
        __nv_bfloat16 l = __float2bfloat16(v - __bfloat162float(h));
        size_t idx = ((size_t)(oy * 20 + ox) * 512 + b) * 256 + oc;
        g_c1h[idx] = h;
        g_c1l[idx] = l;
    }
}

// ---------------- conv2 via mma.sync bf16x3 ----------------
// per s: D[oc(128 tile), b(128 tile)] = sum_{tap,ic} W * X
// 648 k-stages of 32 ic; 3-stage cp.async pipeline; smem 3*32KB
#define C2_STAGES 648
#define OFF_AH 0
#define OFF_AL 8192
#define OFF_BH 16384
#define OFF_BL 24576
#define C2_STAGE_BYTES 32768
#define CONV2_SMEM (3 * C2_STAGE_BYTES)

__device__ __forceinline__ void c2_load(uint32_t sb, int i, int oc0, int bb0,
                                        int oy, int ox, int tid) {
    const int tap = i >> 3, icc = i & 7, ic0 = icc * 32;
    const int ky = tap / 9, kx = tap % 9;
    const int pix = (2 * oy + ky) * 20 + 2 * ox + kx;
#pragma unroll
    for (int rep = 0; rep < 2; rep++) {
        int q = tid + rep * 256;
        int row = q >> 2, c = q & 3;
        uint32_t soff = row * 64 + ((c ^ ((row >> 1) & 3)) * 16);
        size_t aoff = (size_t)(oc0 + row) * 20736 + tap * 256 + ic0 + c * 8;
        cpa16(sb + OFF_AH + soff, g_w2h + aoff);
        cpa16(sb + OFF_AL + soff, g_w2l + aoff);
        size_t boff = ((size_t)pix * 512 + bb0 + row) * 256 + ic0 + c * 8;
        cpa16(sb + OFF_BH + soff, g_c1h + boff);
        cpa16(sb + OFF_BL + soff, g_c1l + boff);
    }
}

__global__ __launch_bounds__(256, 1) void k_conv2mma(const float* __restrict__ b2) {
    extern __shared__ __align__(1024) char smem[];
    const uint32_t sbase = smem_u32(smem);
    const int tid = threadIdx.x;
    const int wid = tid >> 5, lane = tid & 31;
    const int oc0 = (blockIdx.x >> 2) * 128;
    const int bb0 = (blockIdx.x & 3) * 128;
    const int s = blockIdx.y;
    const int oy = s / 6, ox = s % 6;
    const int warpm = wid >> 2, warpn = wid & 3;

    float acc[4][4][4];
#pragma unroll
    for (int m = 0; m < 4; m++)
#pragma unroll
        for (int n = 0; n < 4; n++)
#pragma unroll
            for (int k = 0; k < 4; k++) acc[m][n][k] = 0.f;

    // precompute ldmatrix offsets (lane-dependent)
    uint32_t offA[4][2], offB[2][2];
#pragma unroll
    for (int m = 0; m < 4; m++)
#pragma unroll
        for (int kk = 0; kk < 2; kk++) {
            int row = warpm * 64 + m * 16 + (lane & 15);
            int lc = 2 * kk + (lane >> 4);
            offA[m][kk] = row * 64 + ((lc ^ ((row >> 1) & 3)) * 16);
        }
#pragma unroll
    for (int p = 0; p < 2; p++)
#pragma unroll
        for (int kk = 0; kk < 2; kk++) {
            int row = warpn * 32 + p * 16 + (lane & 7) + ((lane >> 4) & 1) * 8;
            int lc = 2 * kk + ((lane >> 3) & 1);
            offB[p][kk] = row * 64 + ((lc ^ ((row >> 1) & 3)) * 16);
        }

    c2_load(sbase, 0, oc0, bb0, oy, ox, tid);
    CP_COMMIT();
    c2_load(sbase + C2_STAGE_BYTES, 1, oc0, bb0, oy, ox, tid);
    CP_COMMIT();

    uint32_t bufs[3] = {sbase, sbase + C2_STAGE_BYTES, sbase + 2 * C2_STAGE_BYTES};
    int ld = 2, cp = 0;
    for (int i = 0; i < C2_STAGES; i++) {
        if (i + 2 < C2_STAGES) c2_load(bufs[ld], i + 2, oc0, bb0, oy, ox, tid);
        CP_COMMIT();
        CP_WAIT2();
        __syncthreads();
        const uint32_t bb = bufs[cp];
#pragma unroll
        for (int kk = 0; kk < 2; kk++) {
            uint32_t bh[2][4], blr[2][4];
            ldm4(bh[0], bb + OFF_BH + offB[0][kk]);
            ldm4(bh[1], bb + OFF_BH + offB[1][kk]);
            ldm4(blr[0], bb + OFF_BL + offB[0][kk]);
            ldm4(blr[1], bb + OFF_BL + offB[1][kk]);
#pragma unroll
            for (int m = 0; m < 4; m++) {
                uint32_t ah[4], al[4];
                ldm4(ah, bb + OFF_AH + offA[m][kk]);
                ldm4(al, bb + OFF_AL + offA[m][kk]);
#pragma unroll
                for (int n = 0; n < 4; n++) {
                    const uint32_t* bhp = &bh[n >> 1][(n & 1) * 2];
                    const uint32_t* blp = &blr[n >> 1][(n & 1) * 2];
                    mma_bf16(acc[m][n], ah, bhp);
                    mma_bf16(acc[m][n], ah, blp);
                    mma_bf16(acc[m][n], al, bhp);
                }
            }
        }
        __syncthreads();
        ld = (ld + 1) == 3 ? 0 : ld + 1;
        cp = (cp + 1) == 3 ? 0 : cp + 1;
    }

    // epilogue: add bias, write g_pose2[(oc*36+s)*512 + b]
#pragma unroll
    for (int m = 0; m < 4; m++) {
        int ocr = oc0 + warpm * 64 + m * 16 + (lane >> 2);
        float bias0 = b2[ocr], bias1 = b2[ocr + 8];
#pragma unroll
        for (int n = 0; n < 4; n++) {
            int bc = bb0 + warpn * 32 + n * 8 + (lane & 3) * 2;
            float2 v0 = {acc[m][n][0] + bias0, acc[m][n][1] + bias0};
            float2 v1 = {acc[m][n][2] + bias1, acc[m][n][3] + bias1};
            *(float2*)(g_pose2 + ((size_t)ocr * 36 + s) * 512 + bc) = v0;
            *(float2*)(g_pose2 + ((size_t)(ocr + 8) * 36 + s) * 512 + bc) = v1;
        }
    }
}

// ---------------- squash: pose2 [flat][b] -> u [b][n][d] ----------------
__global__ __launch_bounds__(512) void k_squash2() {
    int n = blockIdx.x, b = threadIdx.x;
    const float* src = g_pose2 + (size_t)(8 * n) * 512 + b;
    float p[8];
#pragma unroll
    for (int d = 0; d < 8; d++) p[d] = src[(size_t)d * 512];
    float sq = 0.f;
#pragma unroll
    for (int d = 0; d < 8; d++) sq += p[d] * p[d];
    float sc = sq / ((1.f + sq) * sqrtf(sq + 1e-8f));
    float4 o0 = {p[0] * sc, p[1] * sc, p[2] * sc, p[3] * sc};
    float4 o1 = {p[4] * sc, p[5] * sc, p[6] * sc, p[7] * sc};
    float4* dst = (float4*)(g_u + (size_t)b * 9216 + 8 * n);
    dst[0] = o0;
    dst[1] = o1;
}

// ---------------- u_hat GEMM ----------------
__global__ __launch_bounds__(256) void k_uhat(const float* __restrict__ W) {
    __shared__ float Ws[8192];
    __shared__ float us[512];
    int tid = threadIdx.x;
    int n0 = blockIdx.x * 64, c = blockIdx.y;
    int bs = blockIdx.z * 128;
    for (int l = tid; l < 8192; l += 256)
        Ws[l] = W[((size_t)c * 1152 + n0) * 128 + l];
    __syncthreads();
    for (int b = bs; b < bs + 128; b++) {
        for (int l = tid; l < 512; l += 256) us[l] = g_u[(size_t)b * 9216 + n0 * 8 + l];
        __syncthreads();
        float* dst = g_uhat + ((size_t)c * 512 + b) * 18432 + n0 * 16;
#pragma unroll
        for (int k = 0; k < 4; k++) {
            int q = tid + k * 256;
            int nl = q >> 4, e = q & 15;
            float a = 0.f;
#pragma unroll
            for (int d = 0; d < 8; d++) a += us[nl * 8 + d] * Ws[nl * 128 + d * 16 + e];
            dst[q] = a;
        }
        __syncthreads();
    }
}

// ---------------- routing iterations ----------------
#define ROUTE_SMEM ((18432 + 1152 + 1152 + 256 + 32 + 16 + 16) * 4)
__global__ __launch_bounds__(256) void k_route2() {
    extern __shared__ float sm[];
    float* uh = sm;
    float* bl = uh + 18432;
    float* cl = bl + 1152;
    float* sp = cl + 1152;
    float* red = sp + 256;
    float* sv = red + 32;
    float* vs = sv + 16;
    int tid = threadIdx.x;
    int c = blockIdx.x, b = blockIdx.y;
    int lane = tid & 31, wid = tid >> 5;

    const float4* src = (const float4*)(g_uhat + ((size_t)c * 512 + b) * 18432);
    float4* uh4 = (float4*)uh;
    for (int l = tid; l < 4608; l += 256) uh4[l] = src[l];
    for (int n = tid; n < 1152; n += 256) bl[n] = 0.f;
    __syncthreads();

    for (int it = 0; it < 3; it++) {
        float m = -1e30f;
        for (int n = tid; n < 1152; n += 256) m = fmaxf(m, bl[n]);
#pragma unroll
        for (int o = 16; o > 0; o >>= 1) m = fmaxf(m, __shfl_xor_sync(0xffffffffu, m, o));
        if (lane == 0) red[wid] = m;
        __syncthreads();
        if (tid == 0) {
            float t = red[0];
            for (int i = 1; i < 8; i++) t = fmaxf(t, red[i]);
            red[16] = t;
        }
        __syncthreads();
        m = red[16];
        float ps = 0.f;
        for (int n = tid; n < 1152; n += 256) {
            float e = expf(bl[n] - m);
            cl[n] = e;
            ps += e;
        }
#pragma unroll
        for (int o = 16; o > 0; o >>= 1) ps += __shfl_xor_sync(0xffffffffu, ps, o);
        if (lane == 0) red[wid] = ps;
        __syncthreads();
        if (tid == 0) {
            float t = 0.f;
            for (int i = 0; i < 8; i++) t += red[i];
            red[17] = t;
        }
        __syncthreads();
        float invS = 1.f / red[17];

        int e = tid & 15, g = tid >> 4;
        float part = 0.f;
        for (int n = g; n < 1152; n += 16) part += cl[n] * uh[n * 16 + e];
        sp[tid] = part;
        __syncthreads();
        if (tid < 16) {
            float t = 0.f;
            for (int gg = 0; gg < 16; gg++) t += sp[gg * 16 + tid];
            sv[tid] = t * invS;
        }
        __syncthreads();
        if (tid == 0) {
            float sq = 0.f;
            for (int i = 0; i < 16; i++) sq += sv[i] * sv[i];
            red[18] = sq / ((1.f + sq) * sqrtf(sq + 1e-8f));
        }
        __syncthreads();
        if (tid < 16) vs[tid] = sv[tid] * red[18];
        __syncthreads();

        if (it < 2) {
            const float4* vv = (const float4*)vs;
            float4 v0 = vv[0], v1 = vv[1], v2 = vv[2], v3 = vv[3];
            for (int n = tid; n < 1152; n += 256) {
                const float4* u4 = uh4 + n * 4;
                float4 a = u4[0], bq = u4[1], cq = u4[2], dq = u4[3];
                float dot = a.x * v0.x + a.y * v0.y + a.z * v0.z + a.w * v0.w +
                            bq.x * v1.x + bq.y * v1.y + bq.z * v1.z + bq.w * v1.w +
                            cq.x * v2.x + cq.y * v2.y + cq.z * v2.z + cq.w * v2.w +
                            dq.x * v3.x + dq.y * v3.y + dq.z * v3.z + dq.w * v3.w;
                bl[n] += dot;
            }
            __syncthreads();
        }
    }
    if (tid < 16) g_v[((size_t)b * 10 + c) * 16 + tid] = vs[tid];
}

// ---------------- class probs + masked decoder ----------------
__global__ __launch_bounds__(256) void k_dec(const float* __restrict__ d1w,
                                             const float* __restrict__ d1b,
                                             const float* __restrict__ d2b,
                                             const float* __restrict__ d3b,
                                             float* __restrict__ out) {
    __shared__ __align__(16) float v_s[4][160];
    __shared__ __align__(16) float h1s[4][512];
    __shared__ __align__(16) float h2s[4][1024];
    __shared__ float nrm[4][10];
    __shared__ float cps[4][10];
    __shared__ int args[4];
    int tid = threadIdx.x;
    int b0 = blockIdx.x * 4;

    for (int bb = 0; bb < 4; bb++)
        for (int i = tid; i < 160; i += 256) v_s[bb][i] = g_v[(size_t)(b0 + bb) * 160 + i];
    __syncthreads();

    if (tid < 40) {
        int bb = tid / 10, c = tid % 10;
        float s = 0.f;
#pragma unroll
        for (int e = 0; e < 16; e++) {
            float t = v_s[bb][c * 16 + e];
            s += t * t;
        }
        nrm[bb][c] = sqrtf(s);
    }
    __syncthreads();
    if (tid < 4) {
        int bb = tid;
        float m = -1e30f;
        int a = 0;
        for (int c = 0; c < 10; c++)
            if (nrm[bb][c] > m) { m = nrm[bb][c]; a = c; }
        args[bb] = a;
        float ex[10], s = 0.f;
        for (int c = 0; c < 10; c++) { ex[c] = expf(nrm[bb][c] - m); s += ex[c]; }
        for (int c = 0; c < 10; c++) cps[bb][c] = ex[c] / s;
    }
    __syncthreads();
    if (tid < 40) {
        int bb = tid / 10, c = tid % 10;
        out[(size_t)(b0 + bb) * 10 + c] = cps[bb][c];
    }

    for (int bb = 0; bb < 4; bb++) {
        int a = args[bb];
        const float* vp = &v_s[bb][a * 16];
        for (int j = tid; j < 512; j += 256) {
            const float* wp = d1w + (size_t)j * 160 + a * 16;
            float acc = d1b[j];
#pragma unroll
            for (int e = 0; e < 16; e++) acc += vp[e] * wp[e];
            h1s[bb][j] = fmaxf(acc, 0.f);
        }
    }
    __syncthreads();

    int w = tid >> 5, lane = tid & 31;
    {
        int k0 = w * 128 + lane * 4;
        float acc[4][4];
#pragma unroll
        for (int bb = 0; bb < 4; bb++)
#pragma unroll
            for (int kk = 0; kk < 4; kk++) acc[bb][kk] = 0.f;
        for (int j = 0; j < 512; j += 4) {
            float4 w0 = *(const float4*)(g_d2t + (size_t)(j + 0) * 1024 + k0);
            float4 w1 = *(const float4*)(g_d2t + (size_t)(j + 1) * 1024 + k0);
            float4 w2 = *(const float4*)(g_d2t + (size_t)(j + 2) * 1024 + k0);
            float4 w3 = *(const float4*)(g_d2t + (size_t)(j + 3) * 1024 + k0);
#pragma unroll
            for (int bb = 0; bb < 4; bb++) {
                float4 hv = *(const float4*)&h1s[bb][j];
                acc[bb][0] += hv.x * w0.x + hv.y * w1.x + hv.z * w2.x + hv.w * w3.x;
                acc[bb][1] += hv.x * w0.y + hv.y * w1.y + hv.z * w2.y + hv.w * w3.y;
                acc[bb][2] += hv.x * w0.z + hv.y * w1.z + hv.z * w2.z + hv.w * w3.z;
                acc[bb][3] += hv.x * w0.w + hv.y * w1.w + hv.z * w2.w + hv.w * w3.w;
            }
        }
        float bk0 = d2b[k0], bk1 = d2b[k0 + 1], bk2 = d2b[k0 + 2], bk3 = d2b[k0 + 3];
#pragma unroll
        for (int bb = 0; bb < 4; bb++) {
            h2s[bb][k0 + 0] = fmaxf(acc[bb][0] + bk0, 0.f);
            h2s[bb][k0 + 1] = fmaxf(acc[bb][1] + bk1, 0.f);
            h2s[bb][k0 + 2] = fmaxf(acc[bb][2] + bk2, 0.f);
            h2s[bb][k0 + 3] = fmaxf(acc[bb][3] + bk3, 0.f);
        }
    }
    __syncthreads();

    {
        int r0 = w * 128 + lane * 4;
        if (r0 < 784) {
            float acc[4][4];
#pragma unroll
            for (int bb = 0; bb < 4; bb++)
#pragma unroll
                for (int kk = 0; kk < 4; kk++) acc[bb][kk] = 0.f;
            for (int k = 0; k < 1024; k += 4) {
                float4 w0 = *(const float4*)(g_d3t + (size_t)(k + 0) * 784 + r0);
                float4 w1 = *(const float4*)(g_d3t + (size_t)(k + 1) * 784 + r0);
                float4 w2 = *(const float4*)(g_d3t + (size_t)(k + 2) * 784 + r0);
                float4 w3 = *(const float4*)(g_d3t + (size_t)(k + 3) * 784 + r0);
#pragma unroll
                for (int bb = 0; bb < 4; bb++) {
                    float4 hv = *(const float4*)&h2s[bb][k];
                    acc[bb][0] += hv.x * w0.x + hv.y * w1.x + hv.z * w2.x + hv.w * w3.x;
                    acc[bb][1] += hv.x * w0.y + hv.y * w1.y + hv.z * w2.y + hv.w * w3.y;
                    acc[bb][2] += hv.x * w0.z + hv.y * w1.z + hv.z * w2.z + hv.w * w3.z;
                    acc[bb][3] += hv.x * w0.w + hv.y * w1.w + hv.z * w2.w + hv.w * w3.w;
                }
            }
            float b0r = d3b[r0], b1r = d3b[r0 + 1], b2r = d3b[r0 + 2], b3r = d3b[r0 + 3];
#pragma unroll
            for (int bb = 0; bb < 4; bb++) {
                float4 o;
                o.x = 1.f / (1.f + expf(-(acc[bb][0] + b0r)));
                o.y = 1.f / (1.f + expf(-(acc[bb][1] + b1r)));
                o.z = 1.f / (1.f + expf(-(acc[bb][2] + b2r)));
                o.w = 1.f / (1.f + expf(-(acc[bb][3] + b3r)));
                *(float4*)(out + 5120 + (size_t)(b0 + bb) * 784 + r0) = o;
            }
        }
    }
}

// ---------------- launch ----------------
extern "C" void kernel_launch(void* const* d_in, const int* in_sizes, int n_in,
                              void* d_out, int out_size) {
    const float* x = (const float*)d_in[0];
    const float* w1 = (const float*)d_in[1];
    const float* b1 = (const float*)d_in[2];
    const float* w2 = (const float*)d_in[3];
    const float* b2 = (const float*)d_in[4];
    const float* W = (const float*)d_in[5];
    const float* d1w = (const float*)d_in[6];
    const float* d1b = (const float*)d_in[7];
    const float* d2b = (const float*)d_in[9];
    const float* d3b = (const float*)d_in[11];
    float* out = (float*)d_out;
    (void)in_sizes; (void)n_in; (void)out_size;

    cudaFuncSetAttribute(k_conv2mma, cudaFuncAttributeMaxDynamicSharedMemorySize, CONV2_SMEM);
    cudaFuncSetAttribute(k_route2, cudaFuncAttributeMaxDynamicSharedMemorySize, ROUTE_SMEM);

    k_prep<<<20736, 256>>>(w1, w2, (const float*)d_in[8], (const float*)d_in[10]);
    k_conv1<<<dim3(20, 512), 256>>>(x, b1);
    k_conv2mma<<<dim3(8, 36), 256, CONV2_SMEM>>>(b2);
    k_squash2<<<1152, 512>>>();
    k_uhat<<<dim3(18, 10, 4), 256>>>(W);
    k_route2<<<dim3(10, 512), 256, ROUTE_SMEM>>>();
    k_dec<<<128, 256>>>(d1w, d1b, d2b, d3b, out);
}

// round 4
// speedup vs baseline: 2.5685x; 1.0403x over previous
#include <cuda_runtime.h>
#include <cuda_bf16.h>
#include <cstdint>

#define NB 512

// ---------------- device scratch ----------------
__device__ float g_wt1[81 * 256];                              // conv1 w: [tap][oc]
__device__ __align__(128) __nv_bfloat16 g_w2h[256 * 81 * 256]; // conv2 w hi: [oc][tap][ic]
__device__ __align__(128) __nv_bfloat16 g_w2l[256 * 81 * 256]; // conv2 w lo
__device__ float g_d2t[512 * 1024];                            // d2_w^T
__device__ float g_d3t[1024 * 784];                            // d3_w^T
__device__ __align__(128) __nv_bfloat16 g_c1h[(size_t)400 * 512 * 256]; // conv1 out hi: [pix][b][ic]
__device__ __align__(128) __nv_bfloat16 g_c1l[(size_t)400 * 512 * 256]; // conv1 out lo
__device__ float g_pose2[(size_t)9216 * 512];                  // conv2 out: [oc*36+s][b]
__device__ float g_u[(size_t)NB * 9216];                       // squashed: [b][n][d]
__device__ float g_uhat[(size_t)10 * 512 * 18432];             // [c][b][n*16+e]
__device__ float g_v[(size_t)NB * 160];                        // [b][c][e]

// ---------------- helpers ----------------
__device__ __forceinline__ uint32_t smem_u32(const void* p) {
    uint32_t a;
    asm("{ .reg .u64 t; cvta.to.shared.u64 t, %1; cvt.u32.u64 %0, t; }" : "=r"(a) : "l"(p));
    return a;
}
__device__ __forceinline__ void cpa16(uint32_t dst, const __nv_bfloat16* src) {
    asm volatile("cp.async.cg.shared.global [%0], [%1], 16;" :: "r"(dst), "l"(__cvta_generic_to_global(src)));
}
#define CP_COMMIT() asm volatile("cp.async.commit_group;" ::: "memory")
#define CP_WAIT2()  asm volatile("cp.async.wait_group 2;" ::: "memory")

__device__ __forceinline__ void ldm4(uint32_t* r, uint32_t addr) {
    asm volatile("ldmatrix.sync.aligned.m8n8.x4.shared.b16 {%0,%1,%2,%3}, [%4];"
                 : "=r"(r[0]), "=r"(r[1]), "=r"(r[2]), "=r"(r[3]) : "r"(addr));
}
__device__ __forceinline__ void mma_bf16(float* c, const uint32_t* a, const uint32_t* b) {
    asm volatile("mma.sync.aligned.m16n8k16.row.col.f32.bf16.bf16.f32 "
                 "{%0,%1,%2,%3}, {%4,%5,%6,%7}, {%8,%9}, {%0,%1,%2,%3};"
                 : "+f"(c[0]), "+f"(c[1]), "+f"(c[2]), "+f"(c[3])
                 : "r"(a[0]), "r"(a[1]), "r"(a[2]), "r"(a[3]), "r"(b[0]), "r"(b[1]));
}

// ---------------- weight re-layout + hi/lo split ----------------
__global__ void k_prep(const float* __restrict__ w1, const float* __restrict__ w2,
                       const float* __restrict__ d2w, const float* __restrict__ d3w) {
    int i = blockIdx.x * blockDim.x + threadIdx.x;
    if (i < 81 * 256) {
        int k = i / 256, oc = i % 256;
        g_wt1[i] = w1[oc * 81 + k];
    }
    if (i < 256 * 81 * 256) {
        int ic = i % 256;
        int tap = (i / 256) % 81;
        int oc = i / (256 * 81);
        float v = w2[((size_t)oc * 256 + ic) * 81 + tap];
        __nv_bfloat16 h = __float2bfloat16(v);
        g_w2h[i] = h;
        g_w2l[i] = __float2bfloat16(v - __bfloat162float(h));
    }
    if (i < 512 * 1024) {
        int k = i % 1024, j = i / 1024;
        g_d2t[i] = d2w[k * 512 + j];
    }
    if (i < 1024 * 784) {
        int r = i % 784, k = i / 784;
        g_d3t[i] = d3w[r * 1024 + k];
    }
}

// ---------------- conv1: (B,1,28,28) -> relu -> bf16 hi/lo [pix][b][oc] ----------------
__global__ __launch_bounds__(256) void k_conv1(const float* __restrict__ x,
                                               const float* __restrict__ b1) {
    __shared__ float xs[784];
    int b = blockIdx.y, oy = blockIdx.x, oc = threadIdx.x;
    const float* xp = x + (size_t)b * 784;
    for (int i = oc; i < 784; i += 256) xs[i] = xp[i];
    __syncthreads();

    float acc[20];
#pragma unroll
    for (int i = 0; i < 20; i++) acc[i] = 0.f;
#pragma unroll
    for (int ky = 0; ky < 9; ky++) {
        float w[9];
#pragma unroll
        for (int kx = 0; kx < 9; kx++) w[kx] = g_wt1[(ky * 9 + kx) * 256 + oc];
        const float* row = &xs[(oy + ky) * 28];
        float in[28];
#pragma unroll
        for (int i = 0; i < 28; i++) in[i] = row[i];
#pragma unroll
        for (int kx = 0; kx < 9; kx++)
#pragma unroll
            for (int ox = 0; ox < 20; ox++) acc[ox] += in[ox + kx] * w[kx];
    }
    float bias = b1[oc];
#pragma unroll
    for (int ox = 0; ox < 20; ox++) {
        float v = acc[ox] + bias;
        v = v > 0.f ? v : 0.f;
        __nv_bfloat16 h = __float2bfloat16(v);
        __nv_bfloat16 l = __float2bfloat16(v - __bfloat162float(h));
        size_t idx = ((size_t)(oy * 20 + ox) * 512 + b) * 256 + oc;
        g_c1h[idx] = h;
        g_c1l[idx] = l;
    }
}

// ---------------- conv2 via mma.sync bf16x3 ----------------
// per block: D[oc(128), b(256)] over site s; 648 k-stages of 32 ic
// 512 threads, 16 warps as 2(m) x 8(n); warp tile 64oc x 32b
// 3-stage cp.async pipeline, 48KB/stage
#define C2_STAGES 648
#define OFF_AH 0
#define OFF_AL 8192
#define OFF_BH 16384
#define OFF_BL 32768
#define C2_STAGE_BYTES 49152
#define CONV2_SMEM (3 * C2_STAGE_BYTES)

__device__ __forceinline__ void c2_load(uint32_t sb, int i, int oc0, int bb0,
                                        int oy, int ox, int tid) {
    const int tap = i >> 3, icc = i & 7, ic0 = icc * 32;
    const int ky = tap / 9, kx = tap % 9;
    const int pix = (2 * oy + ky) * 20 + 2 * ox + kx;
    // A: 128 rows x 64B (hi+lo)
    {
        int row = tid >> 2, c = tid & 3;
        uint32_t soff = row * 64 + ((c ^ ((row >> 1) & 3)) * 16);
        size_t aoff = (size_t)(oc0 + row) * 20736 + tap * 256 + ic0 + c * 8;
        cpa16(sb + OFF_AH + soff, g_w2h + aoff);
        cpa16(sb + OFF_AL + soff, g_w2l + aoff);
    }
    // B: 256 rows x 64B (hi+lo)
#pragma unroll
    for (int rep = 0; rep < 2; rep++) {
        int q = tid + rep * 512;
        int row = q >> 2, c = q & 3;
        uint32_t soff = row * 64 + ((c ^ ((row >> 1) & 3)) * 16);
        size_t boff = ((size_t)pix * 512 + bb0 + row) * 256 + ic0 + c * 8;
        cpa16(sb + OFF_BH + soff, g_c1h + boff);
        cpa16(sb + OFF_BL + soff, g_c1l + boff);
    }
}

__global__ __launch_bounds__(512, 1) void k_conv2mma(const float* __restrict__ b2) {
    extern __shared__ __align__(1024) char smem[];
    const uint32_t sbase = smem_u32(smem);
    const int tid = threadIdx.x;
    const int wid = tid >> 5, lane = tid & 31;
    const int oc0 = (blockIdx.x >> 1) * 128;
    const int bb0 = (blockIdx.x & 1) * 256;
    const int s = blockIdx.y;
    const int oy = s / 6, ox = s % 6;
    const int warpm = wid >> 3, warpn = wid & 7;

    float acc[4][4][4];
#pragma unroll
    for (int m = 0; m < 4; m++)
#pragma unroll
        for (int n = 0; n < 4; n++)
#pragma unroll
            for (int k = 0; k < 4; k++) acc[m][n][k] = 0.f;

    uint32_t offA[4][2], offB[2][2];
#pragma unroll
    for (int m = 0; m < 4; m++)
#pragma unroll
        for (int kk = 0; kk < 2; kk++) {
            int row = warpm * 64 + m * 16 + (lane & 15);
            int lc = 2 * kk + (lane >> 4);
            offA[m][kk] = row * 64 + ((lc ^ ((row >> 1) & 3)) * 16);
        }
#pragma unroll
    for (int p = 0; p < 2; p++)
#pragma unroll
        for (int kk = 0; kk < 2; kk++) {
            int row = warpn * 32 + p * 16 + (lane & 7) + ((lane >> 4) & 1) * 8;
            int lc = 2 * kk + ((lane >> 3) & 1);
            offB[p][kk] = row * 64 + ((lc ^ ((row >> 1) & 3)) * 16);
        }

    c2_load(sbase, 0, oc0, bb0, oy, ox, tid);
    CP_COMMIT();
    c2_load(sbase + C2_STAGE_BYTES, 1, oc0, bb0, oy, ox, tid);
    CP_COMMIT();

    uint32_t bufs[3] = {sbase, sbase + C2_STAGE_BYTES, sbase + 2 * C2_STAGE_BYTES};
    int ld = 2, cp = 0;
    for (int i = 0; i < C2_STAGES; i++) {
        if (i + 2 < C2_STAGES) c2_load(bufs[ld], i + 2, oc0, bb0, oy, ox, tid);
        CP_COMMIT();
        CP_WAIT2();
        __syncthreads();
        const uint32_t bb = bufs[cp];
#pragma unroll
        for (int kk = 0; kk < 2; kk++) {
            uint32_t bh[2][4], blr[2][4];
            ldm4(bh[0], bb + OFF_BH + offB[0][kk]);
            ldm4(bh[1], bb + OFF_BH + offB[1][kk]);
            ldm4(blr[0], bb + OFF_BL + offB[0][kk]);
            ldm4(blr[1], bb + OFF_BL + offB[1][kk]);
#pragma unroll
            for (int m = 0; m < 4; m++) {
                uint32_t ah[4], al[4];
                ldm4(ah, bb + OFF_AH + offA[m][kk]);
                ldm4(al, bb + OFF_AL + offA[m][kk]);
#pragma unroll
                for (int n = 0; n < 4; n++) {
                    const uint32_t* bhp = &bh[n >> 1][(n & 1) * 2];
                    const uint32_t* blp = &blr[n >> 1][(n & 1) * 2];
                    mma_bf16(acc[m][n], ah, bhp);
                    mma_bf16(acc[m][n], ah, blp);
                    mma_bf16(acc[m][n], al, bhp);
                }
            }
        }
        __syncthreads();
        ld = (ld + 1) == 3 ? 0 : ld + 1;
        cp = (cp + 1) == 3 ? 0 : cp + 1;
    }

    // epilogue: add bias, write g_pose2[(oc*36+s)*512 + b]
#pragma unroll
    for (int m = 0; m < 4; m++) {
        int ocr = oc0 + warpm * 64 + m * 16 + (lane >> 2);
        float bias0 = b2[ocr], bias1 = b2[ocr + 8];
#pragma unroll
        for (int n = 0; n < 4; n++) {
            int bc = bb0 + warpn * 32 + n * 8 + (lane & 3) * 2;
            float2 v0 = {acc[m][n][0] + bias0, acc[m][n][1] + bias0};
            float2 v1 = {acc[m][n][2] + bias1, acc[m][n][3] + bias1};
            *(float2*)(g_pose2 + ((size_t)ocr * 36 + s) * 512 + bc) = v0;
            *(float2*)(g_pose2 + ((size_t)(ocr + 8) * 36 + s) * 512 + bc) = v1;
        }
    }
}

// ---------------- squash: pose2 [flat][b] -> u [b][n][d] ----------------
__global__ __launch_bounds__(512) void k_squash2() {
    int n = blockIdx.x, b = threadIdx.x;
    const float* src = g_pose2 + (size_t)(8 * n) * 512 + b;
    float p[8];
#pragma unroll
    for (int d = 0; d < 8; d++) p[d] = src[(size_t)d * 512];
    float sq = 0.f;
#pragma unroll
    for (int d = 0; d < 8; d++) sq += p[d] * p[d];
    float sc = sq / ((1.f + sq) * sqrtf(sq + 1e-8f));
    float4 o0 = {p[0] * sc, p[1] * sc, p[2] * sc, p[3] * sc};
    float4 o1 = {p[4] * sc, p[5] * sc, p[6] * sc, p[7] * sc};
    float4* dst = (float4*)(g_u + (size_t)b * 9216 + 8 * n);
    dst[0] = o0;
    dst[1] = o1;
}

// ---------------- u_hat GEMM ----------------
__global__ __launch_bounds__(256) void k_uhat(const float* __restrict__ W) {
    __shared__ float Ws[8192];
    __shared__ float us[512];
    int tid = threadIdx.x;
    int n0 = blockIdx.x * 64, c = blockIdx.y;
    int bs = blockIdx.z * 128;
    for (int l = tid; l < 8192; l += 256)
        Ws[l] = W[((size_t)c * 1152 + n0) * 128 + l];
    __syncthreads();
    for (int b = bs; b < bs + 128; b++) {
        for (int l = tid; l < 512; l += 256) us[l] = g_u[(size_t)b * 9216 + n0 * 8 + l];
        __syncthreads();
        float* dst = g_uhat + ((size_t)c * 512 + b) * 18432 + n0 * 16;
#pragma unroll
        for (int k = 0; k < 4; k++) {
            int q = tid + k * 256;
            int nl = q >> 4, e = q & 15;
            float a = 0.f;
#pragma unroll
            for (int d = 0; d < 8; d++) a += us[nl * 8 + d] * Ws[nl * 128 + d * 16 + e];
            dst[q] = a;
        }
        __syncthreads();
    }
}

// ---------------- routing iterations ----------------
#define ROUTE_SMEM ((18432 + 1152 + 1152 + 256 + 32 + 16 + 16) * 4)
__global__ __launch_bounds__(256) void k_route2() {
    extern __shared__ float sm[];
    float* uh = sm;
    float* bl = uh + 18432;
    float* cl = bl + 1152;
    float* sp = cl + 1152;
    float* red = sp + 256;
    float* sv = red + 32;
    float* vs = sv + 16;
    int tid = threadIdx.x;
    int c = blockIdx.x, b = blockIdx.y;
    int lane = tid & 31, wid = tid >> 5;

    const float4* src = (const float4*)(g_uhat + ((size_t)c * 512 + b) * 18432);
    float4* uh4 = (float4*)uh;
    for (int l = tid; l < 4608; l += 256) uh4[l] = src[l];
    for (int n = tid; n < 1152; n += 256) bl[n] = 0.f;
    __syncthreads();

    for (int it = 0; it < 3; it++) {
        float m = -1e30f;
        for (int n = tid; n < 1152; n += 256) m = fmaxf(m, bl[n]);
#pragma unroll
        for (int o = 16; o > 0; o >>= 1) m = fmaxf(m, __shfl_xor_sync(0xffffffffu, m, o));
        if (lane == 0) red[wid] = m;
        __syncthreads();
        if (tid == 0) {
            float t = red[0];
            for (int i = 1; i < 8; i++) t = fmaxf(t, red[i]);
            red[16] = t;
        }
        __syncthreads();
        m = red[16];
        float ps = 0.f;
        for (int n = tid; n < 1152; n += 256) {
            float e = expf(bl[n] - m);
            cl[n] = e;
            ps += e;
        }
#pragma unroll
        for (int o = 16; o > 0; o >>= 1) ps += __shfl_xor_sync(0xffffffffu, ps, o);
        if (lane == 0) red[wid] = ps;
        __syncthreads();
        if (tid == 0) {
            float t = 0.f;
            for (int i = 0; i < 8; i++) t += red[i];
            red[17] = t;
        }
        __syncthreads();
        float invS = 1.f / red[17];

        int e = tid & 15, g = tid >> 4;
        float part = 0.f;
        for (int n = g; n < 1152; n += 16) part += cl[n] * uh[n * 16 + e];
        sp[tid] = part;
        __syncthreads();
        if (tid < 16) {
            float t = 0.f;
            for (int gg = 0; gg < 16; gg++) t += sp[gg * 16 + tid];
            sv[tid] = t * invS;
        }
        __syncthreads();
        if (tid == 0) {
            float sq = 0.f;
            for (int i = 0; i < 16; i++) sq += sv[i] * sv[i];
            red[18] = sq / ((1.f + sq) * sqrtf(sq + 1e-8f));
        }
        __syncthreads();
        if (tid < 16) vs[tid] = sv[tid] * red[18];
        __syncthreads();

        if (it < 2) {
            const float4* vv = (const float4*)vs;
            float4 v0 = vv[0], v1 = vv[1], v2 = vv[2], v3 = vv[3];
            for (int n = tid; n < 1152; n += 256) {
                const float4* u4 = uh4 + n * 4;
                float4 a = u4[0], bq = u4[1], cq = u4[2], dq = u4[3];
                float dot = a.x * v0.x + a.y * v0.y + a.z * v0.z + a.w * v0.w +
                            bq.x * v1.x + bq.y * v1.y + bq.z * v1.z + bq.w * v1.w +
                            cq.x * v2.x + cq.y * v2.y + cq.z * v2.z + cq.w * v2.w +
                            dq.x * v3.x + dq.y * v3.y + dq.z * v3.z + dq.w * v3.w;
                bl[n] += dot;
            }
            __syncthreads();
        }
    }
    if (tid < 16) g_v[((size_t)b * 10 + c) * 16 + tid] = vs[tid];
}

// ---------------- class probs + masked decoder ----------------
__global__ __launch_bounds__(256) void k_dec(const float* __restrict__ d1w,
                                             const float* __restrict__ d1b,
                                             const float* __restrict__ d2b,
                                             const float* __restrict__ d3b,
                                             float* __restrict__ out) {
    __shared__ __align__(16) float v_s[4][160];
    __shared__ __align__(16) float h1s[4][512];
    __shared__ __align__(16) float h2s[4][1024];
    __shared__ float nrm[4][10];
    __shared__ float cps[4][10];
    __shared__ int args[4];
    int tid = threadIdx.x;
    int b0 = blockIdx.x * 4;

    for (int bb = 0; bb < 4; bb++)
        for (int i = tid; i < 160; i += 256) v_s[bb][i] = g_v[(size_t)(b0 + bb) * 160 + i];
    __syncthreads();

    if (tid < 40) {
        int bb = tid / 10, c = tid % 10;
        float s = 0.f;
#pragma unroll
        for (int e = 0; e < 16; e++) {
            float t = v_s[bb][c * 16 + e];
            s += t * t;
        }
        nrm[bb][c] = sqrtf(s);
    }
    __syncthreads();
    if (tid < 4) {
        int bb = tid;
        float m = -1e30f;
        int a = 0;
        for (int c = 0; c < 10; c++)
            if (nrm[bb][c] > m) { m = nrm[bb][c]; a = c; }
        args[bb] = a;
        float ex[10], s = 0.f;
        for (int c = 0; c < 10; c++) { ex[c] = expf(nrm[bb][c] - m); s += ex[c]; }
        for (int c = 0; c < 10; c++) cps[bb][c] = ex[c] / s;
    }
    __syncthreads();
    if (tid < 40) {
        int bb = tid / 10, c = tid % 10;
        out[(size_t)(b0 + bb) * 10 + c] = cps[bb][c];
    }

    for (int bb = 0; bb < 4; bb++) {
        int a = args[bb];
        const float* vp = &v_s[bb][a * 16];
        for (int j = tid; j < 512; j += 256) {
            const float* wp = d1w + (size_t)j * 160 + a * 16;
            float acc = d1b[j];
#pragma unroll
            for (int e = 0; e < 16; e++) acc += vp[e] * wp[e];
            h1s[bb][j] = fmaxf(acc, 0.f);
        }
    }
    __syncthreads();

    int w = tid >> 5, lane = tid & 31;
    {
        int k0 = w * 128 + lane * 4;
        float acc[4][4];
#pragma unroll
        for (int bb = 0; bb < 4; bb++)
#pragma unroll
            for (int kk = 0; kk < 4; kk++) acc[bb][kk] = 0.f;
        for (int j = 0; j < 512; j += 4) {
            float4 w0 = *(const float4*)(g_d2t + (size_t)(j + 0) * 1024 + k0);
            float4 w1 = *(const float4*)(g_d2t + (size_t)(j + 1) * 1024 + k0);
            float4 w2 = *(const float4*)(g_d2t + (size_t)(j + 2) * 1024 + k0);
            float4 w3 = *(const float4*)(g_d2t + (size_t)(j + 3) * 1024 + k0);
#pragma unroll
            for (int bb = 0; bb < 4; bb++) {
                float4 hv = *(const float4*)&h1s[bb][j];
                acc[bb][0] += hv.x * w0.x + hv.y * w1.x + hv.z * w2.x + hv.w * w3.x;
                acc[bb][1] += hv.x * w0.y + hv.y * w1.y + hv.z * w2.y + hv.w * w3.y;
                acc[bb][2] += hv.x * w0.z + hv.y * w1.z + hv.z * w2.z + hv.w * w3.z;
                acc[bb][3] += hv.x * w0.w + hv.y * w1.w + hv.z * w2.w + hv.w * w3.w;
            }
        }
        float bk0 = d2b[k0], bk1 = d2b[k0 + 1], bk2 = d2b[k0 + 2], bk3 = d2b[k0 + 3];
#pragma unroll
        for (int bb = 0; bb < 4; bb++) {
            h2s[bb][k0 + 0] = fmaxf(acc[bb][0] + bk0, 0.f);
            h2s[bb][k0 + 1] = fmaxf(acc[bb][1] + bk1, 0.f);
            h2s[bb][k0 + 2] = fmaxf(acc[bb][2] + bk2, 0.f);
            h2s[bb][k0 + 3] = fmaxf(acc[bb][3] + bk3, 0.f);
        }
    }
    __syncthreads();

    {
        int r0 = w * 128 + lane * 4;
        if (r0 < 784) {
            float acc[4][4];
#pragma unroll
            for (int bb = 0; bb < 4; bb++)
#pragma unroll
                for (int kk = 0; kk < 4; kk++) acc[bb][kk] = 0.f;
            for (int k = 0; k < 1024; k += 4) {
                float4 w0 = *(const float4*)(g_d3t + (size_t)(k + 0) * 784 + r0);
                float4 w1 = *(const float4*)(g_d3t + (size_t)(k + 1) * 784 + r0);
                float4 w2 = *(const float4*)(g_d3t + (size_t)(k + 2) * 784 + r0);
                float4 w3 = *(const float4*)(g_d3t + (size_t)(k + 3) * 784 + r0);
#pragma unroll
                for (int bb = 0; bb < 4; bb++) {
                    float4 hv = *(const float4*)&h2s[bb][k];
                    acc[bb][0] += hv.x * w0.x + hv.y * w1.x + hv.z * w2.x + hv.w * w3.x;
                    acc[bb][1] += hv.x * w0.y + hv.y * w1.y + hv.z * w2.y + hv.w * w3.y;
                    acc[bb][2] += hv.x * w0.z + hv.y * w1.z + hv.z * w2.z + hv.w * w3.z;
                    acc[bb][3] += hv.x * w0.w + hv.y * w1.w + hv.z * w2.w + hv.w * w3.w;
                }
            }
            float b0r = d3b[r0], b1r = d3b[r0 + 1], b2r = d3b[r0 + 2], b3r = d3b[r0 + 3];
#pragma unroll
            for (int bb = 0; bb < 4; bb++) {
                float4 o;
                o.x = 1.f / (1.f + expf(-(acc[bb][0] + b0r)));
                o.y = 1.f / (1.f + expf(-(acc[bb][1] + b1r)));
                o.z = 1.f / (1.f + expf(-(acc[bb][2] + b2r)));
                o.w = 1.f / (1.f + expf(-(acc[bb][3] + b3r)));
                *(float4*)(out + 5120 + (size_t)(b0 + bb) * 784 + r0) = o;
            }
        }
    }
}

// ---------------- launch ----------------
extern "C" void kernel_launch(void* const* d_in, const int* in_sizes, int n_in,
                              void* d_out, int out_size) {
    const float* x = (const float*)d_in[0];
    const float* w1 = (const float*)d_in[1];
    const float* b1 = (const float*)d_in[2];
    const float* w2 = (const float*)d_in[3];
    const float* b2 = (const float*)d_in[4];
    const float* W = (const float*)d_in[5];
    const float* d1w = (const float*)d_in[6];
    const float* d1b = (const float*)d_in[7];
    const float* d2b = (const float*)d_in[9];
    const float* d3b = (const float*)d_in[11];
    float* out = (float*)d_out;
    (void)in_sizes; (void)n_in; (void)out_size;

    cudaFuncSetAttribute(k_conv2mma, cudaFuncAttributeMaxDynamicSharedMemorySize, CONV2_SMEM);
    cudaFuncSetAttribute(k_route2, cudaFuncAttributeMaxDynamicSharedMemorySize, ROUTE_SMEM);

    k_prep<<<20736, 256>>>(w1, w2, (const float*)d_in[8], (const float*)d_in[10]);
    k_conv1<<<dim3(20, 512), 256>>>(x, b1);
    k_conv2mma<<<dim3(4, 36), 512, CONV2_SMEM>>>(b2);
    k_squash2<<<1152, 512>>>();
    k_uhat<<<dim3(18, 10, 4), 256>>>(W);
    k_route2<<<dim3(10, 512), 256, ROUTE_SMEM>>>();
    k_dec<<<128, 256>>>(d1w, d1b, d2b, d3b, out);
}

// round 5
// speedup vs baseline: 2.6166x; 1.0187x over previous
#include <cuda_runtime.h>
#include <cuda_bf16.h>
#include <cstdint>

#define NB 512

// ---------------- device scratch ----------------
__device__ float g_wt1[81 * 256];                              // conv1 w: [tap][oc]
__device__ __align__(128) __nv_bfloat16 g_w2h[256 * 81 * 256]; // conv2 w hi: [oc][tap][ic]
__device__ __align__(128) __nv_bfloat16 g_w2l[256 * 81 * 256]; // conv2 w lo
__device__ float g_d2t[512 * 1024];                            // d2_w^T
__device__ float g_d3t[1024 * 784];                            // d3_w^T
__device__ __align__(128) __nv_bfloat16 g_c1h[(size_t)400 * 512 * 256]; // conv1 out hi: [pix][b][ic]
__device__ __align__(128) __nv_bfloat16 g_c1l[(size_t)400 * 512 * 256]; // conv1 out lo
__device__ float g_pose2[(size_t)9216 * 512];                  // conv2 out: [oc*36+s][b]
__device__ float g_u[(size_t)NB * 9216];                       // squashed: [b][n][d]
__device__ float g_uhat[(size_t)10 * 512 * 18432];             // [c][b][n*16+e]
__device__ float g_v[(size_t)NB * 160];                        // [b][c][e]

// ---------------- helpers ----------------
__device__ __forceinline__ uint32_t smem_u32(const void* p) {
    uint32_t a;
    asm("{ .reg .u64 t; cvta.to.shared.u64 t, %1; cvt.u32.u64 %0, t; }" : "=r"(a) : "l"(p));
    return a;
}
__device__ __forceinline__ void cpa16(uint32_t dst, const __nv_bfloat16* src) {
    asm volatile("cp.async.cg.shared.global [%0], [%1], 16;" :: "r"(dst), "l"(__cvta_generic_to_global(src)));
}
#define CP_COMMIT() asm volatile("cp.async.commit_group;" ::: "memory")
#define CP_WAIT1()  asm volatile("cp.async.wait_group 1;" ::: "memory")

__device__ __forceinline__ void ldm4(uint32_t* r, uint32_t addr) {
    asm volatile("ldmatrix.sync.aligned.m8n8.x4.shared.b16 {%0,%1,%2,%3}, [%4];"
                 : "=r"(r[0]), "=r"(r[1]), "=r"(r[2]), "=r"(r[3]) : "r"(addr));
}
__device__ __forceinline__ void mma_bf16(float* c, const uint32_t* a, const uint32_t* b) {
    asm volatile("mma.sync.aligned.m16n8k16.row.col.f32.bf16.bf16.f32 "
                 "{%0,%1,%2,%3}, {%4,%5,%6,%7}, {%8,%9}, {%0,%1,%2,%3};"
                 : "+f"(c[0]), "+f"(c[1]), "+f"(c[2]), "+f"(c[3])
                 : "r"(a[0]), "r"(a[1]), "r"(a[2]), "r"(a[3]), "r"(b[0]), "r"(b[1]));
}

// ---------------- weight re-layout + hi/lo split ----------------
__global__ void k_prep(const float* __restrict__ w1, const float* __restrict__ w2,
                       const float* __restrict__ d2w, const float* __restrict__ d3w) {
    int i = blockIdx.x * blockDim.x + threadIdx.x;
    if (i < 81 * 256) {
        int k = i / 256, oc = i % 256;
        g_wt1[i] = w1[oc * 81 + k];
    }
    if (i < 256 * 81 * 256) {
        int ic = i % 256;
        int tap = (i / 256) % 81;
        int oc = i / (256 * 81);
        float v = w2[((size_t)oc * 256 + ic) * 81 + tap];
        __nv_bfloat16 h = __float2bfloat16(v);
        g_w2h[i] = h;
        g_w2l[i] = __float2bfloat16(v - __bfloat162float(h));
    }
    if (i < 512 * 1024) {
        int k = i % 1024, j = i / 1024;
        g_d2t[i] = d2w[k * 512 + j];
    }
    if (i < 1024 * 784) {
        int r = i % 784, k = i / 784;
        g_d3t[i] = d3w[r * 1024 + k];
    }
}

// ---------------- conv1: (B,1,28,28) -> relu -> bf16 hi/lo [pix][b][oc] ----------------
__global__ __launch_bounds__(256) void k_conv1(const float* __restrict__ x,
                                               const float* __restrict__ b1) {
    __shared__ float xs[784];
    int b = blockIdx.y, oy = blockIdx.x, oc = threadIdx.x;
    const float* xp = x + (size_t)b * 784;
    for (int i = oc; i < 784; i += 256) xs[i] = xp[i];
    __syncthreads();

    float acc[20];
#pragma unroll
    for (int i = 0; i < 20; i++) acc[i] = 0.f;
#pragma unroll
    for (int ky = 0; ky < 9; ky++) {
        float w[9];
#pragma unroll
        for (int kx = 0; kx < 9; kx++) w[kx] = g_wt1[(ky * 9 + kx) * 256 + oc];
        const float* row = &xs[(oy + ky) * 28];
        float in[28];
#pragma unroll
        for (int i = 0; i < 28; i++) in[i] = row[i];
#pragma unroll
        for (int kx = 0; kx < 9; kx++)
#pragma unroll
            for (int ox = 0; ox < 20; ox++) acc[ox] += in[ox + kx] * w[kx];
    }
    float bias = b1[oc];
#pragma unroll
    for (int ox = 0; ox < 20; ox++) {
        float v = acc[ox] + bias;
        v = v > 0.f ? v : 0.f;
        __nv_bfloat16 h = __float2bfloat16(v);
        __nv_bfloat16 l = __float2bfloat16(v - __bfloat162float(h));
        size_t idx = ((size_t)(oy * 20 + ox) * 512 + b) * 256 + oc;
        g_c1h[idx] = h;
        g_c1l[idx] = l;
    }
}

// ---------------- conv2 via mma.sync bf16x3 ----------------
// per block: D[oc(128), b(128)] at site s; 648 k-stages of 32 ic
// 256 threads, 8 warps as 2(m) x 4(n); warp tile 64oc x 32b
// 2-stage cp.async pipeline, 32KB/stage -> 64KB smem, 2 CTAs/SM
#define C2_STAGES 648
#define OFF_AH 0
#define OFF_AL 8192
#define OFF_BH 16384
#define OFF_BL 24576
#define C2_STAGE_BYTES 32768
#define CONV2_SMEM (2 * C2_STAGE_BYTES)

__device__ __forceinline__ void c2_load(uint32_t sb, int i, int oc0, int bb0,
                                        int oy, int ox, int tid) {
    const int tap = i >> 3, icc = i & 7, ic0 = icc * 32;
    const int ky = tap / 9, kx = tap % 9;
    const int pix = (2 * oy + ky) * 20 + 2 * ox + kx;
#pragma unroll
    for (int rep = 0; rep < 2; rep++) {
        int q = tid + rep * 256;
        int row = q >> 2, c = q & 3;
        uint32_t soff = row * 64 + ((c ^ ((row >> 1) & 3)) * 16);
        size_t aoff = (size_t)(oc0 + row) * 20736 + tap * 256 + ic0 + c * 8;
        cpa16(sb + OFF_AH + soff, g_w2h + aoff);
        cpa16(sb + OFF_AL + soff, g_w2l + aoff);
        size_t boff = ((size_t)pix * 512 + bb0 + row) * 256 + ic0 + c * 8;
        cpa16(sb + OFF_BH + soff, g_c1h + boff);
        cpa16(sb + OFF_BL + soff, g_c1l + boff);
    }
}

__global__ __launch_bounds__(256, 2) void k_conv2mma(const float* __restrict__ b2) {
    extern __shared__ __align__(1024) char smem[];
    const uint32_t sbase = smem_u32(smem);
    const int tid = threadIdx.x;
    const int wid = tid >> 5, lane = tid & 31;
    const int oc0 = (blockIdx.x >> 2) * 128;
    const int bb0 = (blockIdx.x & 3) * 128;
    const int s = blockIdx.y;
    const int oy = s / 6, ox = s % 6;
    const int warpm = wid >> 2, warpn = wid & 3;

    float acc[4][4][4];
#pragma unroll
    for (int m = 0; m < 4; m++)
#pragma unroll
        for (int n = 0; n < 4; n++)
#pragma unroll
            for (int k = 0; k < 4; k++) acc[m][n][k] = 0.f;

    uint32_t offA[4][2], offB[2][2];
#pragma unroll
    for (int m = 0; m < 4; m++)
#pragma unroll
        for (int kk = 0; kk < 2; kk++) {
            int row = warpm * 64 + m * 16 + (lane & 15);
            int lc = 2 * kk + (lane >> 4);
            offA[m][kk] = row * 64 + ((lc ^ ((row >> 1) & 3)) * 16);
        }
#pragma unroll
    for (int p = 0; p < 2; p++)
#pragma unroll
        for (int kk = 0; kk < 2; kk++) {
            int row = warpn * 32 + p * 16 + (lane & 7) + ((lane >> 4) & 1) * 8;
            int lc = 2 * kk + ((lane >> 3) & 1);
            offB[p][kk] = row * 64 + ((lc ^ ((row >> 1) & 3)) * 16);
        }

    c2_load(sbase, 0, oc0, bb0, oy, ox, tid);
    CP_COMMIT();

    uint32_t bufs[2] = {sbase, sbase + C2_STAGE_BYTES};
    for (int i = 0; i < C2_STAGES; i++) {
        if (i + 1 < C2_STAGES) c2_load(bufs[(i + 1) & 1], i + 1, oc0, bb0, oy, ox, tid);
        CP_COMMIT();
        CP_WAIT1();
        __syncthreads();
        const uint32_t bb = bufs[i & 1];
#pragma unroll
        for (int kk = 0; kk < 2; kk++) {
            uint32_t bh[2][4], blr[2][4];
            ldm4(bh[0], bb + OFF_BH + offB[0][kk]);
            ldm4(bh[1], bb + OFF_BH + offB[1][kk]);
            ldm4(blr[0], bb + OFF_BL + offB[0][kk]);
            ldm4(blr[1], bb + OFF_BL + offB[1][kk]);
#pragma unroll
            for (int m = 0; m < 4; m++) {
                uint32_t ah[4], al[4];
                ldm4(ah, bb + OFF_AH + offA[m][kk]);
                ldm4(al, bb + OFF_AL + offA[m][kk]);
#pragma unroll
                for (int n = 0; n < 4; n++) {
                    const uint32_t* bhp = &bh[n >> 1][(n & 1) * 2];
                    const uint32_t* blp = &blr[n >> 1][(n & 1) * 2];
                    mma_bf16(acc[m][n], ah, bhp);
                    mma_bf16(acc[m][n], ah, blp);
                    mma_bf16(acc[m][n], al, bhp);
                }
            }
        }
        __syncthreads();
    }

    // epilogue: add bias, write g_pose2[(oc*36+s)*512 + b]
#pragma unroll
    for (int m = 0; m < 4; m++) {
        int ocr = oc0 + warpm * 64 + m * 16 + (lane >> 2);
        float bias0 = b2[ocr], bias1 = b2[ocr + 8];
#pragma unroll
        for (int n = 0; n < 4; n++) {
            int bc = bb0 + warpn * 32 + n * 8 + (lane & 3) * 2;
            float2 v0 = {acc[m][n][0] + bias0, acc[m][n][1] + bias0};
            float2 v1 = {acc[m][n][2] + bias1, acc[m][n][3] + bias1};
            *(float2*)(g_pose2 + ((size_t)ocr * 36 + s) * 512 + bc) = v0;
            *(float2*)(g_pose2 + ((size_t)(ocr + 8) * 36 + s) * 512 + bc) = v1;
        }
    }
}

// ---------------- squash: pose2 [flat][b] -> u [b][n][d] ----------------
__global__ __launch_bounds__(512) void k_squash2() {
    int n = blockIdx.x, b = threadIdx.x;
    const float* src = g_pose2 + (size_t)(8 * n) * 512 + b;
    float p[8];
#pragma unroll
    for (int d = 0; d < 8; d++) p[d] = src[(size_t)d * 512];
    float sq = 0.f;
#pragma unroll
    for (int d = 0; d < 8; d++) sq += p[d] * p[d];
    float sc = sq / ((1.f + sq) * sqrtf(sq + 1e-8f));
    float4 o0 = {p[0] * sc, p[1] * sc, p[2] * sc, p[3] * sc};
    float4 o1 = {p[4] * sc, p[5] * sc, p[6] * sc, p[7] * sc};
    float4* dst = (float4*)(g_u + (size_t)b * 9216 + 8 * n);
    dst[0] = o0;
    dst[1] = o1;
}

// ---------------- u_hat GEMM ----------------
__global__ __launch_bounds__(256) void k_uhat(const float* __restrict__ W) {
    __shared__ float Ws[8192];
    __shared__ float us[512];
    int tid = threadIdx.x;
    int n0 = blockIdx.x * 64, c = blockIdx.y;
    int bs = blockIdx.z * 128;
    for (int l = tid; l < 8192; l += 256)
        Ws[l] = W[((size_t)c * 1152 + n0) * 128 + l];
    __syncthreads();
    for (int b = bs; b < bs + 128; b++) {
        for (int l = tid; l < 512; l += 256) us[l] = g_u[(size_t)b * 9216 + n0 * 8 + l];
        __syncthreads();
        float* dst = g_uhat + ((size_t)c * 512 + b) * 18432 + n0 * 16;
#pragma unroll
        for (int k = 0; k < 4; k++) {
            int q = tid + k * 256;
            int nl = q >> 4, e = q & 15;
            float a = 0.f;
#pragma unroll
            for (int d = 0; d < 8; d++) a += us[nl * 8 + d] * Ws[nl * 128 + d * 16 + e];
            dst[q] = a;
        }
        __syncthreads();
    }
}

// ---------------- routing iterations ----------------
#define ROUTE_SMEM ((18432 + 1152 + 1152 + 256 + 32 + 16 + 16) * 4)
__global__ __launch_bounds__(256) void k_route2() {
    extern __shared__ float sm[];
    float* uh = sm;
    float* bl = uh + 18432;
    float* cl = bl + 1152;
    float* sp = cl + 1152;
    float* red = sp + 256;
    float* sv = red + 32;
    float* vs = sv + 16;
    int tid = threadIdx.x;
    int c = blockIdx.x, b = blockIdx.y;
    int lane = tid & 31, wid = tid >> 5;

    const float4* src = (const float4*)(g_uhat + ((size_t)c * 512 + b) * 18432);
    float4* uh4 = (float4*)uh;
    for (int l = tid; l < 4608; l += 256) uh4[l] = src[l];
    for (int n = tid; n < 1152; n += 256) bl[n] = 0.f;
    __syncthreads();

    for (int it = 0; it < 3; it++) {
        float m = -1e30f;
        for (int n = tid; n < 1152; n += 256) m = fmaxf(m, bl[n]);
#pragma unroll
        for (int o = 16; o > 0; o >>= 1) m = fmaxf(m, __shfl_xor_sync(0xffffffffu, m, o));
        if (lane == 0) red[wid] = m;
        __syncthreads();
        if (tid == 0) {
            float t = red[0];
            for (int i = 1; i < 8; i++) t = fmaxf(t, red[i]);
            red[16] = t;
        }
        __syncthreads();
        m = red[16];
        float ps = 0.f;
        for (int n = tid; n < 1152; n += 256) {
            float e = expf(bl[n] - m);
            cl[n] = e;
            ps += e;
        }
#pragma unroll
        for (int o = 16; o > 0; o >>= 1) ps += __shfl_xor_sync(0xffffffffu, ps, o);
        if (lane == 0) red[wid] = ps;
        __syncthreads();
        if (tid == 0) {
            float t = 0.f;
            for (int i = 0; i < 8; i++) t += red[i];
            red[17] = t;
        }
        __syncthreads();
        float invS = 1.f / red[17];

        int e = tid & 15, g = tid >> 4;
        float part = 0.f;
        for (int n = g; n < 1152; n += 16) part += cl[n] * uh[n * 16 + e];
        sp[tid] = part;
        __syncthreads();
        if (tid < 16) {
            float t = 0.f;
            for (int gg = 0; gg < 16; gg++) t += sp[gg * 16 + tid];
            sv[tid] = t * invS;
        }
        __syncthreads();
        if (tid == 0) {
            float sq = 0.f;
            for (int i = 0; i < 16; i++) sq += sv[i] * sv[i];
            red[18] = sq / ((1.f + sq) * sqrtf(sq + 1e-8f));
        }
        __syncthreads();
        if (tid < 16) vs[tid] = sv[tid] * red[18];
        __syncthreads();

        if (it < 2) {
            const float4* vv = (const float4*)vs;
            float4 v0 = vv[0], v1 = vv[1], v2 = vv[2], v3 = vv[3];
            for (int n = tid; n < 1152; n += 256) {
                const float4* u4 = uh4 + n * 4;
                float4 a = u4[0], bq = u4[1], cq = u4[2], dq = u4[3];
                float dot = a.x * v0.x + a.y * v0.y + a.z * v0.z + a.w * v0.w +
                            bq.x * v1.x + bq.y * v1.y + bq.z * v1.z + bq.w * v1.w +
                            cq.x * v2.x + cq.y * v2.y + cq.z * v2.z + cq.w * v2.w +
                            dq.x * v3.x + dq.y * v3.y + dq.z * v3.z + dq.w * v3.w;
                bl[n] += dot;
            }
            __syncthreads();
        }
    }
    if (tid < 16) g_v[((size_t)b * 10 + c) * 16 + tid] = vs[tid];
}

// ---------------- class probs + masked decoder ----------------
__global__ __launch_bounds__(256) void k_dec(const float* __restrict__ d1w,
                                             const float* __restrict__ d1b,
                                             const float* __restrict__ d2b,
                                             const float* __restrict__ d3b,
                                             float* __restrict__ out) {
    __shared__ __align__(16) float v_s[4][160];
    __shared__ __align__(16) float h1s[4][512];
    __shared__ __align__(16) float h2s[4][1024];
    __shared__ float nrm[4][10];
    __shared__ float cps[4][10];
    __shared__ int args[4];
    int tid = threadIdx.x;
    int b0 = blockIdx.x * 4;

    for (int bb = 0; bb < 4; bb++)
        for (int i = tid; i < 160; i += 256) v_s[bb][i] = g_v[(size_t)(b0 + bb) * 160 + i];
    __syncthreads();

    if (tid < 40) {
        int bb = tid / 10, c = tid % 10;
        float s = 0.f;
#pragma unroll
        for (int e = 0; e < 16; e++) {
            float t = v_s[bb][c * 16 + e];
            s += t * t;
        }
        nrm[bb][c] = sqrtf(s);
    }
    __syncthreads();
    if (tid < 4) {
        int bb = tid;
        float m = -1e30f;
        int a = 0;
        for (int c = 0; c < 10; c++)
            if (nrm[bb][c] > m) { m = nrm[bb][c]; a = c; }
        args[bb] = a;
        float ex[10], s = 0.f;
        for (int c = 0; c < 10; c++) { ex[c] = expf(nrm[bb][c] - m); s += ex[c]; }
        for (int c = 0; c < 10; c++) cps[bb][c] = ex[c] / s;
    }
    __syncthreads();
    if (tid < 40) {
        int bb = tid / 10, c = tid % 10;
        out[(size_t)(b0 + bb) * 10 + c] = cps[bb][c];
    }

    for (int bb = 0; bb < 4; bb++) {
        int a = args[bb];
        const float* vp = &v_s[bb][a * 16];
        for (int j = tid; j < 512; j += 256) {
            const float* wp = d1w + (size_t)j * 160 + a * 16;
            float acc = d1b[j];
#pragma unroll
            for (int e = 0; e < 16; e++) acc += vp[e] * wp[e];
            h1s[bb][j] = fmaxf(acc, 0.f);
        }
    }
    __syncthreads();

    int w = tid >> 5, lane = tid & 31;
    {
        int k0 = w * 128 + lane * 4;
        float acc[4][4];
#pragma unroll
        for (int bb = 0; bb < 4; bb++)
#pragma unroll
            for (int kk = 0; kk < 4; kk++) acc[bb][kk] = 0.f;
        for (int j = 0; j < 512; j += 4) {
            float4 w0 = *(const float4*)(g_d2t + (size_t)(j + 0) * 1024 + k0);
            float4 w1 = *(const float4*)(g_d2t + (size_t)(j + 1) * 1024 + k0);
            float4 w2 = *(const float4*)(g_d2t + (size_t)(j + 2) * 1024 + k0);
            float4 w3 = *(const float4*)(g_d2t + (size_t)(j + 3) * 1024 + k0);
#pragma unroll
            for (int bb = 0; bb < 4; bb++) {
                float4 hv = *(const float4*)&h1s[bb][j];
                acc[bb][0] += hv.x * w0.x + hv.y * w1.x + hv.z * w2.x + hv.w * w3.x;
                acc[bb][1] += hv.x * w0.y + hv.y * w1.y + hv.z * w2.y + hv.w * w3.y;
                acc[bb][2] += hv.x * w0.z + hv.y * w1.z + hv.z * w2.z + hv.w * w3.z;
                acc[bb][3] += hv.x * w0.w + hv.y * w1.w + hv.z * w2.w + hv.w * w3.w;
            }
        }
        float bk0 = d2b[k0], bk1 = d2b[k0 + 1], bk2 = d2b[k0 + 2], bk3 = d2b[k0 + 3];
#pragma unroll
        for (int bb = 0; bb < 4; bb++) {
            h2s[bb][k0 + 0] = fmaxf(acc[bb][0] + bk0, 0.f);
            h2s[bb][k0 + 1] = fmaxf(acc[bb][1] + bk1, 0.f);
            h2s[bb][k0 + 2] = fmaxf(acc[bb][2] + bk2, 0.f);
            h2s[bb][k0 + 3] = fmaxf(acc[bb][3] + bk3, 0.f);
        }
    }
    __syncthreads();

    {
        int r0 = w * 128 + lane * 4;
        if (r0 < 784) {
            float acc[4][4];
#pragma unroll
            for (int bb = 0; bb < 4; bb++)
#pragma unroll
                for (int kk = 0; kk < 4; kk++) acc[bb][kk] = 0.f;
            for (int k = 0; k < 1024; k += 4) {
                float4 w0 = *(const float4*)(g_d3t + (size_t)(k + 0) * 784 + r0);
                float4 w1 = *(const float4*)(g_d3t + (size_t)(k + 1) * 784 + r0);
                float4 w2 = *(const float4*)(g_d3t + (size_t)(k + 2) * 784 + r0);
                float4 w3 = *(const float4*)(g_d3t + (size_t)(k + 3) * 784 + r0);
#pragma unroll
                for (int bb = 0; bb < 4; bb++) {
                    float4 hv = *(const float4*)&h2s[bb][k];
                    acc[bb][0] += hv.x * w0.x + hv.y * w1.x + hv.z * w2.x + hv.w * w3.x;
                    acc[bb][1] += hv.x * w0.y + hv.y * w1.y + hv.z * w2.y + hv.w * w3.y;
                    acc[bb][2] += hv.x * w0.z + hv.y * w1.z + hv.z * w2.z + hv.w * w3.z;
                    acc[bb][3] += hv.x * w0.w + hv.y * w1.w + hv.z * w2.w + hv.w * w3.w;
                }
            }
            float b0r = d3b[r0], b1r = d3b[r0 + 1], b2r = d3b[r0 + 2], b3r = d3b[r0 + 3];
#pragma unroll
            for (int bb = 0; bb < 4; bb++) {
                float4 o;
                o.x = 1.f / (1.f + expf(-(acc[bb][0] + b0r)));
                o.y = 1.f / (1.f + expf(-(acc[bb][1] + b1r)));
                o.z = 1.f / (1.f + expf(-(acc[bb][2] + b2r)));
                o.w = 1.f / (1.f + expf(-(acc[bb][3] + b3r)));
                *(float4*)(out + 5120 + (size_t)(b0 + bb) * 784 + r0) = o;
            }
        }
    }
}

// ---------------- launch ----------------
extern "C" void kernel_launch(void* const* d_in, const int* in_sizes, int n_in,
                              void* d_out, int out_size) {
    const float* x = (const float*)d_in[0];
    const float* w1 = (const float*)d_in[1];
    const float* b1 = (const float*)d_in[2];
    const float* w2 = (const float*)d_in[3];
    const float* b2 = (const float*)d_in[4];
    const float* W = (const float*)d_in[5];
    const float* d1w = (const float*)d_in[6];
    const float* d1b = (const float*)d_in[7];
    const float* d2b = (const float*)d_in[9];
    const float* d3b = (const float*)d_in[11];
    float* out = (float*)d_out;
    (void)in_sizes; (void)n_in; (void)out_size;

    cudaFuncSetAttribute(k_conv2mma, cudaFuncAttributeMaxDynamicSharedMemorySize, CONV2_SMEM);
    cudaFuncSetAttribute(k_route2, cudaFuncAttributeMaxDynamicSharedMemorySize, ROUTE_SMEM);

    k_prep<<<20736, 256>>>(w1, w2, (const float*)d_in[8], (const float*)d_in[10]);
    k_conv1<<<dim3(20, 512), 256>>>(x, b1);
    k_conv2mma<<<dim3(8, 36), 256, CONV2_SMEM>>>(b2);
    k_squash2<<<1152, 512>>>();
    k_uhat<<<dim3(18, 10, 4), 256>>>(W);
    k_route2<<<dim3(10, 512), 256, ROUTE_SMEM>>>();
    k_dec<<<128, 256>>>(d1w, d1b, d2b, d3b, out);
}

// round 6
// speedup vs baseline: 2.6761x; 1.0227x over previous
#include <cuda_runtime.h>
#include <cuda_bf16.h>
#include <cstdint>

#define NB 512

// ---------------- device scratch ----------------
__device__ float g_wt1[81 * 256];                              // conv1 w: [tap][oc]
__device__ __align__(128) __nv_bfloat16 g_w2h[256 * 81 * 256]; // conv2 w hi: [oc][tap][ic]
__device__ __align__(128) __nv_bfloat16 g_w2l[256 * 81 * 256]; // conv2 w lo
__device__ float g_d2t[512 * 1024];                            // d2_w^T
__device__ float g_d3t[1024 * 784];                            // d3_w^T
__device__ __align__(128) __nv_bfloat16 g_c1h[(size_t)400 * 512 * 256]; // conv1 out hi: [pix][b][ic]
__device__ __align__(128) __nv_bfloat16 g_c1l[(size_t)400 * 512 * 256]; // conv1 out lo
__device__ float g_pose2[(size_t)9216 * 512];                  // conv2 out: [oc*36+s][b]
__device__ float g_u[(size_t)NB * 9216];                       // squashed: [b][n][d]
__device__ float g_uhat[(size_t)10 * 512 * 18432];             // [c][b][n*16+e]
__device__ float g_v[(size_t)NB * 160];                        // [b][c][e]

// ---------------- helpers ----------------
__device__ __forceinline__ uint32_t smem_u32(const void* p) {
    uint32_t a;
    asm("{ .reg .u64 t; cvta.to.shared.u64 t, %1; cvt.u32.u64 %0, t; }" : "=r"(a) : "l"(p));
    return a;
}
__device__ __forceinline__ void cpa16(uint32_t dst, const __nv_bfloat16* src) {
    asm volatile("cp.async.cg.shared.global [%0], [%1], 16;" :: "r"(dst), "l"(__cvta_generic_to_global(src)));
}
#define CP_COMMIT() asm volatile("cp.async.commit_group;" ::: "memory")
#define CP_WAIT1()  asm volatile("cp.async.wait_group 1;" ::: "memory")

__device__ __forceinline__ void ldm4(uint32_t* r, uint32_t addr) {
    asm volatile("ldmatrix.sync.aligned.m8n8.x4.shared.b16 {%0,%1,%2,%3}, [%4];"
                 : "=r"(r[0]), "=r"(r[1]), "=r"(r[2]), "=r"(r[3]) : "r"(addr));
}
__device__ __forceinline__ void mma_bf16(float* c, const uint32_t* a, const uint32_t* b) {
    asm volatile("mma.sync.aligned.m16n8k16.row.col.f32.bf16.bf16.f32 "
                 "{%0,%1,%2,%3}, {%4,%5,%6,%7}, {%8,%9}, {%0,%1,%2,%3};"
                 : "+f"(c[0]), "+f"(c[1]), "+f"(c[2]), "+f"(c[3])
                 : "r"(a[0]), "r"(a[1]), "r"(a[2]), "r"(a[3]), "r"(b[0]), "r"(b[1]));
}

// ---------------- weight re-layout + hi/lo split ----------------
__global__ void k_prep(const float* __restrict__ w1, const float* __restrict__ w2,
                       const float* __restrict__ d2w, const float* __restrict__ d3w) {
    int i = blockIdx.x * blockDim.x + threadIdx.x;
    if (i < 81 * 256) {
        int k = i / 256, oc = i % 256;
        g_wt1[i] = w1[oc * 81 + k];
    }
    if (i < 256 * 81 * 256) {
        int ic = i % 256;
        int tap = (i / 256) % 81;
        int oc = i / (256 * 81);
        float v = w2[((size_t)oc * 256 + ic) * 81 + tap];
        __nv_bfloat16 h = __float2bfloat16(v);
        g_w2h[i] = h;
        g_w2l[i] = __float2bfloat16(v - __bfloat162float(h));
    }
    if (i < 512 * 1024) {
        int k = i % 1024, j = i / 1024;
        g_d2t[i] = d2w[k * 512 + j];
    }
    if (i < 1024 * 784) {
        int r = i % 784, k = i / 784;
        g_d3t[i] = d3w[r * 1024 + k];
    }
}

// diagnostic no-op: shifts ncu capture slot so k_conv2mma gets profiled
__global__ void k_probe() {}

// ---------------- conv1: (B,1,28,28) -> relu -> bf16 hi/lo [pix][b][oc] ----------------
__global__ __launch_bounds__(256) void k_conv1(const float* __restrict__ x,
                                               const float* __restrict__ b1) {
    __shared__ float xs[784];
    int b = blockIdx.y, oy = blockIdx.x, oc = threadIdx.x;
    const float* xp = x + (size_t)b * 784;
    for (int i = oc; i < 784; i += 256) xs[i] = xp[i];
    __syncthreads();

    float acc[20];
#pragma unroll
    for (int i = 0; i < 20; i++) acc[i] = 0.f;
#pragma unroll
    for (int ky = 0; ky < 9; ky++) {
        float w[9];
#pragma unroll
        for (int kx = 0; kx < 9; kx++) w[kx] = g_wt1[(ky * 9 + kx) * 256 + oc];
        const float* row = &xs[(oy + ky) * 28];
        float in[28];
#pragma unroll
        for (int i = 0; i < 28; i++) in[i] = row[i];
#pragma unroll
        for (int kx = 0; kx < 9; kx++)
#pragma unroll
            for (int ox = 0; ox < 20; ox++) acc[ox] += in[ox + kx] * w[kx];
    }
    float bias = b1[oc];
#pragma unroll
    for (int ox = 0; ox < 20; ox++) {
        float v = acc[ox] + bias;
        v = v > 0.f ? v : 0.f;
        __nv_bfloat16 h = __float2bfloat16(v);
        __nv_bfloat16 l = __float2bfloat16(v - __bfloat162float(h));
        size_t idx = ((size_t)(oy * 20 + ox) * 512 + b) * 256 + oc;
        g_c1h[idx] = h;
        g_c1l[idx] = l;
    }
}

// ---------------- conv2 via mma.sync bf16x3, chain-broken ordering ----------------
#define C2_STAGES 648
#define OFF_AH 0
#define OFF_AL 8192
#define OFF_BH 16384
#define OFF_BL 24576
#define C2_STAGE_BYTES 32768
#define CONV2_SMEM (2 * C2_STAGE_BYTES)

__device__ __forceinline__ void c2_load(uint32_t sb, int i, int oc0, int bb0,
                                        int oy, int ox, int tid) {
    const int tap = i >> 3, icc = i & 7, ic0 = icc * 32;
    const int ky = tap / 9, kx = tap % 9;
    const int pix = (2 * oy + ky) * 20 + 2 * ox + kx;
#pragma unroll
    for (int rep = 0; rep < 2; rep++) {
        int q = tid + rep * 256;
        int row = q >> 2, c = q & 3;
        uint32_t soff = row * 64 + ((c ^ ((row >> 1) & 3)) * 16);
        size_t aoff = (size_t)(oc0 + row) * 20736 + tap * 256 + ic0 + c * 8;
        cpa16(sb + OFF_AH + soff, g_w2h + aoff);
        cpa16(sb + OFF_AL + soff, g_w2l + aoff);
        size_t boff = ((size_t)pix * 512 + bb0 + row) * 256 + ic0 + c * 8;
        cpa16(sb + OFF_BH + soff, g_c1h + boff);
        cpa16(sb + OFF_BL + soff, g_c1l + boff);
    }
}

__global__ __launch_bounds__(256, 2) void k_conv2mma(const float* __restrict__ b2) {
    extern __shared__ __align__(1024) char smem[];
    const uint32_t sbase = smem_u32(smem);
    const int tid = threadIdx.x;
    const int wid = tid >> 5, lane = tid & 31;
    const int oc0 = (blockIdx.x >> 2) * 128;
    const int bb0 = (blockIdx.x & 3) * 128;
    const int s = blockIdx.y;
    const int oy = s / 6, ox = s % 6;
    const int warpm = wid >> 2, warpn = wid & 3;

    float acc[4][4][4];
#pragma unroll
    for (int m = 0; m < 4; m++)
#pragma unroll
        for (int n = 0; n < 4; n++)
#pragma unroll
            for (int k = 0; k < 4; k++) acc[m][n][k] = 0.f;

    uint32_t offA[4][2], offB[2][2];
#pragma unroll
    for (int m = 0; m < 4; m++)
#pragma unroll
        for (int kk = 0; kk < 2; kk++) {
            int row = warpm * 64 + m * 16 + (lane & 15);
            int lc = 2 * kk + (lane >> 4);
            offA[m][kk] = row * 64 + ((lc ^ ((row >> 1) & 3)) * 16);
        }
#pragma unroll
    for (int p = 0; p < 2; p++)
#pragma unroll
        for (int kk = 0; kk < 2; kk++) {
            int row = warpn * 32 + p * 16 + (lane & 7) + ((lane >> 4) & 1) * 8;
            int lc = 2 * kk + ((lane >> 3) & 1);
            offB[p][kk] = row * 64 + ((lc ^ ((row >> 1) & 3)) * 16);
        }

    c2_load(sbase, 0, oc0, bb0, oy, ox, tid);
    CP_COMMIT();

    uint32_t bufs[2] = {sbase, sbase + C2_STAGE_BYTES};
    for (int i = 0; i < C2_STAGES; i++) {
        if (i + 1 < C2_STAGES) c2_load(bufs[(i + 1) & 1], i + 1, oc0, bb0, oy, ox, tid);
        CP_COMMIT();
        CP_WAIT1();
        __syncthreads();
        const uint32_t bb = bufs[i & 1];
#pragma unroll
        for (int kk = 0; kk < 2; kk++) {
            uint32_t bh[2][4], blr[2][4];
            ldm4(bh[0], bb + OFF_BH + offB[0][kk]);
            ldm4(bh[1], bb + OFF_BH + offB[1][kk]);
            ldm4(blr[0], bb + OFF_BL + offB[0][kk]);
            ldm4(blr[1], bb + OFF_BL + offB[1][kk]);
#pragma unroll
            for (int mp = 0; mp < 2; mp++) {
                uint32_t ah[2][4], al[2][4];
                ldm4(ah[0], bb + OFF_AH + offA[2 * mp + 0][kk]);
                ldm4(ah[1], bb + OFF_AH + offA[2 * mp + 1][kk]);
                ldm4(al[0], bb + OFF_AL + offA[2 * mp + 0][kk]);
                ldm4(al[1], bb + OFF_AL + offA[2 * mp + 1][kk]);
                // term 1: hi*hi — 8 independent MMAs
#pragma unroll
                for (int mi = 0; mi < 2; mi++)
#pragma unroll
                    for (int n = 0; n < 4; n++)
                        mma_bf16(acc[2 * mp + mi][n], ah[mi], &bh[n >> 1][(n & 1) * 2]);
                // term 2: hi*lo — 8 independent MMAs
#pragma unroll
                for (int mi = 0; mi < 2; mi++)
#pragma unroll
                    for (int n = 0; n < 4; n++)
                        mma_bf16(acc[2 * mp + mi][n], ah[mi], &blr[n >> 1][(n & 1) * 2]);
                // term 3: lo*hi — 8 independent MMAs
#pragma unroll
                for (int mi = 0; mi < 2; mi++)
#pragma unroll
                    for (int n = 0; n < 4; n++)
                        mma_bf16(acc[2 * mp + mi][n], al[mi], &bh[n >> 1][(n & 1) * 2]);
            }
        }
        __syncthreads();
    }

    // epilogue: add bias, write g_pose2[(oc*36+s)*512 + b]
#pragma unroll
    for (int m = 0; m < 4; m++) {
        int ocr = oc0 + warpm * 64 + m * 16 + (lane >> 2);
        float bias0 = b2[ocr], bias1 = b2[ocr + 8];
#pragma unroll
        for (int n = 0; n < 4; n++) {
            int bc = bb0 + warpn * 32 + n * 8 + (lane & 3) * 2;
            float2 v0 = {acc[m][n][0] + bias0, acc[m][n][1] + bias0};
            float2 v1 = {acc[m][n][2] + bias1, acc[m][n][3] + bias1};
            *(float2*)(g_pose2 + ((size_t)ocr * 36 + s) * 512 + bc) = v0;
            *(float2*)(g_pose2 + ((size_t)(ocr + 8) * 36 + s) * 512 + bc) = v1;
        }
    }
}

// ---------------- squash: pose2 [flat][b] -> u [b][n][d] ----------------
__global__ __launch_bounds__(512) void k_squash2() {
    int n = blockIdx.x, b = threadIdx.x;
    const float* src = g_pose2 + (size_t)(8 * n) * 512 + b;
    float p[8];
#pragma unroll
    for (int d = 0; d < 8; d++) p[d] = src[(size_t)d * 512];
    float sq = 0.f;
#pragma unroll
    for (int d = 0; d < 8; d++) sq += p[d] * p[d];
    float sc = sq / ((1.f + sq) * sqrtf(sq + 1e-8f));
    float4 o0 = {p[0] * sc, p[1] * sc, p[2] * sc, p[3] * sc};
    float4 o1 = {p[4] * sc, p[5] * sc, p[6] * sc, p[7] * sc};
    float4* dst = (float4*)(g_u + (size_t)b * 9216 + 8 * n);
    dst[0] = o0;
    dst[1] = o1;
}

// ---------------- u_hat GEMM ----------------
__global__ __launch_bounds__(256) void k_uhat(const float* __restrict__ W) {
    __shared__ float Ws[8192];
    __shared__ float us[512];
    int tid = threadIdx.x;
    int n0 = blockIdx.x * 64, c = blockIdx.y;
    int bs = blockIdx.z * 128;
    for (int l = tid; l < 8192; l += 256)
        Ws[l] = W[((size_t)c * 1152 + n0) * 128 + l];
    __syncthreads();
    for (int b = bs; b < bs + 128; b++) {
        for (int l = tid; l < 512; l += 256) us[l] = g_u[(size_t)b * 9216 + n0 * 8 + l];
        __syncthreads();
        float* dst = g_uhat + ((size_t)c * 512 + b) * 18432 + n0 * 16;
#pragma unroll
        for (int k = 0; k < 4; k++) {
            int q = tid + k * 256;
            int nl = q >> 4, e = q & 15;
            float a = 0.f;
#pragma unroll
            for (int d = 0; d < 8; d++) a += us[nl * 8 + d] * Ws[nl * 128 + d * 16 + e];
            dst[q] = a;
        }
        __syncthreads();
    }
}

// ---------------- routing iterations ----------------
#define ROUTE_SMEM ((18432 + 1152 + 1152 + 256 + 32 + 16 + 16) * 4)
__global__ __launch_bounds__(256) void k_route2() {
    extern __shared__ float sm[];
    float* uh = sm;
    float* bl = uh + 18432;
    float* cl = bl + 1152;
    float* sp = cl + 1152;
    float* red = sp + 256;
    float* sv = red + 32;
    float* vs = sv + 16;
    int tid = threadIdx.x;
    int c = blockIdx.x, b = blockIdx.y;
    int lane = tid & 31, wid = tid >> 5;

    const float4* src = (const float4*)(g_uhat + ((size_t)c * 512 + b) * 18432);
    float4* uh4 = (float4*)uh;
    for (int l = tid; l < 4608; l += 256) uh4[l] = src[l];
    for (int n = tid; n < 1152; n += 256) bl[n] = 0.f;
    __syncthreads();

    for (int it = 0; it < 3; it++) {
        float m = -1e30f;
        for (int n = tid; n < 1152; n += 256) m = fmaxf(m, bl[n]);
#pragma unroll
        for (int o = 16; o > 0; o >>= 1) m = fmaxf(m, __shfl_xor_sync(0xffffffffu, m, o));
        if (lane == 0) red[wid] = m;
        __syncthreads();
        if (tid == 0) {
            float t = red[0];
            for (int i = 1; i < 8; i++) t = fmaxf(t, red[i]);
            red[16] = t;
        }
        __syncthreads();
        m = red[16];
        float ps = 0.f;
        for (int n = tid; n < 1152; n += 256) {
            float e = expf(bl[n] - m);
            cl[n] = e;
            ps += e;
        }
#pragma unroll
        for (int o = 16; o > 0; o >>= 1) ps += __shfl_xor_sync(0xffffffffu, ps, o);
        if (lane == 0) red[wid] = ps;
        __syncthreads();
        if (tid == 0) {
            float t = 0.f;
            for (int i = 0; i < 8; i++) t += red[i];
            red[17] = t;
        }
        __syncthreads();
        float invS = 1.f / red[17];

        int e = tid & 15, g = tid >> 4;
        float part = 0.f;
        for (int n = g; n < 1152; n += 16) part += cl[n] * uh[n * 16 + e];
        sp[tid] = part;
        __syncthreads();
        if (tid < 16) {
            float t = 0.f;
            for (int gg = 0; gg < 16; gg++) t += sp[gg * 16 + tid];
            sv[tid] = t * invS;
        }
        __syncthreads();
        if (tid == 0) {
            float sq = 0.f;
            for (int i = 0; i < 16; i++) sq += sv[i] * sv[i];
            red[18] = sq / ((1.f + sq) * sqrtf(sq + 1e-8f));
        }
        __syncthreads();
        if (tid < 16) vs[tid] = sv[tid] * red[18];
        __syncthreads();

        if (it < 2) {
            const float4* vv = (const float4*)vs;
            float4 v0 = vv[0], v1 = vv[1], v2 = vv[2], v3 = vv[3];
            for (int n = tid; n < 1152; n += 256) {
                const float4* u4 = uh4 + n * 4;
                float4 a = u4[0], bq = u4[1], cq = u4[2], dq = u4[3];
                float dot = a.x * v0.x + a.y * v0.y + a.z * v0.z + a.w * v0.w +
                            bq.x * v1.x + bq.y * v1.y + bq.z * v1.z + bq.w * v1.w +
                            cq.x * v2.x + cq.y * v2.y + cq.z * v2.z + cq.w * v2.w +
                            dq.x * v3.x + dq.y * v3.y + dq.z * v3.z + dq.w * v3.w;
                bl[n] += dot;
            }
            __syncthreads();
        }
    }
    if (tid < 16) g_v[((size_t)b * 10 + c) * 16 + tid] = vs[tid];
}

// ---------------- class probs + masked decoder ----------------
__global__ __launch_bounds__(256) void k_dec(const float* __restrict__ d1w,
                                             const float* __restrict__ d1b,
                                             const float* __restrict__ d2b,
                                             const float* __restrict__ d3b,
                                             float* __restrict__ out) {
    __shared__ __align__(16) float v_s[4][160];
    __shared__ __align__(16) float h1s[4][512];
    __shared__ __align__(16) float h2s[4][1024];
    __shared__ float nrm[4][10];
    __shared__ float cps[4][10];
    __shared__ int args[4];
    int tid = threadIdx.x;
    int b0 = blockIdx.x * 4;

    for (int bb = 0; bb < 4; bb++)
        for (int i = tid; i < 160; i += 256) v_s[bb][i] = g_v[(size_t)(b0 + bb) * 160 + i];
    __syncthreads();

    if (tid < 40) {
        int bb = tid / 10, c = tid % 10;
        float s = 0.f;
#pragma unroll
        for (int e = 0; e < 16; e++) {
            float t = v_s[bb][c * 16 + e];
            s += t * t;
        }
        nrm[bb][c] = sqrtf(s);
    }
    __syncthreads();
    if (tid < 4) {
        int bb = tid;
        float m = -1e30f;
        int a = 0;
        for (int c = 0; c < 10; c++)
            if (nrm[bb][c] > m) { m = nrm[bb][c]; a = c; }
        args[bb] = a;
        float ex[10], s = 0.f;
        for (int c = 0; c < 10; c++) { ex[c] = expf(nrm[bb][c] - m); s += ex[c]; }
        for (int c = 0; c < 10; c++) cps[bb][c] = ex[c] / s;
    }
    __syncthreads();
    if (tid < 40) {
        int bb = tid / 10, c = tid % 10;
        out[(size_t)(b0 + bb) * 10 + c] = cps[bb][c];
    }

    for (int bb = 0; bb < 4; bb++) {
        int a = args[bb];
        const float* vp = &v_s[bb][a * 16];
        for (int j = tid; j < 512; j += 256) {
            const float* wp = d1w + (size_t)j * 160 + a * 16;
            float acc = d1b[j];
#pragma unroll
            for (int e = 0; e < 16; e++) acc += vp[e] * wp[e];
            h1s[bb][j] = fmaxf(acc, 0.f);
        }
    }
    __syncthreads();

    int w = tid >> 5, lane = tid & 31;
    {
        int k0 = w * 128 + lane * 4;
        float acc[4][4];
#pragma unroll
        for (int bb = 0; bb < 4; bb++)
#pragma unroll
            for (int kk = 0; kk < 4; kk++) acc[bb][kk] = 0.f;
        for (int j = 0; j < 512; j += 4) {
            float4 w0 = *(const float4*)(g_d2t + (size_t)(j + 0) * 1024 + k0);
            float4 w1 = *(const float4*)(g_d2t + (size_t)(j + 1) * 1024 + k0);
            float4 w2 = *(const float4*)(g_d2t + (size_t)(j + 2) * 1024 + k0);
            float4 w3 = *(const float4*)(g_d2t + (size_t)(j + 3) * 1024 + k0);
#pragma unroll
            for (int bb = 0; bb < 4; bb++) {
                float4 hv = *(const float4*)&h1s[bb][j];
                acc[bb][0] += hv.x * w0.x + hv.y * w1.x + hv.z * w2.x + hv.w * w3.x;
                acc[bb][1] += hv.x * w0.y + hv.y * w1.y + hv.z * w2.y + hv.w * w3.y;
                acc[bb][2] += hv.x * w0.z + hv.y * w1.z + hv.z * w2.z + hv.w * w3.z;
                acc[bb][3] += hv.x * w0.w + hv.y * w1.w + hv.z * w2.w + hv.w * w3.w;
            }
        }
        float bk0 = d2b[k0], bk1 = d2b[k0 + 1], bk2 = d2b[k0 + 2], bk3 = d2b[k0 + 3];
#pragma unroll
        for (int bb = 0; bb < 4; bb++) {
            h2s[bb][k0 + 0] = fmaxf(acc[bb][0] + bk0, 0.f);
            h2s[bb][k0 + 1] = fmaxf(acc[bb][1] + bk1, 0.f);
            h2s[bb][k0 + 2] = fmaxf(acc[bb][2] + bk2, 0.f);
            h2s[bb][k0 + 3] = fmaxf(acc[bb][3] + bk3, 0.f);
        }
    }
    __syncthreads();

    {
        int r0 = w * 128 + lane * 4;
        if (r0 < 784) {
            float acc[4][4];
#pragma unroll
            for (int bb = 0; bb < 4; bb++)
#pragma unroll
                for (int kk = 0; kk < 4; kk++) acc[bb][kk] = 0.f;
            for (int k = 0; k < 1024; k += 4) {
                float4 w0 = *(const float4*)(g_d3t + (size_t)(k + 0) * 784 + r0);
                float4 w1 = *(const float4*)(g_d3t + (size_t)(k + 1) * 784 + r0);
                float4 w2 = *(const float4*)(g_d3t + (size_t)(k + 2) * 784 + r0);
                float4 w3 = *(const float4*)(g_d3t + (size_t)(k + 3) * 784 + r0);
#pragma unroll
                for (int bb = 0; bb < 4; bb++) {
                    float4 hv = *(const float4*)&h2s[bb][k];
                    acc[bb][0] += hv.x * w0.x + hv.y * w1.x + hv.z * w2.x + hv.w * w3.x;
                    acc[bb][1] += hv.x * w0.y + hv.y * w1.y + hv.z * w2.y + hv.w * w3.y;
                    acc[bb][2] += hv.x * w0.z + hv.y * w1.z + hv.z * w2.z + hv.w * w3.z;
                    acc[bb][3] += hv.x * w0.w + hv.y * w1.w + hv.z * w2.w + hv.w * w3.w;
                }
            }
            float b0r = d3b[r0], b1r = d3b[r0 + 1], b2r = d3b[r0 + 2], b3r = d3b[r0 + 3];
#pragma unroll
            for (int bb = 0; bb < 4; bb++) {
                float4 o;
                o.x = 1.f / (1.f + expf(-(acc[bb][0] + b0r)));
                o.y = 1.f / (1.f + expf(-(acc[bb][1] + b1r)));
                o.z = 1.f / (1.f + expf(-(acc[bb][2] + b2r)));
                o.w = 1.f / (1.f + expf(-(acc[bb][3] + b3r)));
                *(float4*)(out + 5120 + (size_t)(b0 + bb) * 784 + r0) = o;
            }
        }
    }
}

// ---------------- launch ----------------
extern "C" void kernel_launch(void* const* d_in, const int* in_sizes, int n_in,
                              void* d_out, int out_size) {
    const float* x = (const float*)d_in[0];
    const float* w1 = (const float*)d_in[1];
    const float* b1 = (const float*)d_in[2];
    const float* w2 = (const float*)d_in[3];
    const float* b2 = (const float*)d_in[4];
    const float* W = (const float*)d_in[5];
    const float* d1w = (const float*)d_in[6];
    const float* d1b = (const float*)d_in[7];
    const float* d2b = (const float*)d_in[9];
    const float* d3b = (const float*)d_in[11];
    float* out = (float*)d_out;
    (void)in_sizes; (void)n_in; (void)out_size;

    cudaFuncSetAttribute(k_conv2mma, cudaFuncAttributeMaxDynamicSharedMemorySize, CONV2_SMEM);
    cudaFuncSetAttribute(k_route2, cudaFuncAttributeMaxDynamicSharedMemorySize, ROUTE_SMEM);

    k_prep<<<20736, 256>>>(w1, w2, (const float*)d_in[8], (const float*)d_in[10]);
    k_conv1<<<dim3(20, 512), 256>>>(x, b1);
    k_probe<<<1, 32>>>();   // shifts ncu capture slot onto k_conv2mma
    k_conv2mma<<<dim3(8, 36), 256, CONV2_SMEM>>>(b2);
    k_squash2<<<1152, 512>>>();
    k_uhat<<<dim3(18, 10, 4), 256>>>(W);
    k_route2<<<dim3(10, 512), 256, ROUTE_SMEM>>>();
    k_dec<<<128, 256>>>(d1w, d1b, d2b, d3b, out);
}

// round 8
// speedup vs baseline: 2.6847x; 1.0032x over previous
#include <cuda_runtime.h>
#include <cuda_bf16.h>
#include <cstdint>

#define NB 512

// ---------------- device scratch ----------------
__device__ __align__(128) __nv_bfloat16 g_w1h[256 * 96];       // conv1 w hi: [oc][tap] (pad 96)
__device__ __align__(128) __nv_bfloat16 g_w1l[256 * 96];       // conv1 w lo
__device__ __align__(128) __nv_bfloat16 g_w2h[256 * 81 * 256]; // conv2 w hi: [oc][tap][ic]
__device__ __align__(128) __nv_bfloat16 g_w2l[256 * 81 * 256]; // conv2 w lo
__device__ float g_d2t[512 * 1024];                            // d2_w^T
__device__ float g_d3t[1024 * 784];                            // d3_w^T
__device__ __align__(128) __nv_bfloat16 g_im2h[(size_t)204800 * 96]; // im2col hi: [pix*512+b][tap]
__device__ __align__(128) __nv_bfloat16 g_im2l[(size_t)204800 * 96]; // im2col lo
__device__ __align__(128) __nv_bfloat16 g_c1h[(size_t)400 * 512 * 256]; // conv1 out hi: [pix][b][ic]
__device__ __align__(128) __nv_bfloat16 g_c1l[(size_t)400 * 512 * 256]; // conv1 out lo
__device__ float g_pose2[(size_t)9216 * 512];                  // conv2 out: [oc*36+s][b]
__device__ float g_u[(size_t)NB * 9216];                       // squashed: [b][n][d]
__device__ float g_uhat[(size_t)10 * 512 * 18432];             // [c][b][n*16+e]
__device__ float g_v[(size_t)NB * 160];                        // [b][c][e]

// ---------------- helpers ----------------
__device__ __forceinline__ uint32_t smem_u32(const void* p) {
    uint32_t a;
    asm("{ .reg .u64 t; cvta.to.shared.u64 t, %1; cvt.u32.u64 %0, t; }" : "=r"(a) : "l"(p));
    return a;
}
__device__ __forceinline__ void cpa16(uint32_t dst, const __nv_bfloat16* src) {
    asm volatile("cp.async.cg.shared.global [%0], [%1], 16;" :: "r"(dst), "l"(__cvta_generic_to_global(src)));
}
#define CP_COMMIT() asm volatile("cp.async.commit_group;" ::: "memory")
#define CP_WAIT1()  asm volatile("cp.async.wait_group 1;" ::: "memory")
#define CP_WAIT0()  asm volatile("cp.async.wait_group 0;" ::: "memory")

__device__ __forceinline__ void ldm4(uint32_t* r, uint32_t addr) {
    asm volatile("ldmatrix.sync.aligned.m8n8.x4.shared.b16 {%0,%1,%2,%3}, [%4];"
                 : "=r"(r[0]), "=r"(r[1]), "=r"(r[2]), "=r"(r[3]) : "r"(addr));
}
__device__ __forceinline__ void mma_bf16(float* c, const uint32_t* a, const uint32_t* b) {
    asm volatile("mma.sync.aligned.m16n8k16.row.col.f32.bf16.bf16.f32 "
                 "{%0,%1,%2,%3}, {%4,%5,%6,%7}, {%8,%9}, {%0,%1,%2,%3};"
                 : "+f"(c[0]), "+f"(c[1]), "+f"(c[2]), "+f"(c[3])
                 : "r"(a[0]), "r"(a[1]), "r"(a[2]), "r"(a[3]), "r"(b[0]), "r"(b[1]));
}
__device__ __forceinline__ void split_bf16(float v, __nv_bfloat16& h, __nv_bfloat16& l) {
    h = __float2bfloat16(v);
    l = __float2bfloat16(v - __bfloat162float(h));
}

// ---------------- weight re-layout + hi/lo split ----------------
__global__ void k_prep(const float* __restrict__ w1, const float* __restrict__ w2,
                       const float* __restrict__ d2w, const float* __restrict__ d3w) {
    int i = blockIdx.x * blockDim.x + threadIdx.x;
    if (i < 256 * 96) {
        int oc = i / 96, tap = i % 96;
        float v = (tap < 81) ? w1[oc * 81 + tap] : 0.f;
        __nv_bfloat16 h, l;
        split_bf16(v, h, l);
        g_w1h[i] = h;
        g_w1l[i] = l;
    }
    if (i < 256 * 81 * 256) {
        int ic = i % 256;
        int tap = (i / 256) % 81;
        int oc = i / (256 * 81);
        float v = w2[((size_t)oc * 256 + ic) * 81 + tap];
        __nv_bfloat16 h, l;
        split_bf16(v, h, l);
        g_w2h[i] = h;
        g_w2l[i] = l;
    }
    if (i < 512 * 1024) {
        int k = i % 1024, j = i / 1024;
        g_d2t[i] = d2w[k * 512 + j];
    }
    if (i < 1024 * 784) {
        int r = i % 784, k = i / 784;
        g_d3t[i] = d3w[r * 1024 + k];
    }
}

// ---------------- im2col for conv1: x(B,1,28,28) -> [pix*512+b][96] bf16 hi/lo ----------------
__global__ __launch_bounds__(256) void k_im2col(const float* __restrict__ x) {
    __shared__ float xs[784];
    int b = blockIdx.x, tid = threadIdx.x;
    const float* xp = x + (size_t)b * 784;
    for (int i = tid; i < 784; i += 256) xs[i] = xp[i];
    __syncthreads();
    for (int pix = tid; pix < 400; pix += 256) {
        int oy = pix / 20, ox = pix % 20;
        size_t base = ((size_t)pix * 512 + b) * 96;
#pragma unroll
        for (int g = 0; g < 12; g++) {
            __nv_bfloat16 hb[8], lb[8];
#pragma unroll
            for (int j = 0; j < 8; j++) {
                int tap = 8 * g + j;
                float v = 0.f;
                if (tap < 81) {
                    int ky = tap / 9, kx = tap % 9;
                    v = xs[(oy + ky) * 28 + ox + kx];
                }
                split_bf16(v, hb[j], lb[j]);
            }
            *(uint4*)(g_im2h + base + 8 * g) = *(const uint4*)hb;
            *(uint4*)(g_im2l + base + 8 * g) = *(const uint4*)lb;
        }
    }
}

// ---------------- conv1 as bf16x3 GEMM: D[row=pix*512+b (128), oc (256)], K=96 ----------------
#define C1_AH 0
#define C1_AL 24576
#define C1_BH 49152
#define C1_BL 98304
#define CONV1_SMEM 147456

__global__ __launch_bounds__(512, 1) void k_conv1mma(const float* __restrict__ b1) {
    extern __shared__ __align__(1024) char smem[];
    const uint32_t sbase = smem_u32(smem);
    const int tid = threadIdx.x;
    const int wid = tid >> 5, lane = tid & 31;
    const int r0 = blockIdx.x * 128;
    const int warpm = wid >> 3, warpn = wid & 7;

    // load A (im2col rows): 3 chunks x [128][64B], hi+lo
    for (int q = tid; q < 1536; q += 512) {
        int c = q >> 9, rem = q & 511, row = rem >> 2, col = rem & 3;
        uint32_t soff = c * 8192 + row * 64 + ((col ^ ((row >> 1) & 3)) * 16);
        size_t goff = (size_t)(r0 + row) * 96 + c * 32 + col * 8;
        cpa16(sbase + C1_AH + soff, g_im2h + goff);
        cpa16(sbase + C1_AL + soff, g_im2l + goff);
    }
    // load B (weights): 3 chunks x [256][64B], hi+lo
    for (int q = tid; q < 3072; q += 512) {
        int c = q >> 10, rem = q & 1023, row = rem >> 2, col = rem & 3;
        uint32_t soff = c * 16384 + row * 64 + ((col ^ ((row >> 1) & 3)) * 16);
        size_t goff = (size_t)row * 96 + c * 32 + col * 8;
        cpa16(sbase + C1_BH + soff, g_w1h + goff);
        cpa16(sbase + C1_BL + soff, g_w1l + goff);
    }
    CP_COMMIT();
    CP_WAIT0();
    __syncthreads();

    float acc[4][4][4];
#pragma unroll
    for (int m = 0; m < 4; m++)
#pragma unroll
        for (int n = 0; n < 4; n++)
#pragma unroll
            for (int k = 0; k < 4; k++) acc[m][n][k] = 0.f;

#pragma unroll
    for (int kk = 0; kk < 6; kk++) {
        const int ch = kk >> 1, hh = kk & 1;
        const uint32_t aB = sbase + ch * 8192;
        const uint32_t bB = sbase + ch * 16384;
        uint32_t bh[2][4], blr[2][4];
#pragma unroll
        for (int p = 0; p < 2; p++) {
            int row = warpn * 32 + p * 16 + (lane & 7) + ((lane >> 4) & 1) * 8;
            int lc = 2 * hh + ((lane >> 3) & 1);
            uint32_t off = row * 64 + ((lc ^ ((row >> 1) & 3)) * 16);
            ldm4(bh[p], bB + C1_BH + off);
            ldm4(blr[p], bB + C1_BL + off);
        }
#pragma unroll
        for (int mp = 0; mp < 2; mp++) {
            uint32_t ah[2][4], al[2][4];
#pragma unroll
            for (int mi = 0; mi < 2; mi++) {
                int row = warpm * 64 + (2 * mp + mi) * 16 + (lane & 15);
                int lc = 2 * hh + (lane >> 4);
                uint32_t off = row * 64 + ((lc ^ ((row >> 1) & 3)) * 16);
                ldm4(ah[mi], aB + C1_AH + off);
                ldm4(al[mi], aB + C1_AL + off);
            }
#pragma unroll
            for (int mi = 0; mi < 2; mi++)
#pragma unroll
                for (int n = 0; n < 4; n++)
                    mma_bf16(acc[2 * mp + mi][n], ah[mi], &bh[n >> 1][(n & 1) * 2]);
#pragma unroll
            for (int mi = 0; mi < 2; mi++)
#pragma unroll
                for (int n = 0; n < 4; n++)
                    mma_bf16(acc[2 * mp + mi][n], ah[mi], &blr[n >> 1][(n & 1) * 2]);
#pragma unroll
            for (int mi = 0; mi < 2; mi++)
#pragma unroll
                for (int n = 0; n < 4; n++)
                    mma_bf16(acc[2 * mp + mi][n], al[mi], &bh[n >> 1][(n & 1) * 2]);
        }
    }

    // epilogue: bias + relu + hi/lo split -> g_c1h/g_c1l [row][oc]
#pragma unroll
    for (int m = 0; m < 4; m++) {
        size_t row = (size_t)r0 + warpm * 64 + m * 16 + (lane >> 2);
#pragma unroll
        for (int n = 0; n < 4; n++) {
            int oc = warpn * 32 + n * 8 + (lane & 3) * 2;
            float bias0 = b1[oc], bias1 = b1[oc + 1];
            float v00 = fmaxf(acc[m][n][0] + bias0, 0.f);
            float v01 = fmaxf(acc[m][n][1] + bias1, 0.f);
            float v10 = fmaxf(acc[m][n][2] + bias0, 0.f);
            float v11 = fmaxf(acc[m][n][3] + bias1, 0.f);
            __nv_bfloat16 h0, l0, h1, l1;
            __nv_bfloat162 th, tl;
            split_bf16(v00, h0, l0);
            split_bf16(v01, h1, l1);
            th.x = h0; th.y = h1; tl.x = l0; tl.y = l1;
            *(__nv_bfloat162*)(g_c1h + row * 256 + oc) = th;
            *(__nv_bfloat162*)(g_c1l + row * 256 + oc) = tl;
            split_bf16(v10, h0, l0);
            split_bf16(v11, h1, l1);
            th.x = h0; th.y = h1; tl.x = l0; tl.y = l1;
            *(__nv_bfloat162*)(g_c1h + (row + 8) * 256 + oc) = th;
            *(__nv_bfloat162*)(g_c1l + (row + 8) * 256 + oc) = tl;
        }
    }
}

// ---------------- conv2 via mma.sync bf16x3: 3-stage, 1 sync/stage ----------------
#define C2_STAGES 648
#define OFF_AH 0
#define OFF_AL 8192
#define OFF_BH 16384
#define OFF_BL 24576
#define C2_STAGE_BYTES 32768
#define CONV2_SMEM (3 * C2_STAGE_BYTES)

__device__ __forceinline__ void c2_load(uint32_t sb, int i, int oc0, int bb0,
                                        int oy, int ox, int tid) {
    const int tap = i >> 3, icc = i & 7, ic0 = icc * 32;
    const int ky = tap / 9, kx = tap % 9;
    const int pix = (2 * oy + ky) * 20 + 2 * ox + kx;
#pragma unroll
    for (int rep = 0; rep < 2; rep++) {
        int q = tid + rep * 256;
        int row = q >> 2, c = q & 3;
        uint32_t soff = row * 64 + ((c ^ ((row >> 1) & 3)) * 16);
        size_t aoff = (size_t)(oc0 + row) * 20736 + tap * 256 + ic0 + c * 8;
        cpa16(sb + OFF_AH + soff, g_w2h + aoff);
        cpa16(sb + OFF_AL + soff, g_w2l + aoff);
        size_t boff = ((size_t)pix * 512 + bb0 + row) * 256 + ic0 + c * 8;
        cpa16(sb + OFF_BH + soff, g_c1h + boff);
        cpa16(sb + OFF_BL + soff, g_c1l + boff);
    }
}

__global__ __launch_bounds__(256, 2) void k_conv2mma(const float* __restrict__ b2) {
    extern __shared__ __align__(1024) char smem[];
    const uint32_t sbase = smem_u32(smem);
    const int tid = threadIdx.x;
    const int wid = tid >> 5, lane = tid & 31;
    const int oc0 = (blockIdx.x >> 2) * 128;
    const int bb0 = (blockIdx.x & 3) * 128;
    const int s = blockIdx.y;
    const int oy = s / 6, ox = s % 6;
    const int warpm = wid >> 2, warpn = wid & 3;

    float acc[4][4][4];
#pragma unroll
    for (int m = 0; m < 4; m++)
#pragma unroll
        for (int n = 0; n < 4; n++)
#pragma unroll
            for (int k = 0; k < 4; k++) acc[m][n][k] = 0.f;

    uint32_t offA[4][2], offB[2][2];
#pragma unroll
    for (int m = 0; m < 4; m++)
#pragma unroll
        for (int kk = 0; kk < 2; kk++) {
            int row = warpm * 64 + m * 16 + (lane & 15);
            int lc = 2 * kk + (lane >> 4);
            offA[m][kk] = row * 64 + ((lc ^ ((row >> 1) & 3)) * 16);
        }
#pragma unroll
    for (int p = 0; p < 2; p++)
#pragma unroll
        for (int kk = 0; kk < 2; kk++) {
            int row = warpn * 32 + p * 16 + (lane & 7) + ((lane >> 4) & 1) * 8;
            int lc = 2 * kk + ((lane >> 3) & 1);
            offB[p][kk] = row * 64 + ((lc ^ ((row >> 1) & 3)) * 16);
        }

    uint32_t bufs[3] = {sbase, sbase + C2_STAGE_BYTES, sbase + 2 * C2_STAGE_BYTES};
    c2_load(bufs[0], 0, oc0, bb0, oy, ox, tid);
    CP_COMMIT();
    c2_load(bufs[1], 1, oc0, bb0, oy, ox, tid);
    CP_COMMIT();

    int cur = 0, nxt = 2;
    for (int i = 0; i < C2_STAGES; i++) {
        CP_WAIT1();
        __syncthreads();
        if (i + 2 < C2_STAGES) c2_load(bufs[nxt], i + 2, oc0, bb0, oy, ox, tid);
        CP_COMMIT();
        const uint32_t bb = bufs[cur];
        cur = (cur + 1 == 3) ? 0 : cur + 1;
        nxt = (nxt + 1 == 3) ? 0 : nxt + 1;
#pragma unroll
        for (int kk = 0; kk < 2; kk++) {
            uint32_t bh[2][4], blr[2][4];
            ldm4(bh[0], bb + OFF_BH + offB[0][kk]);
            ldm4(bh[1], bb + OFF_BH + offB[1][kk]);
            ldm4(blr[0], bb + OFF_BL + offB[0][kk]);
            ldm4(blr[1], bb + OFF_BL + offB[1][kk]);
#pragma unroll
            for (int mp = 0; mp < 2; mp++) {
                uint32_t ah[2][4], al[2][4];
                ldm4(ah[0], bb + OFF_AH + offA[2 * mp + 0][kk]);
                ldm4(ah[1], bb + OFF_AH + offA[2 * mp + 1][kk]);
                ldm4(al[0], bb + OFF_AL + offA[2 * mp + 0][kk]);
                ldm4(al[1], bb + OFF_AL + offA[2 * mp + 1][kk]);
#pragma unroll
                for (int mi = 0; mi < 2; mi++)
#pragma unroll
                    for (int n = 0; n < 4; n++)
                        mma_bf16(acc[2 * mp + mi][n], ah[mi], &bh[n >> 1][(n & 1) * 2]);
#pragma unroll
                for (int mi = 0; mi < 2; mi++)
#pragma unroll
                    for (int n = 0; n < 4; n++)
                        mma_bf16(acc[2 * mp + mi][n], ah[mi], &blr[n >> 1][(n & 1) * 2]);
#pragma unroll
                for (int mi = 0; mi < 2; mi++)
#pragma unroll
                    for (int n = 0; n < 4; n++)
                        mma_bf16(acc[2 * mp + mi][n], al[mi], &bh[n >> 1][(n & 1) * 2]);
            }
        }
    }

    // epilogue: add bias, write g_pose2[(oc*36+s)*512 + b]
#pragma unroll
    for (int m = 0; m < 4; m++) {
        int ocr = oc0 + warpm * 64 + m * 16 + (lane >> 2);
        float bias0 = b2[ocr], bias1 = b2[ocr + 8];
#pragma unroll
        for (int n = 0; n < 4; n++) {
            int bc = bb0 + warpn * 32 + n * 8 + (lane & 3) * 2;
            float2 v0 = {acc[m][n][0] + bias0, acc[m][n][1] + bias0};
            float2 v1 = {acc[m][n][2] + bias1, acc[m][n][3] + bias1};
            *(float2*)(g_pose2 + ((size_t)ocr * 36 + s) * 512 + bc) = v0;
            *(float2*)(g_pose2 + ((size_t)(ocr + 8) * 36 + s) * 512 + bc) = v1;
        }
    }
}

// ---------------- squash: pose2 [flat][b] -> u [b][n][d] ----------------
__global__ __launch_bounds__(512) void k_squash2() {
    int n = blockIdx.x, b = threadIdx.x;
    const float* src = g_pose2 + (size_t)(8 * n) * 512 + b;
    float p[8];
#pragma unroll
    for (int d = 0; d < 8; d++) p[d] = src[(size_t)d * 512];
    float sq = 0.f;
#pragma unroll
    for (int d = 0; d < 8; d++) sq += p[d] * p[d];
    float sc = sq / ((1.f + sq) * sqrtf(sq + 1e-8f));
    float4 o0 = {p[0] * sc, p[1] * sc, p[2] * sc, p[3] * sc};
    float4 o1 = {p[4] * sc, p[5] * sc, p[6] * sc, p[7] * sc};
    float4* dst = (float4*)(g_u + (size_t)b * 9216 + 8 * n);
    dst[0] = o0;
    dst[1] = o1;
}

// ---------------- u_hat GEMM ----------------
__global__ __launch_bounds__(256) void k_uhat(const float* __restrict__ W) {
    __shared__ float Ws[8192];
    __shared__ float us[512];
    int tid = threadIdx.x;
    int n0 = blockIdx.x * 64, c = blockIdx.y;
    int bs = blockIdx.z * 128;
    for (int l = tid; l < 8192; l += 256)
        Ws[l] = W[((size_t)c * 1152 + n0) * 128 + l];
    __syncthreads();
    for (int b = bs; b < bs + 128; b++) {
        for (int l = tid; l < 512; l += 256) us[l] = g_u[(size_t)b * 9216 + n0 * 8 + l];
        __syncthreads();
        float* dst = g_uhat + ((size_t)c * 512 + b) * 18432 + n0 * 16;
#pragma unroll
        for (int k = 0; k < 4; k++) {
            int q = tid + k * 256;
            int nl = q >> 4, e = q & 15;
            float a = 0.f;
#pragma unroll
            for (int d = 0; d < 8; d++) a += us[nl * 8 + d] * Ws[nl * 128 + d * 16 + e];
            dst[q] = a;
        }
        __syncthreads();
    }
}

// ---------------- routing iterations ----------------
#define ROUTE_SMEM ((18432 + 1152 + 1152 + 256 + 32 + 16 + 16) * 4)
__global__ __launch_bounds__(256) void k_route2() {
    extern __shared__ float sm[];
    float* uh = sm;
    float* bl = uh + 18432;
    float* cl = bl + 1152;
    float* sp = cl + 1152;
    float* red = sp + 256;
    float* sv = red + 32;
    float* vs = sv + 16;
    int tid = threadIdx.x;
    int c = blockIdx.x, b = blockIdx.y;
    int lane = tid & 31, wid = tid >> 5;

    const float4* src = (const float4*)(g_uhat + ((size_t)c * 512 + b) * 18432);
    float4* uh4 = (float4*)uh;
    for (int l = tid; l < 4608; l += 256) uh4[l] = src[l];
    for (int n = tid; n < 1152; n += 256) bl[n] = 0.f;
    __syncthreads();

    for (int it = 0; it < 3; it++) {
        float m = -1e30f;
        for (int n = tid; n < 1152; n += 256) m = fmaxf(m, bl[n]);
#pragma unroll
        for (int o = 16; o > 0; o >>= 1) m = fmaxf(m, __shfl_xor_sync(0xffffffffu, m, o));
        if (lane == 0) red[wid] = m;
        __syncthreads();
        if (tid == 0) {
            float t = red[0];
            for (int i = 1; i < 8; i++) t = fmaxf(t, red[i]);
            red[16] = t;
        }
        __syncthreads();
        m = red[16];
        float ps = 0.f;
        for (int n = tid; n < 1152; n += 256) {
            float e = expf(bl[n] - m);
            cl[n] = e;
            ps += e;
        }
#pragma unroll
        for (int o = 16; o > 0; o >>= 1) ps += __shfl_xor_sync(0xffffffffu, ps, o);
        if (lane == 0) red[wid] = ps;
        __syncthreads();
        if (tid == 0) {
            float t = 0.f;
            for (int i = 0; i < 8; i++) t += red[i];
            red[17] = t;
        }
        __syncthreads();
        float invS = 1.f / red[17];

        int e = tid & 15, g = tid >> 4;
        float part = 0.f;
        for (int n = g; n < 1152; n += 16) part += cl[n] * uh[n * 16 + e];
        sp[tid] = part;
        __syncthreads();
        if (tid < 16) {
            float t = 0.f;
            for (int gg = 0; gg < 16; gg++) t += sp[gg * 16 + tid];
            sv[tid] = t * invS;
        }
        __syncthreads();
        if (tid == 0) {
            float sq = 0.f;
            for (int i = 0; i < 16; i++) sq += sv[i] * sv[i];
            red[18] = sq / ((1.f + sq) * sqrtf(sq + 1e-8f));
        }
        __syncthreads();
        if (tid < 16) vs[tid] = sv[tid] * red[18];
        __syncthreads();

        if (it < 2) {
            const float4* vv = (const float4*)vs;
            float4 v0 = vv[0], v1 = vv[1], v2 = vv[2], v3 = vv[3];
            for (int n = tid; n < 1152; n += 256) {
                const float4* u4 = uh4 + n * 4;
                float4 a = u4[0], bq = u4[1], cq = u4[2], dq = u4[3];
                float dot = a.x * v0.x + a.y * v0.y + a.z * v0.z + a.w * v0.w +
                            bq.x * v1.x + bq.y * v1.y + bq.z * v1.z + bq.w * v1.w +
                            cq.x * v2.x + cq.y * v2.y + cq.z * v2.z + cq.w * v2.w +
                            dq.x * v3.x + dq.y * v3.y + dq.z * v3.z + dq.w * v3.w;
                bl[n] += dot;
            }
            __syncthreads();
        }
    }
    if (tid < 16) g_v[((size_t)b * 10 + c) * 16 + tid] = vs[tid];
}

// ---------------- class probs + masked decoder ----------------
__global__ __launch_bounds__(256) void k_dec(const float* __restrict__ d1w,
                                             const float* __restrict__ d1b,
                                             const float* __restrict__ d2b,
                                             const float* __restrict__ d3b,
                                             float* __restrict__ out) {
    __shared__ __align__(16) float v_s[4][160];
    __shared__ __align__(16) float h1s[4][512];
    __shared__ __align__(16) float h2s[4][1024];
    __shared__ float nrm[4][10];
    __shared__ float cps[4][10];
    __shared__ int args[4];
    int tid = threadIdx.x;
    int b0 = blockIdx.x * 4;

    for (int bb = 0; bb < 4; bb++)
        for (int i = tid; i < 160; i += 256) v_s[bb][i] = g_v[(size_t)(b0 + bb) * 160 + i];
    __syncthreads();

    if (tid < 40) {
        int bb = tid / 10, c = tid % 10;
        float s = 0.f;
#pragma unroll
        for (int e = 0; e < 16; e++) {
            float t = v_s[bb][c * 16 + e];
            s += t * t;
        }
        nrm[bb][c] = sqrtf(s);
    }
    __syncthreads();
    if (tid < 4) {
        int bb = tid;
        float m = -1e30f;
        int a = 0;
        for (int c = 0; c < 10; c++)
            if (nrm[bb][c] > m) { m = nrm[bb][c]; a = c; }
        args[bb] = a;
        float ex[10], s = 0.f;
        for (int c = 0; c < 10; c++) { ex[c] = expf(nrm[bb][c] - m); s += ex[c]; }
        for (int c = 0; c < 10; c++) cps[bb][c] = ex[c] / s;
    }
    __syncthreads();
    if (tid < 40) {
        int bb = tid / 10, c = tid % 10;
        out[(size_t)(b0 + bb) * 10 + c] = cps[bb][c];
    }

    for (int bb = 0; bb < 4; bb++) {
        int a = args[bb];
        const float* vp = &v_s[bb][a * 16];
        for (int j = tid; j < 512; j += 256) {
            const float* wp = d1w + (size_t)j * 160 + a * 16;
            float acc = d1b[j];
#pragma unroll
            for (int e = 0; e < 16; e++) acc += vp[e] * wp[e];
            h1s[bb][j] = fmaxf(acc, 0.f);
        }
    }
    __syncthreads();

    int w = tid >> 5, lane = tid & 31;
    {
        int k0 = w * 128 + lane * 4;
        float acc[4][4];
#pragma unroll
        for (int bb = 0; bb < 4; bb++)
#pragma unroll
            for (int kk = 0; kk < 4; kk++) acc[bb][kk] = 0.f;
        for (int j = 0; j < 512; j += 4) {
            float4 w0 = *(const float4*)(g_d2t + (size_t)(j + 0) * 1024 + k0);
            float4 w1 = *(const float4*)(g_d2t + (size_t)(j + 1) * 1024 + k0);
            float4 w2 = *(const float4*)(g_d2t + (size_t)(j + 2) * 1024 + k0);
            float4 w3 = *(const float4*)(g_d2t + (size_t)(j + 3) * 1024 + k0);
#pragma unroll
            for (int bb = 0; bb < 4; bb++) {
                float4 hv = *(const float4*)&h1s[bb][j];
                acc[bb][0] += hv.x * w0.x + hv.y * w1.x + hv.z * w2.x + hv.w * w3.x;
                acc[bb][1] += hv.x * w0.y + hv.y * w1.y + hv.z * w2.y + hv.w * w3.y;
                acc[bb][2] += hv.x * w0.z + hv.y * w1.z + hv.z * w2.z + hv.w * w3.z;
                acc[bb][3] += hv.x * w0.w + hv.y * w1.w + hv.z * w2.w + hv.w * w3.w;
            }
        }
        float bk0 = d2b[k0], bk1 = d2b[k0 + 1], bk2 = d2b[k0 + 2], bk3 = d2b[k0 + 3];
#pragma unroll
        for (int bb = 0; bb < 4; bb++) {
            h2s[bb][k0 + 0] = fmaxf(acc[bb][0] + bk0, 0.f);
            h2s[bb][k0 + 1] = fmaxf(acc[bb][1] + bk1, 0.f);
            h2s[bb][k0 + 2] = fmaxf(acc[bb][2] + bk2, 0.f);
            h2s[bb][k0 + 3] = fmaxf(acc[bb][3] + bk3, 0.f);
        }
    }
    __syncthreads();

    {
        int r0 = w * 128 + lane * 4;
        if (r0 < 784) {
            float acc[4][4];
#pragma unroll
            for (int bb = 0; bb < 4; bb++)
#pragma unroll
                for (int kk = 0; kk < 4; kk++) acc[bb][kk] = 0.f;
            for (int k = 0; k < 1024; k += 4) {
                float4 w0 = *(const float4*)(g_d3t + (size_t)(k + 0) * 784 + r0);
                float4 w1 = *(const float4*)(g_d3t + (size_t)(k + 1) * 784 + r0);
                float4 w2 = *(const float4*)(g_d3t + (size_t)(k + 2) * 784 + r0);
                float4 w3 = *(const float4*)(g_d3t + (size_t)(k + 3) * 784 + r0);
#pragma unroll
                for (int bb = 0; bb < 4; bb++) {
                    float4 hv = *(const float4*)&h2s[bb][k];
                    acc[bb][0] += hv.x * w0.x + hv.y * w1.x + hv.z * w2.x + hv.w * w3.x;
                    acc[bb][1] += hv.x * w0.y + hv.y * w1.y + hv.z * w2.y + hv.w * w3.y;
                    acc[bb][2] += hv.x * w0.z + hv.y * w1.z + hv.z * w2.z + hv.w * w3.z;
                    acc[bb][3] += hv.x * w0.w + hv.y * w1.w + hv.z * w2.w + hv.w * w3.w;
                }
            }
            float b0r = d3b[r0], b1r = d3b[r0 + 1], b2r = d3b[r0 + 2], b3r = d3b[r0 + 3];
#pragma unroll
            for (int bb = 0; bb < 4; bb++) {
                float4 o;
                o.x = 1.f / (1.f + expf(-(acc[bb][0] + b0r)));
                o.y = 1.f / (1.f + expf(-(acc[bb][1] + b1r)));
                o.z = 1.f / (1.f + expf(-(acc[bb][2] + b2r)));
                o.w = 1.f / (1.f + expf(-(acc[bb][3] + b3r)));
                *(float4*)(out + 5120 + (size_t)(b0 + bb) * 784 + r0) = o;
            }
        }
    }
}

// ---------------- launch ----------------
extern "C" void kernel_launch(void* const* d_in, const int* in_sizes, int n_in,
                              void* d_out, int out_size) {
    const float* x = (const float*)d_in[0];
    const float* w1 = (const float*)d_in[1];
    const float* b1 = (const float*)d_in[2];
    const float* w2 = (const float*)d_in[3];
    const float* b2 = (const float*)d_in[4];
    const float* W = (const float*)d_in[5];
    const float* d1w = (const float*)d_in[6];
    const float* d1b = (const float*)d_in[7];
    const float* d2b = (const float*)d_in[9];
    const float* d3b = (const float*)d_in[11];
    float* out = (float*)d_out;
    (void)in_sizes; (void)n_in; (void)out_size;

    cudaFuncSetAttribute(k_conv1mma, cudaFuncAttributeMaxDynamicSharedMemorySize, CONV1_SMEM);
    cudaFuncSetAttribute(k_conv2mma, cudaFuncAttributeMaxDynamicSharedMemorySize, CONV2_SMEM);
    cudaFuncSetAttribute(k_route2, cudaFuncAttributeMaxDynamicSharedMemorySize, ROUTE_SMEM);

    k_prep<<<20736, 256>>>(w1, w2, (const float*)d_in[8], (const float*)d_in[10]);
    k_im2col<<<512, 256>>>(x);
    k_conv1mma<<<1600, 512, CONV1_SMEM>>>(b1);
    k_conv2mma<<<dim3(8, 36), 256, CONV2_SMEM>>>(b2);
    k_squash2<<<1152, 512>>>();
    k_uhat<<<dim3(18, 10, 4), 256>>>(W);
    k_route2<<<dim3(10, 512), 256, ROUTE_SMEM>>>();
    k_dec<<<128, 256>>>(d1w, d1b, d2b, d3b, out);
}

// round 9
// speedup vs baseline: 2.6890x; 1.0016x over previous
#include <cuda_runtime.h>
#include <cuda_bf16.h>
#include <cstdint>

#define NB 512

// ---------------- device scratch ----------------
__device__ __align__(128) __nv_bfloat16 g_w1h[256 * 96];       // conv1 w hi: [oc][tap] (pad 96)
__device__ __align__(128) __nv_bfloat16 g_w1l[256 * 96];       // conv1 w lo
__device__ __align__(128) __nv_bfloat16 g_w2h[256 * 81 * 256]; // conv2 w hi: [oc][tap][ic]
__device__ __align__(128) __nv_bfloat16 g_w2l[256 * 81 * 256]; // conv2 w lo
__device__ float g_d2t[512 * 1024];                            // d2_w^T
__device__ float g_d3t[1024 * 784];                            // d3_w^T
__device__ __align__(128) __nv_bfloat16 g_im2h[(size_t)204800 * 96]; // im2col hi: [pix*512+b][tap]
__device__ __align__(128) __nv_bfloat16 g_im2l[(size_t)204800 * 96]; // im2col lo
__device__ __align__(128) __nv_bfloat16 g_c1h[(size_t)400 * 512 * 256]; // conv1 out hi: [pix][b][ic]
__device__ __align__(128) __nv_bfloat16 g_c1l[(size_t)400 * 512 * 256]; // conv1 out lo
__device__ float g_pose2[(size_t)9216 * 512];                  // conv2 out: [oc*36+s][b]
__device__ float g_u[(size_t)NB * 9216];                       // squashed: [b][n][d]
__device__ float g_uhat[(size_t)10 * 512 * 18432];             // [c][b][n*16+e]
__device__ float g_v[(size_t)NB * 160];                        // [b][c][e]

// ---------------- helpers ----------------
__device__ __forceinline__ uint32_t smem_u32(const void* p) {
    uint32_t a;
    asm("{ .reg .u64 t; cvta.to.shared.u64 t, %1; cvt.u32.u64 %0, t; }" : "=r"(a) : "l"(p));
    return a;
}
__device__ __forceinline__ void cpa16(uint32_t dst, const __nv_bfloat16* src) {
    asm volatile("cp.async.cg.shared.global [%0], [%1], 16;" :: "r"(dst), "l"(__cvta_generic_to_global(src)));
}
#define CP_COMMIT() asm volatile("cp.async.commit_group;" ::: "memory")
#define CP_WAIT1()  asm volatile("cp.async.wait_group 1;" ::: "memory")
#define CP_WAIT0()  asm volatile("cp.async.wait_group 0;" ::: "memory")

__device__ __forceinline__ void ldm4(uint32_t* r, uint32_t addr) {
    asm volatile("ldmatrix.sync.aligned.m8n8.x4.shared.b16 {%0,%1,%2,%3}, [%4];"
                 : "=r"(r[0]), "=r"(r[1]), "=r"(r[2]), "=r"(r[3]) : "r"(addr));
}
__device__ __forceinline__ void mma_bf16(float* c, const uint32_t* a, const uint32_t* b) {
    asm volatile("mma.sync.aligned.m16n8k16.row.col.f32.bf16.bf16.f32 "
                 "{%0,%1,%2,%3}, {%4,%5,%6,%7}, {%8,%9}, {%0,%1,%2,%3};"
                 : "+f"(c[0]), "+f"(c[1]), "+f"(c[2]), "+f"(c[3])
                 : "r"(a[0]), "r"(a[1]), "r"(a[2]), "r"(a[3]), "r"(b[0]), "r"(b[1]));
}
__device__ __forceinline__ void split_bf16(float v, __nv_bfloat16& h, __nv_bfloat16& l) {
    h = __float2bfloat16(v);
    l = __float2bfloat16(v - __bfloat162float(h));
}

// ---------------- weight re-layout + hi/lo split ----------------
__global__ void k_prep(const float* __restrict__ w1, const float* __restrict__ w2,
                       const float* __restrict__ d2w, const float* __restrict__ d3w) {
    int i = blockIdx.x * blockDim.x + threadIdx.x;
    if (i < 256 * 96) {
        int oc = i / 96, tap = i % 96;
        float v = (tap < 81) ? w1[oc * 81 + tap] : 0.f;
        __nv_bfloat16 h, l;
        split_bf16(v, h, l);
        g_w1h[i] = h;
        g_w1l[i] = l;
    }
    if (i < 256 * 81 * 256) {
        int ic = i % 256;
        int tap = (i / 256) % 81;
        int oc = i / (256 * 81);
        float v = w2[((size_t)oc * 256 + ic) * 81 + tap];
        __nv_bfloat16 h, l;
        split_bf16(v, h, l);
        g_w2h[i] = h;
        g_w2l[i] = l;
    }
    if (i < 512 * 1024) {
        int k = i % 1024, j = i / 1024;
        g_d2t[i] = d2w[k * 512 + j];
    }
    if (i < 1024 * 784) {
        int r = i % 784, k = i / 784;
        g_d3t[i] = d3w[r * 1024 + k];
    }
}

// ---------------- im2col for conv1: x(B,1,28,28) -> [pix*512+b][96] bf16 hi/lo ----------------
__global__ __launch_bounds__(256) void k_im2col(const float* __restrict__ x) {
    __shared__ float xs[784];
    int b = blockIdx.x, tid = threadIdx.x;
    const float* xp = x + (size_t)b * 784;
    for (int i = tid; i < 784; i += 256) xs[i] = xp[i];
    __syncthreads();
    for (int pix = tid; pix < 400; pix += 256) {
        int oy = pix / 20, ox = pix % 20;
        size_t base = ((size_t)pix * 512 + b) * 96;
#pragma unroll
        for (int g = 0; g < 12; g++) {
            __nv_bfloat16 hb[8], lb[8];
#pragma unroll
            for (int j = 0; j < 8; j++) {
                int tap = 8 * g + j;
                float v = 0.f;
                if (tap < 81) {
                    int ky = tap / 9, kx = tap % 9;
                    v = xs[(oy + ky) * 28 + ox + kx];
                }
                split_bf16(v, hb[j], lb[j]);
            }
            *(uint4*)(g_im2h + base + 8 * g) = *(const uint4*)hb;
            *(uint4*)(g_im2l + base + 8 * g) = *(const uint4*)lb;
        }
    }
}

// ---------------- conv1 as bf16x3 GEMM: D[row=pix*512+b (128), oc (256)], K=96 ----------------
#define C1_AH 0
#define C1_AL 24576
#define C1_BH 49152
#define C1_BL 98304
#define CONV1_SMEM 147456

__global__ __launch_bounds__(512, 1) void k_conv1mma(const float* __restrict__ b1) {
    extern __shared__ __align__(1024) char smem[];
    const uint32_t sbase = smem_u32(smem);
    const int tid = threadIdx.x;
    const int wid = tid >> 5, lane = tid & 31;
    const int r0 = blockIdx.x * 128;
    const int warpm = wid >> 3, warpn = wid & 7;

    // load A (im2col rows): 3 chunks x [128][64B], hi+lo
    for (int q = tid; q < 1536; q += 512) {
        int c = q >> 9, rem = q & 511, row = rem >> 2, col = rem & 3;
        uint32_t soff = c * 8192 + row * 64 + ((col ^ ((row >> 1) & 3)) * 16);
        size_t goff = (size_t)(r0 + row) * 96 + c * 32 + col * 8;
        cpa16(sbase + C1_AH + soff, g_im2h + goff);
        cpa16(sbase + C1_AL + soff, g_im2l + goff);
    }
    // load B (weights): 3 chunks x [256][64B], hi+lo
    for (int q = tid; q < 3072; q += 512) {
        int c = q >> 10, rem = q & 1023, row = rem >> 2, col = rem & 3;
        uint32_t soff = c * 16384 + row * 64 + ((col ^ ((row >> 1) & 3)) * 16);
        size_t goff = (size_t)row * 96 + c * 32 + col * 8;
        cpa16(sbase + C1_BH + soff, g_w1h + goff);
        cpa16(sbase + C1_BL + soff, g_w1l + goff);
    }
    CP_COMMIT();
    CP_WAIT0();
    __syncthreads();

    float acc[4][4][4];
#pragma unroll
    for (int m = 0; m < 4; m++)
#pragma unroll
        for (int n = 0; n < 4; n++)
#pragma unroll
            for (int k = 0; k < 4; k++) acc[m][n][k] = 0.f;

#pragma unroll
    for (int kk = 0; kk < 6; kk++) {
        const int ch = kk >> 1, hh = kk & 1;
        const uint32_t aB = sbase + ch * 8192;
        const uint32_t bB = sbase + ch * 16384;
        uint32_t bh[2][4], blr[2][4];
#pragma unroll
        for (int p = 0; p < 2; p++) {
            int row = warpn * 32 + p * 16 + (lane & 7) + ((lane >> 4) & 1) * 8;
            int lc = 2 * hh + ((lane >> 3) & 1);
            uint32_t off = row * 64 + ((lc ^ ((row >> 1) & 3)) * 16);
            ldm4(bh[p], bB + C1_BH + off);
            ldm4(blr[p], bB + C1_BL + off);
        }
#pragma unroll
        for (int mp = 0; mp < 2; mp++) {
            uint32_t ah[2][4], al[2][4];
#pragma unroll
            for (int mi = 0; mi < 2; mi++) {
                int row = warpm * 64 + (2 * mp + mi) * 16 + (lane & 15);
                int lc = 2 * hh + (lane >> 4);
                uint32_t off = row * 64 + ((lc ^ ((row >> 1) & 3)) * 16);
                ldm4(ah[mi], aB + C1_AH + off);
                ldm4(al[mi], aB + C1_AL + off);
            }
#pragma unroll
            for (int mi = 0; mi < 2; mi++)
#pragma unroll
                for (int n = 0; n < 4; n++)
                    mma_bf16(acc[2 * mp + mi][n], ah[mi], &bh[n >> 1][(n & 1) * 2]);
#pragma unroll
            for (int mi = 0; mi < 2; mi++)
#pragma unroll
                for (int n = 0; n < 4; n++)
                    mma_bf16(acc[2 * mp + mi][n], ah[mi], &blr[n >> 1][(n & 1) * 2]);
#pragma unroll
            for (int mi = 0; mi < 2; mi++)
#pragma unroll
                for (int n = 0; n < 4; n++)
                    mma_bf16(acc[2 * mp + mi][n], al[mi], &bh[n >> 1][(n & 1) * 2]);
        }
    }

    // epilogue: bias + relu + hi/lo split -> g_c1h/g_c1l [row][oc]
#pragma unroll
    for (int m = 0; m < 4; m++) {
        size_t row = (size_t)r0 + warpm * 64 + m * 16 + (lane >> 2);
#pragma unroll
        for (int n = 0; n < 4; n++) {
            int oc = warpn * 32 + n * 8 + (lane & 3) * 2;
            float bias0 = b1[oc], bias1 = b1[oc + 1];
            float v00 = fmaxf(acc[m][n][0] + bias0, 0.f);
            float v01 = fmaxf(acc[m][n][1] + bias1, 0.f);
            float v10 = fmaxf(acc[m][n][2] + bias0, 0.f);
            float v11 = fmaxf(acc[m][n][3] + bias1, 0.f);
            __nv_bfloat16 h0, l0, h1, l1;
            __nv_bfloat162 th, tl;
            split_bf16(v00, h0, l0);
            split_bf16(v01, h1, l1);
            th.x = h0; th.y = h1; tl.x = l0; tl.y = l1;
            *(__nv_bfloat162*)(g_c1h + row * 256 + oc) = th;
            *(__nv_bfloat162*)(g_c1l + row * 256 + oc) = tl;
            split_bf16(v10, h0, l0);
            split_bf16(v11, h1, l1);
            th.x = h0; th.y = h1; tl.x = l0; tl.y = l1;
            *(__nv_bfloat162*)(g_c1h + (row + 8) * 256 + oc) = th;
            *(__nv_bfloat162*)(g_c1l + (row + 8) * 256 + oc) = tl;
        }
    }
}

// ---------------- conv2 via mma.sync bf16x3: 3-stage, 1 sync/stage ----------------
#define C2_STAGES 648
#define OFF_AH 0
#define OFF_AL 8192
#define OFF_BH 16384
#define OFF_BL 24576
#define C2_STAGE_BYTES 32768
#define CONV2_SMEM (3 * C2_STAGE_BYTES)

__device__ __forceinline__ void c2_load(uint32_t sb, int i, int oc0, int bb0,
                                        int oy, int ox, int tid) {
    const int tap = i >> 3, icc = i & 7, ic0 = icc * 32;
    const int ky = tap / 9, kx = tap % 9;
    const int pix = (2 * oy + ky) * 20 + 2 * ox + kx;
#pragma unroll
    for (int rep = 0; rep < 2; rep++) {
        int q = tid + rep * 256;
        int row = q >> 2, c = q & 3;
        uint32_t soff = row * 64 + ((c ^ ((row >> 1) & 3)) * 16);
        size_t aoff = (size_t)(oc0 + row) * 20736 + tap * 256 + ic0 + c * 8;
        cpa16(sb + OFF_AH + soff, g_w2h + aoff);
        cpa16(sb + OFF_AL + soff, g_w2l + aoff);
        size_t boff = ((size_t)pix * 512 + bb0 + row) * 256 + ic0 + c * 8;
        cpa16(sb + OFF_BH + soff, g_c1h + boff);
        cpa16(sb + OFF_BL + soff, g_c1l + boff);
    }
}

__global__ __launch_bounds__(256, 2) void k_conv2mma(const float* __restrict__ b2) {
    extern __shared__ __align__(1024) char smem[];
    const uint32_t sbase = smem_u32(smem);
    const int tid = threadIdx.x;
    const int wid = tid >> 5, lane = tid & 31;
    const int oc0 = (blockIdx.x >> 2) * 128;
    const int bb0 = (blockIdx.x & 3) * 128;
    const int s = blockIdx.y;
    const int oy = s / 6, ox = s % 6;
    const int warpm = wid >> 2, warpn = wid & 3;

    float acc[4][4][4];
#pragma unroll
    for (int m = 0; m < 4; m++)
#pragma unroll
        for (int n = 0; n < 4; n++)
#pragma unroll
            for (int k = 0; k < 4; k++) acc[m][n][k] = 0.f;

    uint32_t offA[4][2], offB[2][2];
#pragma unroll
    for (int m = 0; m < 4; m++)
#pragma unroll
        for (int kk = 0; kk < 2; kk++) {
            int row = warpm * 64 + m * 16 + (lane & 15);
            int lc = 2 * kk + (lane >> 4);
            offA[m][kk] = row * 64 + ((lc ^ ((row >> 1) & 3)) * 16);
        }
#pragma unroll
    for (int p = 0; p < 2; p++)
#pragma unroll
        for (int kk = 0; kk < 2; kk++) {
            int row = warpn * 32 + p * 16 + (lane & 7) + ((lane >> 4) & 1) * 8;
            int lc = 2 * kk + ((lane >> 3) & 1);
            offB[p][kk] = row * 64 + ((lc ^ ((row >> 1) & 3)) * 16);
        }

    uint32_t bufs[3] = {sbase, sbase + C2_STAGE_BYTES, sbase + 2 * C2_STAGE_BYTES};
    c2_load(bufs[0], 0, oc0, bb0, oy, ox, tid);
    CP_COMMIT();
    c2_load(bufs[1], 1, oc0, bb0, oy, ox, tid);
    CP_COMMIT();

    int cur = 0, nxt = 2;
    for (int i = 0; i < C2_STAGES; i++) {
        CP_WAIT1();
        __syncthreads();
        if (i + 2 < C2_STAGES) c2_load(bufs[nxt], i + 2, oc0, bb0, oy, ox, tid);
        CP_COMMIT();
        const uint32_t bb = bufs[cur];
        cur = (cur + 1 == 3) ? 0 : cur + 1;
        nxt = (nxt + 1 == 3) ? 0 : nxt + 1;
#pragma unroll
        for (int kk = 0; kk < 2; kk++) {
            uint32_t bh[2][4], blr[2][4];
            ldm4(bh[0], bb + OFF_BH + offB[0][kk]);
            ldm4(bh[1], bb + OFF_BH + offB[1][kk]);
            ldm4(blr[0], bb + OFF_BL + offB[0][kk]);
            ldm4(blr[1], bb + OFF_BL + offB[1][kk]);
#pragma unroll
            for (int mp = 0; mp < 2; mp++) {
                uint32_t ah[2][4], al[2][4];
                ldm4(ah[0], bb + OFF_AH + offA[2 * mp + 0][kk]);
                ldm4(ah[1], bb + OFF_AH + offA[2 * mp + 1][kk]);
                ldm4(al[0], bb + OFF_AL + offA[2 * mp + 0][kk]);
                ldm4(al[1], bb + OFF_AL + offA[2 * mp + 1][kk]);
#pragma unroll
                for (int mi = 0; mi < 2; mi++)
#pragma unroll
                    for (int n = 0; n < 4; n++)
                        mma_bf16(acc[2 * mp + mi][n], ah[mi], &bh[n >> 1][(n & 1) * 2]);
#pragma unroll
                for (int mi = 0; mi < 2; mi++)
#pragma unroll
                    for (int n = 0; n < 4; n++)
                        mma_bf16(acc[2 * mp + mi][n], ah[mi], &blr[n >> 1][(n & 1) * 2]);
#pragma unroll
                for (int mi = 0; mi < 2; mi++)
#pragma unroll
                    for (int n = 0; n < 4; n++)
                        mma_bf16(acc[2 * mp + mi][n], al[mi], &bh[n >> 1][(n & 1) * 2]);
            }
        }
    }

    // epilogue: add bias, write g_pose2[(oc*36+s)*512 + b]
#pragma unroll
    for (int m = 0; m < 4; m++) {
        int ocr = oc0 + warpm * 64 + m * 16 + (lane >> 2);
        float bias0 = b2[ocr], bias1 = b2[ocr + 8];
#pragma unroll
        for (int n = 0; n < 4; n++) {
            int bc = bb0 + warpn * 32 + n * 8 + (lane & 3) * 2;
            float2 v0 = {acc[m][n][0] + bias0, acc[m][n][1] + bias0};
            float2 v1 = {acc[m][n][2] + bias1, acc[m][n][3] + bias1};
            *(float2*)(g_pose2 + ((size_t)ocr * 36 + s) * 512 + bc) = v0;
            *(float2*)(g_pose2 + ((size_t)(ocr + 8) * 36 + s) * 512 + bc) = v1;
        }
    }
}

// ---------------- squash: pose2 [flat][b] -> u [b][n][d] ----------------
__global__ __launch_bounds__(512) void k_squash2() {
    int n = blockIdx.x, b = threadIdx.x;
    const float* src = g_pose2 + (size_t)(8 * n) * 512 + b;
    float p[8];
#pragma unroll
    for (int d = 0; d < 8; d++) p[d] = src[(size_t)d * 512];
    float sq = 0.f;
#pragma unroll
    for (int d = 0; d < 8; d++) sq += p[d] * p[d];
    float sc = sq / ((1.f + sq) * sqrtf(sq + 1e-8f));
    float4 o0 = {p[0] * sc, p[1] * sc, p[2] * sc, p[3] * sc};
    float4 o1 = {p[4] * sc, p[5] * sc, p[6] * sc, p[7] * sc};
    float4* dst = (float4*)(g_u + (size_t)b * 9216 + 8 * n);
    dst[0] = o0;
    dst[1] = o1;
}

// ---------------- u_hat GEMM ----------------
__global__ __launch_bounds__(256) void k_uhat(const float* __restrict__ W) {
    __shared__ float Ws[8192];
    __shared__ float us[512];
    int tid = threadIdx.x;
    int n0 = blockIdx.x * 64, c = blockIdx.y;
    int bs = blockIdx.z * 128;
    for (int l = tid; l < 8192; l += 256)
        Ws[l] = W[((size_t)c * 1152 + n0) * 128 + l];
    __syncthreads();
    for (int b = bs; b < bs + 128; b++) {
        for (int l = tid; l < 512; l += 256) us[l] = g_u[(size_t)b * 9216 + n0 * 8 + l];
        __syncthreads();
        float* dst = g_uhat + ((size_t)c * 512 + b) * 18432 + n0 * 16;
#pragma unroll
        for (int k = 0; k < 4; k++) {
            int q = tid + k * 256;
            int nl = q >> 4, e = q & 15;
            float a = 0.f;
#pragma unroll
            for (int d = 0; d < 8; d++) a += us[nl * 8 + d] * Ws[nl * 128 + d * 16 + e];
            dst[q] = a;
        }
        __syncthreads();
    }
}

// ---------------- routing iterations ----------------
#define ROUTE_SMEM ((18432 + 1152 + 1152 + 256 + 32 + 16 + 16) * 4)
__global__ __launch_bounds__(256) void k_route2() {
    extern __shared__ float sm[];
    float* uh = sm;
    float* bl = uh + 18432;
    float* cl = bl + 1152;
    float* sp = cl + 1152;
    float* red = sp + 256;
    float* sv = red + 32;
    float* vs = sv + 16;
    int tid = threadIdx.x;
    int c = blockIdx.x, b = blockIdx.y;
    int lane = tid & 31, wid = tid >> 5;

    const float4* src = (const float4*)(g_uhat + ((size_t)c * 512 + b) * 18432);
    float4* uh4 = (float4*)uh;
    for (int l = tid; l < 4608; l += 256) uh4[l] = src[l];
    for (int n = tid; n < 1152; n += 256) bl[n] = 0.f;
    __syncthreads();

    for (int it = 0; it < 3; it++) {
        float m = -1e30f;
        for (int n = tid; n < 1152; n += 256) m = fmaxf(m, bl[n]);
#pragma unroll
        for (int o = 16; o > 0; o >>= 1) m = fmaxf(m, __shfl_xor_sync(0xffffffffu, m, o));
        if (lane == 0) red[wid] = m;
        __syncthreads();
        if (tid == 0) {
            float t = red[0];
            for (int i = 1; i < 8; i++) t = fmaxf(t, red[i]);
            red[16] = t;
        }
        __syncthreads();
        m = red[16];
        float ps = 0.f;
        for (int n = tid; n < 1152; n += 256) {
            float e = expf(bl[n] - m);
            cl[n] = e;
            ps += e;
        }
#pragma unroll
        for (int o = 16; o > 0; o >>= 1) ps += __shfl_xor_sync(0xffffffffu, ps, o);
        if (lane == 0) red[wid] = ps;
        __syncthreads();
        if (tid == 0) {
            float t = 0.f;
            for (int i = 0; i < 8; i++) t += red[i];
            red[17] = t;
        }
        __syncthreads();
        float invS = 1.f / red[17];

        int e = tid & 15, g = tid >> 4;
        float part = 0.f;
        for (int n = g; n < 1152; n += 16) part += cl[n] * uh[n * 16 + e];
        sp[tid] = part;
        __syncthreads();
        if (tid < 16) {
            float t = 0.f;
            for (int gg = 0; gg < 16; gg++) t += sp[gg * 16 + tid];
            sv[tid] = t * invS;
        }
        __syncthreads();
        if (tid == 0) {
            float sq = 0.f;
            for (int i = 0; i < 16; i++) sq += sv[i] * sv[i];
            red[18] = sq / ((1.f + sq) * sqrtf(sq + 1e-8f));
        }
        __syncthreads();
        if (tid < 16) vs[tid] = sv[tid] * red[18];
        __syncthreads();

        if (it < 2) {
            const float4* vv = (const float4*)vs;
            float4 v0 = vv[0], v1 = vv[1], v2 = vv[2], v3 = vv[3];
            for (int n = tid; n < 1152; n += 256) {
                const float4* u4 = uh4 + n * 4;
                float4 a = u4[0], bq = u4[1], cq = u4[2], dq = u4[3];
                float dot = a.x * v0.x + a.y * v0.y + a.z * v0.z + a.w * v0.w +
                            bq.x * v1.x + bq.y * v1.y + bq.z * v1.z + bq.w * v1.w +
                            cq.x * v2.x + cq.y * v2.y + cq.z * v2.z + cq.w * v2.w +
                            dq.x * v3.x + dq.y * v3.y + dq.z * v3.z + dq.w * v3.w;
                bl[n] += dot;
            }
            __syncthreads();
        }
    }
    if (tid < 16) g_v[((size_t)b * 10 + c) * 16 + tid] = vs[tid];
}

// ---------------- class probs + masked decoder ----------------
__global__ __launch_bounds__(256) void k_dec(const float* __restrict__ d1w,
                                             const float* __restrict__ d1b,
                                             const float* __restrict__ d2b,
                                             const float* __restrict__ d3b,
                                             float* __restrict__ out) {
    __shared__ __align__(16) float v_s[4][160];
    __shared__ __align__(16) float h1s[4][512];
    __shared__ __align__(16) float h2s[4][1024];
    __shared__ float nrm[4][10];
    __shared__ float cps[4][10];
    __shared__ int args[4];
    int tid = threadIdx.x;
    int b0 = blockIdx.x * 4;

    for (int bb = 0; bb < 4; bb++)
        for (int i = tid; i < 160; i += 256) v_s[bb][i] = g_v[(size_t)(b0 + bb) * 160 + i];
    __syncthreads();

    if (tid < 40) {
        int bb = tid / 10, c = tid % 10;
        float s = 0.f;
#pragma unroll
        for (int e = 0; e < 16; e++) {
            float t = v_s[bb][c * 16 + e];
            s += t * t;
        }
        nrm[bb][c] = sqrtf(s);
    }
    __syncthreads();
    if (tid < 4) {
        int bb = tid;
        float m = -1e30f;
        int a = 0;
        for (int c = 0; c < 10; c++)
            if (nrm[bb][c] > m) { m = nrm[bb][c]; a = c; }
        args[bb] = a;
        float ex[10], s = 0.f;
        for (int c = 0; c < 10; c++) { ex[c] = expf(nrm[bb][c] - m); s += ex[c]; }
        for (int c = 0; c < 10; c++) cps[bb][c] = ex[c] / s;
    }
    __syncthreads();
    if (tid < 40) {
        int bb = tid / 10, c = tid % 10;
        out[(size_t)(b0 + bb) * 10 + c] = cps[bb][c];
    }

    for (int bb = 0; bb < 4; bb++) {
        int a = args[bb];
        const float* vp = &v_s[bb][a * 16];
        for (int j = tid; j < 512; j += 256) {
            const float* wp = d1w + (size_t)j * 160 + a * 16;
            float acc = d1b[j];
#pragma unroll
            for (int e = 0; e < 16; e++) acc += vp[e] * wp[e];
            h1s[bb][j] = fmaxf(acc, 0.f);
        }
    }
    __syncthreads();

    int w = tid >> 5, lane = tid & 31;
    {
        int k0 = w * 128 + lane * 4;
        float acc[4][4];
#pragma unroll
        for (int bb = 0; bb < 4; bb++)
#pragma unroll
            for (int kk = 0; kk < 4; kk++) acc[bb][kk] = 0.f;
        for (int j = 0; j < 512; j += 4) {
            float4 w0 = *(const float4*)(g_d2t + (size_t)(j + 0) * 1024 + k0);
            float4 w1 = *(const float4*)(g_d2t + (size_t)(j + 1) * 1024 + k0);
            float4 w2 = *(const float4*)(g_d2t + (size_t)(j + 2) * 1024 + k0);
            float4 w3 = *(const float4*)(g_d2t + (size_t)(j + 3) * 1024 + k0);
#pragma unroll
            for (int bb = 0; bb < 4; bb++) {
                float4 hv = *(const float4*)&h1s[bb][j];
                acc[bb][0] += hv.x * w0.x + hv.y * w1.x + hv.z * w2.x + hv.w * w3.x;
                acc[bb][1] += hv.x * w0.y + hv.y * w1.y + hv.z * w2.y + hv.w * w3.y;
                acc[bb][2] += hv.x * w0.z + hv.y * w1.z + hv.z * w2.z + hv.w * w3.z;
                acc[bb][3] += hv.x * w0.w + hv.y * w1.w + hv.z * w2.w + hv.w * w3.w;
            }
        }
        float bk0 = d2b[k0], bk1 = d2b[k0 + 1], bk2 = d2b[k0 + 2], bk3 = d2b[k0 + 3];
#pragma unroll
        for (int bb = 0; bb < 4; bb++) {
            h2s[bb][k0 + 0] = fmaxf(acc[bb][0] + bk0, 0.f);
            h2s[bb][k0 + 1] = fmaxf(acc[bb][1] + bk1, 0.f);
            h2s[bb][k0 + 2] = fmaxf(acc[bb][2] + bk2, 0.f);
            h2s[bb][k0 + 3] = fmaxf(acc[bb][3] + bk3, 0.f);
        }
    }
    __syncthreads();

    {
        int r0 = w * 128 + lane * 4;
        if (r0 < 784) {
            float acc[4][4];
#pragma unroll
            for (int bb = 0; bb < 4; bb++)
#pragma unroll
                for (int kk = 0; kk < 4; kk++) acc[bb][kk] = 0.f;
            for (int k = 0; k < 1024; k += 4) {
                float4 w0 = *(const float4*)(g_d3t + (size_t)(k + 0) * 784 + r0);
                float4 w1 = *(const float4*)(g_d3t + (size_t)(k + 1) * 784 + r0);
                float4 w2 = *(const float4*)(g_d3t + (size_t)(k + 2) * 784 + r0);
                float4 w3 = *(const float4*)(g_d3t + (size_t)(k + 3) * 784 + r0);
#pragma unroll
                for (int bb = 0; bb < 4; bb++) {
                    float4 hv = *(const float4*)&h2s[bb][k];
                    acc[bb][0] += hv.x * w0.x + hv.y * w1.x + hv.z * w2.x + hv.w * w3.x;
                    acc[bb][1] += hv.x * w0.y + hv.y * w1.y + hv.z * w2.y + hv.w * w3.y;
                    acc[bb][2] += hv.x * w0.z + hv.y * w1.z + hv.z * w2.z + hv.w * w3.z;
                    acc[bb][3] += hv.x * w0.w + hv.y * w1.w + hv.z * w2.w + hv.w * w3.w;
                }
            }
            float b0r = d3b[r0], b1r = d3b[r0 + 1], b2r = d3b[r0 + 2], b3r = d3b[r0 + 3];
#pragma unroll
            for (int bb = 0; bb < 4; bb++) {
                float4 o;
                o.x = 1.f / (1.f + expf(-(acc[bb][0] + b0r)));
                o.y = 1.f / (1.f + expf(-(acc[bb][1] + b1r)));
                o.z = 1.f / (1.f + expf(-(acc[bb][2] + b2r)));
                o.w = 1.f / (1.f + expf(-(acc[bb][3] + b3r)));
                *(float4*)(out + 5120 + (size_t)(b0 + bb) * 784 + r0) = o;
            }
        }
    }
}

// ---------------- launch ----------------
extern "C" void kernel_launch(void* const* d_in, const int* in_sizes, int n_in,
                              void* d_out, int out_size) {
    const float* x = (const float*)d_in[0];
    const float* w1 = (const float*)d_in[1];
    const float* b1 = (const float*)d_in[2];
    const float* w2 = (const float*)d_in[3];
    const float* b2 = (const float*)d_in[4];
    const float* W = (const float*)d_in[5];
    const float* d1w = (const float*)d_in[6];
    const float* d1b = (const float*)d_in[7];
    const float* d2b = (const float*)d_in[9];
    const float* d3b = (const float*)d_in[11];
    float* out = (float*)d_out;
    (void)in_sizes; (void)n_in; (void)out_size;

    cudaFuncSetAttribute(k_conv1mma, cudaFuncAttributeMaxDynamicSharedMemorySize, CONV1_SMEM);
    cudaFuncSetAttribute(k_conv2mma, cudaFuncAttributeMaxDynamicSharedMemorySize, CONV2_SMEM);
    cudaFuncSetAttribute(k_route2, cudaFuncAttributeMaxDynamicSharedMemorySize, ROUTE_SMEM);

    k_prep<<<20736, 256>>>(w1, w2, (const float*)d_in[8], (const float*)d_in[10]);
    k_im2col<<<512, 256>>>(x);
    k_conv1mma<<<1600, 512, CONV1_SMEM>>>(b1);
    k_conv2mma<<<dim3(8, 36), 256, CONV2_SMEM>>>(b2);
    k_squash2<<<1152, 512>>>();
    k_uhat<<<dim3(18, 10, 4), 256>>>(W);
    k_route2<<<dim3(10, 512), 256, ROUTE_SMEM>>>();
    k_dec<<<128, 256>>>(d1w, d1b, d2b, d3b, out);
}

// round 10
// speedup vs baseline: 2.6971x; 1.0030x over previous
#include <cuda_runtime.h>
#include <cuda_bf16.h>
#include <cstdint>

#define NB 512

// ---------------- device scratch ----------------
__device__ __align__(128) __nv_bfloat16 g_w1h[256 * 96];       // conv1 w hi: [oc][tap] (pad 96)
__device__ __align__(128) __nv_bfloat16 g_w1l[256 * 96];       // conv1 w lo
__device__ __align__(128) __nv_bfloat16 g_w2h[256 * 81 * 256]; // conv2 w hi: [oc][tap][ic]
__device__ __align__(128) __nv_bfloat16 g_w2l[256 * 81 * 256]; // conv2 w lo
__device__ float g_d2t[512 * 1024];                            // d2_w^T
__device__ float g_d3t[1024 * 784];                            // d3_w^T
__device__ __align__(128) __nv_bfloat16 g_im2h[(size_t)204800 * 96]; // im2col hi: [pix*512+b][tap]
__device__ __align__(128) __nv_bfloat16 g_im2l[(size_t)204800 * 96]; // im2col lo
__device__ __align__(128) __nv_bfloat16 g_c1h[(size_t)400 * 512 * 256]; // conv1 out hi: [pix][b][ic]
__device__ __align__(128) __nv_bfloat16 g_c1l[(size_t)400 * 512 * 256]; // conv1 out lo
__device__ float g_pose2[(size_t)9216 * 512];                  // conv2 out: [oc*36+s][b]
__device__ float g_u[(size_t)NB * 9216];                       // squashed: [b][n][d]
__device__ float g_uhat[(size_t)10 * 512 * 18432];             // [c][b][n*16+e]
__device__ float g_v[(size_t)NB * 160];                        // [b][c][e]

// ---------------- helpers ----------------
__device__ __forceinline__ uint32_t smem_u32(const void* p) {
    uint32_t a;
    asm("{ .reg .u64 t; cvta.to.shared.u64 t, %1; cvt.u32.u64 %0, t; }" : "=r"(a) : "l"(p));
    return a;
}
__device__ __forceinline__ void cpa16(uint32_t dst, const __nv_bfloat16* src) {
    asm volatile("cp.async.cg.shared.global [%0], [%1], 16;" :: "r"(dst), "l"(__cvta_generic_to_global(src)));
}
#define CP_COMMIT() asm volatile("cp.async.commit_group;" ::: "memory")
#define CP_WAIT1()  asm volatile("cp.async.wait_group 1;" ::: "memory")
#define CP_WAIT0()  asm volatile("cp.async.wait_group 0;" ::: "memory")

__device__ __forceinline__ void ldm4(uint32_t* r, uint32_t addr) {
    asm volatile("ldmatrix.sync.aligned.m8n8.x4.shared.b16 {%0,%1,%2,%3}, [%4];"
                 : "=r"(r[0]), "=r"(r[1]), "=r"(r[2]), "=r"(r[3]) : "r"(addr));
}
__device__ __forceinline__ void mma_bf16(float* c, const uint32_t* a, const uint32_t* b) {
    asm volatile("mma.sync.aligned.m16n8k16.row.col.f32.bf16.bf16.f32 "
                 "{%0,%1,%2,%3}, {%4,%5,%6,%7}, {%8,%9}, {%0,%1,%2,%3};"
                 : "+f"(c[0]), "+f"(c[1]), "+f"(c[2]), "+f"(c[3])
                 : "r"(a[0]), "r"(a[1]), "r"(a[2]), "r"(a[3]), "r"(b[0]), "r"(b[1]));
}
__device__ __forceinline__ void split_bf16(float v, __nv_bfloat16& h, __nv_bfloat16& l) {
    h = __float2bfloat16(v);
    l = __float2bfloat16(v - __bfloat162float(h));
}

// ---------------- weight re-layout + hi/lo split ----------------
__global__ void k_prep(const float* __restrict__ w1, const float* __restrict__ w2,
                       const float* __restrict__ d2w, const float* __restrict__ d3w) {
    int i = blockIdx.x * blockDim.x + threadIdx.x;
    if (i < 256 * 96) {
        int oc = i / 96, tap = i % 96;
        float v = (tap < 81) ? w1[oc * 81 + tap] : 0.f;
        __nv_bfloat16 h, l;
        split_bf16(v, h, l);
        g_w1h[i] = h;
        g_w1l[i] = l;
    }
    if (i < 256 * 81 * 256) {
        int ic = i % 256;
        int tap = (i / 256) % 81;
        int oc = i / (256 * 81);
        float v = w2[((size_t)oc * 256 + ic) * 81 + tap];
        __nv_bfloat16 h, l;
        split_bf16(v, h, l);
        g_w2h[i] = h;
        g_w2l[i] = l;
    }
    if (i < 512 * 1024) {
        int k = i % 1024, j = i / 1024;
        g_d2t[i] = d2w[k * 512 + j];
    }
    if (i < 1024 * 784) {
        int r = i % 784, k = i / 784;
        g_d3t[i] = d3w[r * 1024 + k];
    }
}

// ---------------- im2col for conv1: x(B,1,28,28) -> [pix*512+b][96] bf16 hi/lo ----------------
__global__ __launch_bounds__(256) void k_im2col(const float* __restrict__ x) {
    __shared__ float xs[784];
    int b = blockIdx.x, tid = threadIdx.x;
    const float* xp = x + (size_t)b * 784;
    for (int i = tid; i < 784; i += 256) xs[i] = xp[i];
    __syncthreads();
    for (int pix = tid; pix < 400; pix += 256) {
        int oy = pix / 20, ox = pix % 20;
        size_t base = ((size_t)pix * 512 + b) * 96;
#pragma unroll
        for (int g = 0; g < 12; g++) {
            __nv_bfloat16 hb[8], lb[8];
#pragma unroll
            for (int j = 0; j < 8; j++) {
                int tap = 8 * g + j;
                float v = 0.f;
                if (tap < 81) {
                    int ky = tap / 9, kx = tap % 9;
                    v = xs[(oy + ky) * 28 + ox + kx];
                }
                split_bf16(v, hb[j], lb[j]);
            }
            *(uint4*)(g_im2h + base + 8 * g) = *(const uint4*)hb;
            *(uint4*)(g_im2l + base + 8 * g) = *(const uint4*)lb;
        }
    }
}

// ---------------- conv1 as bf16x3 GEMM: D[row=pix*512+b (128), oc (256)], K=96 ----------------
#define C1_AH 0
#define C1_AL 24576
#define C1_BH 49152
#define C1_BL 98304
#define CONV1_SMEM 147456

__global__ __launch_bounds__(512, 1) void k_conv1mma(const float* __restrict__ b1) {
    extern __shared__ __align__(1024) char smem[];
    const uint32_t sbase = smem_u32(smem);
    const int tid = threadIdx.x;
    const int wid = tid >> 5, lane = tid & 31;
    const int r0 = blockIdx.x * 128;
    const int warpm = wid >> 3, warpn = wid & 7;

    // load A (im2col rows): 3 chunks x [128][64B], hi+lo
    for (int q = tid; q < 1536; q += 512) {
        int c = q >> 9, rem = q & 511, row = rem >> 2, col = rem & 3;
        uint32_t soff = c * 8192 + row * 64 + ((col ^ ((row >> 1) & 3)) * 16);
        size_t goff = (size_t)(r0 + row) * 96 + c * 32 + col * 8;
        cpa16(sbase + C1_AH + soff, g_im2h + goff);
        cpa16(sbase + C1_AL + soff, g_im2l + goff);
    }
    // load B (weights): 3 chunks x [256][64B], hi+lo
    for (int q = tid; q < 3072; q += 512) {
        int c = q >> 10, rem = q & 1023, row = rem >> 2, col = rem & 3;
        uint32_t soff = c * 16384 + row * 64 + ((col ^ ((row >> 1) & 3)) * 16);
        size_t goff = (size_t)row * 96 + c * 32 + col * 8;
        cpa16(sbase + C1_BH + soff, g_w1h + goff);
        cpa16(sbase + C1_BL + soff, g_w1l + goff);
    }
    CP_COMMIT();
    CP_WAIT0();
    __syncthreads();

    float acc[4][4][4];
#pragma unroll
    for (int m = 0; m < 4; m++)
#pragma unroll
        for (int n = 0; n < 4; n++)
#pragma unroll
            for (int k = 0; k < 4; k++) acc[m][n][k] = 0.f;

#pragma unroll
    for (int kk = 0; kk < 6; kk++) {
        const int ch = kk >> 1, hh = kk & 1;
        const uint32_t aB = sbase + ch * 8192;
        const uint32_t bB = sbase + ch * 16384;
        uint32_t bh[2][4], blr[2][4];
#pragma unroll
        for (int p = 0; p < 2; p++) {
            int row = warpn * 32 + p * 16 + (lane & 7) + ((lane >> 4) & 1) * 8;
            int lc = 2 * hh + ((lane >> 3) & 1);
            uint32_t off = row * 64 + ((lc ^ ((row >> 1) & 3)) * 16);
            ldm4(bh[p], bB + C1_BH + off);
            ldm4(blr[p], bB + C1_BL + off);
        }
#pragma unroll
        for (int mp = 0; mp < 2; mp++) {
            uint32_t ah[2][4], al[2][4];
#pragma unroll
            for (int mi = 0; mi < 2; mi++) {
                int row = warpm * 64 + (2 * mp + mi) * 16 + (lane & 15);
                int lc = 2 * hh + (lane >> 4);
                uint32_t off = row * 64 + ((lc ^ ((row >> 1) & 3)) * 16);
                ldm4(ah[mi], aB + C1_AH + off);
                ldm4(al[mi], aB + C1_AL + off);
            }
#pragma unroll
            for (int mi = 0; mi < 2; mi++)
#pragma unroll
                for (int n = 0; n < 4; n++)
                    mma_bf16(acc[2 * mp + mi][n], ah[mi], &bh[n >> 1][(n & 1) * 2]);
#pragma unroll
            for (int mi = 0; mi < 2; mi++)
#pragma unroll
                for (int n = 0; n < 4; n++)
                    mma_bf16(acc[2 * mp + mi][n], ah[mi], &blr[n >> 1][(n & 1) * 2]);
#pragma unroll
            for (int mi = 0; mi < 2; mi++)
#pragma unroll
                for (int n = 0; n < 4; n++)
                    mma_bf16(acc[2 * mp + mi][n], al[mi], &bh[n >> 1][(n & 1) * 2]);
        }
    }

    // epilogue: bias + relu + hi/lo split -> g_c1h/g_c1l [row][oc]
#pragma unroll
    for (int m = 0; m < 4; m++) {
        size_t row = (size_t)r0 + warpm * 64 + m * 16 + (lane >> 2);
#pragma unroll
        for (int n = 0; n < 4; n++) {
            int oc = warpn * 32 + n * 8 + (lane & 3) * 2;
            float bias0 = b1[oc], bias1 = b1[oc + 1];
            float v00 = fmaxf(acc[m][n][0] + bias0, 0.f);
            float v01 = fmaxf(acc[m][n][1] + bias1, 0.f);
            float v10 = fmaxf(acc[m][n][2] + bias0, 0.f);
            float v11 = fmaxf(acc[m][n][3] + bias1, 0.f);
            __nv_bfloat16 h0, l0, h1, l1;
            __nv_bfloat162 th, tl;
            split_bf16(v00, h0, l0);
            split_bf16(v01, h1, l1);
            th.x = h0; th.y = h1; tl.x = l0; tl.y = l1;
            *(__nv_bfloat162*)(g_c1h + row * 256 + oc) = th;
            *(__nv_bfloat162*)(g_c1l + row * 256 + oc) = tl;
            split_bf16(v10, h0, l0);
            split_bf16(v11, h1, l1);
            th.x = h0; th.y = h1; tl.x = l0; tl.y = l1;
            *(__nv_bfloat162*)(g_c1h + (row + 8) * 256 + oc) = th;
            *(__nv_bfloat162*)(g_c1l + (row + 8) * 256 + oc) = tl;
        }
    }
}

// ---------------- conv2 via mma.sync bf16x3: 3-stage, 1 sync/stage ----------------
#define C2_STAGES 648
#define OFF_AH 0
#define OFF_AL 8192
#define OFF_BH 16384
#define OFF_BL 24576
#define C2_STAGE_BYTES 32768
#define CONV2_SMEM (3 * C2_STAGE_BYTES)

__device__ __forceinline__ void c2_load(uint32_t sb, int i, int oc0, int bb0,
                                        int oy, int ox, int tid) {
    const int tap = i >> 3, icc = i & 7, ic0 = icc * 32;
    const int ky = tap / 9, kx = tap % 9;
    const int pix = (2 * oy + ky) * 20 + 2 * ox + kx;
#pragma unroll
    for (int rep = 0; rep < 2; rep++) {
        int q = tid + rep * 256;
        int row = q >> 2, c = q & 3;
        uint32_t soff = row * 64 + ((c ^ ((row >> 1) & 3)) * 16);
        size_t aoff = (size_t)(oc0 + row) * 20736 + tap * 256 + ic0 + c * 8;
        cpa16(sb + OFF_AH + soff, g_w2h + aoff);
        cpa16(sb + OFF_AL + soff, g_w2l + aoff);
        size_t boff = ((size_t)pix * 512 + bb0 + row) * 256 + ic0 + c * 8;
        cpa16(sb + OFF_BH + soff, g_c1h + boff);
        cpa16(sb + OFF_BL + soff, g_c1l + boff);
    }
}

__global__ __launch_bounds__(256, 2) void k_conv2mma(const float* __restrict__ b2) {
    extern __shared__ __align__(1024) char smem[];
    const uint32_t sbase = smem_u32(smem);
    const int tid = threadIdx.x;
    const int wid = tid >> 5, lane = tid & 31;
    const int oc0 = (blockIdx.x >> 2) * 128;
    const int bb0 = (blockIdx.x & 3) * 128;
    const int s = blockIdx.y;
    const int oy = s / 6, ox = s % 6;
    const int warpm = wid >> 2, warpn = wid & 3;

    float acc[4][4][4];
#pragma unroll
    for (int m = 0; m < 4; m++)
#pragma unroll
        for (int n = 0; n < 4; n++)
#pragma unroll
            for (int k = 0; k < 4; k++) acc[m][n][k] = 0.f;

    uint32_t offA[4][2], offB[2][2];
#pragma unroll
    for (int m = 0; m < 4; m++)
#pragma unroll
        for (int kk = 0; kk < 2; kk++) {
            int row = warpm * 64 + m * 16 + (lane & 15);
            int lc = 2 * kk + (lane >> 4);
            offA[m][kk] = row * 64 + ((lc ^ ((row >> 1) & 3)) * 16);
        }
#pragma unroll
    for (int p = 0; p < 2; p++)
#pragma unroll
        for (int kk = 0; kk < 2; kk++) {
            int row = warpn * 32 + p * 16 + (lane & 7) + ((lane >> 4) & 1) * 8;
            int lc = 2 * kk + ((lane >> 3) & 1);
            offB[p][kk] = row * 64 + ((lc ^ ((row >> 1) & 3)) * 16);
        }

    uint32_t bufs[3] = {sbase, sbase + C2_STAGE_BYTES, sbase + 2 * C2_STAGE_BYTES};
    c2_load(bufs[0], 0, oc0, bb0, oy, ox, tid);
    CP_COMMIT();
    c2_load(bufs[1], 1, oc0, bb0, oy, ox, tid);
    CP_COMMIT();

    int cur = 0, nxt = 2;
    for (int i = 0; i < C2_STAGES; i++) {
        CP_WAIT1();
        __syncthreads();
        if (i + 2 < C2_STAGES) c2_load(bufs[nxt], i + 2, oc0, bb0, oy, ox, tid);
        CP_COMMIT();
        const uint32_t bb = bufs[cur];
        cur = (cur + 1 == 3) ? 0 : cur + 1;
        nxt = (nxt + 1 == 3) ? 0 : nxt + 1;
#pragma unroll
        for (int kk = 0; kk < 2; kk++) {
            uint32_t bh[2][4], blr[2][4];
            ldm4(bh[0], bb + OFF_BH + offB[0][kk]);
            ldm4(bh[1], bb + OFF_BH + offB[1][kk]);
            ldm4(blr[0], bb + OFF_BL + offB[0][kk]);
            ldm4(blr[1], bb + OFF_BL + offB[1][kk]);
#pragma unroll
            for (int mp = 0; mp < 2; mp++) {
                uint32_t ah[2][4], al[2][4];
                ldm4(ah[0], bb + OFF_AH + offA[2 * mp + 0][kk]);
                ldm4(ah[1], bb + OFF_AH + offA[2 * mp + 1][kk]);
                ldm4(al[0], bb + OFF_AL + offA[2 * mp + 0][kk]);
                ldm4(al[1], bb + OFF_AL + offA[2 * mp + 1][kk]);
#pragma unroll
                for (int mi = 0; mi < 2; mi++)
#pragma unroll
                    for (int n = 0; n < 4; n++)
                        mma_bf16(acc[2 * mp + mi][n], ah[mi], &bh[n >> 1][(n & 1) * 2]);
#pragma unroll
                for (int mi = 0; mi < 2; mi++)
#pragma unroll
                    for (int n = 0; n < 4; n++)
                        mma_bf16(acc[2 * mp + mi][n], ah[mi], &blr[n >> 1][(n & 1) * 2]);
#pragma unroll
                for (int mi = 0; mi < 2; mi++)
#pragma unroll
                    for (int n = 0; n < 4; n++)
                        mma_bf16(acc[2 * mp + mi][n], al[mi], &bh[n >> 1][(n & 1) * 2]);
            }
        }
    }

    // epilogue: add bias, write g_pose2[(oc*36+s)*512 + b]
#pragma unroll
    for (int m = 0; m < 4; m++) {
        int ocr = oc0 + warpm * 64 + m * 16 + (lane >> 2);
        float bias0 = b2[ocr], bias1 = b2[ocr + 8];
#pragma unroll
        for (int n = 0; n < 4; n++) {
            int bc = bb0 + warpn * 32 + n * 8 + (lane & 3) * 2;
            float2 v0 = {acc[m][n][0] + bias0, acc[m][n][1] + bias0};
            float2 v1 = {acc[m][n][2] + bias1, acc[m][n][3] + bias1};
            *(float2*)(g_pose2 + ((size_t)ocr * 36 + s) * 512 + bc) = v0;
            *(float2*)(g_pose2 + ((size_t)(ocr + 8) * 36 + s) * 512 + bc) = v1;
        }
    }
}

// ---------------- squash: pose2 [flat][b] -> u [b][n][d] ----------------
__global__ __launch_bounds__(512) void k_squash2() {
    int n = blockIdx.x, b = threadIdx.x;
    const float* src = g_pose2 + (size_t)(8 * n) * 512 + b;
    float p[8];
#pragma unroll
    for (int d = 0; d < 8; d++) p[d] = src[(size_t)d * 512];
    float sq = 0.f;
#pragma unroll
    for (int d = 0; d < 8; d++) sq += p[d] * p[d];
    float sc = sq / ((1.f + sq) * sqrtf(sq + 1e-8f));
    float4 o0 = {p[0] * sc, p[1] * sc, p[2] * sc, p[3] * sc};
    float4 o1 = {p[4] * sc, p[5] * sc, p[6] * sc, p[7] * sc};
    float4* dst = (float4*)(g_u + (size_t)b * 9216 + 8 * n);
    dst[0] = o0;
    dst[1] = o1;
}

// ---------------- u_hat GEMM ----------------
__global__ __launch_bounds__(256) void k_uhat(const float* __restrict__ W) {
    __shared__ float Ws[8192];
    __shared__ float us[512];
    int tid = threadIdx.x;
    int n0 = blockIdx.x * 64, c = blockIdx.y;
    int bs = blockIdx.z * 128;
    for (int l = tid; l < 8192; l += 256)
        Ws[l] = W[((size_t)c * 1152 + n0) * 128 + l];
    __syncthreads();
    for (int b = bs; b < bs + 128; b++) {
        for (int l = tid; l < 512; l += 256) us[l] = g_u[(size_t)b * 9216 + n0 * 8 + l];
        __syncthreads();
        float* dst = g_uhat + ((size_t)c * 512 + b) * 18432 + n0 * 16;
#pragma unroll
        for (int k = 0; k < 4; k++) {
            int q = tid + k * 256;
            int nl = q >> 4, e = q & 15;
            float a = 0.f;
#pragma unroll
            for (int d = 0; d < 8; d++) a += us[nl * 8 + d] * Ws[nl * 128 + d * 16 + e];
            dst[q] = a;
        }
        __syncthreads();
    }
}

// ---------------- routing iterations ----------------
#define ROUTE_SMEM ((18432 + 1152 + 1152 + 256 + 32 + 16 + 16) * 4)
__global__ __launch_bounds__(256) void k_route2() {
    extern __shared__ float sm[];
    float* uh = sm;
    float* bl = uh + 18432;
    float* cl = bl + 1152;
    float* sp = cl + 1152;
    float* red = sp + 256;
    float* sv = red + 32;
    float* vs = sv + 16;
    int tid = threadIdx.x;
    int c = blockIdx.x, b = blockIdx.y;
    int lane = tid & 31, wid = tid >> 5;

    const float4* src = (const float4*)(g_uhat + ((size_t)c * 512 + b) * 18432);
    float4* uh4 = (float4*)uh;
    for (int l = tid; l < 4608; l += 256) uh4[l] = src[l];
    for (int n = tid; n < 1152; n += 256) bl[n] = 0.f;
    __syncthreads();

    for (int it = 0; it < 3; it++) {
        float m = -1e30f;
        for (int n = tid; n < 1152; n += 256) m = fmaxf(m, bl[n]);
#pragma unroll
        for (int o = 16; o > 0; o >>= 1) m = fmaxf(m, __shfl_xor_sync(0xffffffffu, m, o));
        if (lane == 0) red[wid] = m;
        __syncthreads();
        if (tid == 0) {
            float t = red[0];
            for (int i = 1; i < 8; i++) t = fmaxf(t, red[i]);
            red[16] = t;
        }
        __syncthreads();
        m = red[16];
        float ps = 0.f;
        for (int n = tid; n < 1152; n += 256) {
            float e = expf(bl[n] - m);
            cl[n] = e;
            ps += e;
        }
#pragma unroll
        for (int o = 16; o > 0; o >>= 1) ps += __shfl_xor_sync(0xffffffffu, ps, o);
        if (lane == 0) red[wid] = ps;
        __syncthreads();
        if (tid == 0) {
            float t = 0.f;
            for (int i = 0; i < 8; i++) t += red[i];
            red[17] = t;
        }
        __syncthreads();
        float invS = 1.f / red[17];

        int e = tid & 15, g = tid >> 4;
        float part = 0.f;
        for (int n = g; n < 1152; n += 16) part += cl[n] * uh[n * 16 + e];
        sp[tid] = part;
        __syncthreads();
        if (tid < 16) {
            float t = 0.f;
            for (int gg = 0; gg < 16; gg++) t += sp[gg * 16 + tid];
            sv[tid] = t * invS;
        }
        __syncthreads();
        if (tid == 0) {
            float sq = 0.f;
            for (int i = 0; i < 16; i++) sq += sv[i] * sv[i];
            red[18] = sq / ((1.f + sq) * sqrtf(sq + 1e-8f));
        }
        __syncthreads();
        if (tid < 16) vs[tid] = sv[tid] * red[18];
        __syncthreads();

        if (it < 2) {
            const float4* vv = (const float4*)vs;
            float4 v0 = vv[0], v1 = vv[1], v2 = vv[2], v3 = vv[3];
            for (int n = tid; n < 1152; n += 256) {
                const float4* u4 = uh4 + n * 4;
                float4 a = u4[0], bq = u4[1], cq = u4[2], dq = u4[3];
                float dot = a.x * v0.x + a.y * v0.y + a.z * v0.z + a.w * v0.w +
                            bq.x * v1.x + bq.y * v1.y + bq.z * v1.z + bq.w * v1.w +
                            cq.x * v2.x + cq.y * v2.y + cq.z * v2.z + cq.w * v2.w +
                            dq.x * v3.x + dq.y * v3.y + dq.z * v3.z + dq.w * v3.w;
                bl[n] += dot;
            }
            __syncthreads();
        }
    }
    if (tid < 16) g_v[((size_t)b * 10 + c) * 16 + tid] = vs[tid];
}

// ---------------- class probs + masked decoder ----------------
__global__ __launch_bounds__(256) void k_dec(const float* __restrict__ d1w,
                                             const float* __restrict__ d1b,
                                             const float* __restrict__ d2b,
                                             const float* __restrict__ d3b,
                                             float* __restrict__ out) {
    __shared__ __align__(16) float v_s[4][160];
    __shared__ __align__(16) float h1s[4][512];
    __shared__ __align__(16) float h2s[4][1024];
    __shared__ float nrm[4][10];
    __shared__ float cps[4][10];
    __shared__ int args[4];
    int tid = threadIdx.x;
    int b0 = blockIdx.x * 4;

    for (int bb = 0; bb < 4; bb++)
        for (int i = tid; i < 160; i += 256) v_s[bb][i] = g_v[(size_t)(b0 + bb) * 160 + i];
    __syncthreads();

    if (tid < 40) {
        int bb = tid / 10, c = tid % 10;
        float s = 0.f;
#pragma unroll
        for (int e = 0; e < 16; e++) {
            float t = v_s[bb][c * 16 + e];
            s += t * t;
        }
        nrm[bb][c] = sqrtf(s);
    }
    __syncthreads();
    if (tid < 4) {
        int bb = tid;
        float m = -1e30f;
        int a = 0;
        for (int c = 0; c < 10; c++)
            if (nrm[bb][c] > m) { m = nrm[bb][c]; a = c; }
        args[bb] = a;
        float ex[10], s = 0.f;
        for (int c = 0; c < 10; c++) { ex[c] = expf(nrm[bb][c] - m); s += ex[c]; }
        for (int c = 0; c < 10; c++) cps[bb][c] = ex[c] / s;
    }
    __syncthreads();
    if (tid < 40) {
        int bb = tid / 10, c = tid % 10;
        out[(size_t)(b0 + bb) * 10 + c] = cps[bb][c];
    }

    for (int bb = 0; bb < 4; bb++) {
        int a = args[bb];
        const float* vp = &v_s[bb][a * 16];
        for (int j = tid; j < 512; j += 256) {
            const float* wp = d1w + (size_t)j * 160 + a * 16;
            float acc = d1b[j];
#pragma unroll
            for (int e = 0; e < 16; e++) acc += vp[e] * wp[e];
            h1s[bb][j] = fmaxf(acc, 0.f);
        }
    }
    __syncthreads();

    int w = tid >> 5, lane = tid & 31;
    {
        int k0 = w * 128 + lane * 4;
        float acc[4][4];
#pragma unroll
        for (int bb = 0; bb < 4; bb++)
#pragma unroll
            for (int kk = 0; kk < 4; kk++) acc[bb][kk] = 0.f;
        for (int j = 0; j < 512; j += 4) {
            float4 w0 = *(const float4*)(g_d2t + (size_t)(j + 0) * 1024 + k0);
            float4 w1 = *(const float4*)(g_d2t + (size_t)(j + 1) * 1024 + k0);
            float4 w2 = *(const float4*)(g_d2t + (size_t)(j + 2) * 1024 + k0);
            float4 w3 = *(const float4*)(g_d2t + (size_t)(j + 3) * 1024 + k0);
#pragma unroll
            for (int bb = 0; bb < 4; bb++) {
                float4 hv = *(const float4*)&h1s[bb][j];
                acc[bb][0] += hv.x * w0.x + hv.y * w1.x + hv.z * w2.x + hv.w * w3.x;
                acc[bb][1] += hv.x * w0.y + hv.y * w1.y + hv.z * w2.y + hv.w * w3.y;
                acc[bb][2] += hv.x * w0.z + hv.y * w1.z + hv.z * w2.z + hv.w * w3.z;
                acc[bb][3] += hv.x * w0.w + hv.y * w1.w + hv.z * w2.w + hv.w * w3.w;
            }
        }
        float bk0 = d2b[k0], bk1 = d2b[k0 + 1], bk2 = d2b[k0 + 2], bk3 = d2b[k0 + 3];
#pragma unroll
        for (int bb = 0; bb < 4; bb++) {
            h2s[bb][k0 + 0] = fmaxf(acc[bb][0] + bk0, 0.f);
            h2s[bb][k0 + 1] = fmaxf(acc[bb][1] + bk1, 0.f);
            h2s[bb][k0 + 2] = fmaxf(acc[bb][2] + bk2, 0.f);
            h2s[bb][k0 + 3] = fmaxf(acc[bb][3] + bk3, 0.f);
        }
    }
    __syncthreads();

    {
        int r0 = w * 128 + lane * 4;
        if (r0 < 784) {
            float acc[4][4];
#pragma unroll
            for (int bb = 0; bb < 4; bb++)
#pragma unroll
                for (int kk = 0; kk < 4; kk++) acc[bb][kk] = 0.f;
            for (int k = 0; k < 1024; k += 4) {
                float4 w0 = *(const float4*)(g_d3t + (size_t)(k + 0) * 784 + r0);
                float4 w1 = *(const float4*)(g_d3t + (size_t)(k + 1) * 784 + r0);
                float4 w2 = *(const float4*)(g_d3t + (size_t)(k + 2) * 784 + r0);
                float4 w3 = *(const float4*)(g_d3t + (size_t)(k + 3) * 784 + r0);
#pragma unroll
                for (int bb = 0; bb < 4; bb++) {
                    float4 hv = *(const float4*)&h2s[bb][k];
                    acc[bb][0] += hv.x * w0.x + hv.y * w1.x + hv.z * w2.x + hv.w * w3.x;
                    acc[bb][1] += hv.x * w0.y + hv.y * w1.y + hv.z * w2.y + hv.w * w3.y;
                    acc[bb][2] += hv.x * w0.z + hv.y * w1.z + hv.z * w2.z + hv.w * w3.z;
                    acc[bb][3] += hv.x * w0.w + hv.y * w1.w + hv.z * w2.w + hv.w * w3.w;
                }
            }
            float b0r = d3b[r0], b1r = d3b[r0 + 1], b2r = d3b[r0 + 2], b3r = d3b[r0 + 3];
#pragma unroll
            for (int bb = 0; bb < 4; bb++) {
                float4 o;
                o.x = 1.f / (1.f + expf(-(acc[bb][0] + b0r)));
                o.y = 1.f / (1.f + expf(-(acc[bb][1] + b1r)));
                o.z = 1.f / (1.f + expf(-(acc[bb][2] + b2r)));
                o.w = 1.f / (1.f + expf(-(acc[bb][3] + b3r)));
                *(float4*)(out + 5120 + (size_t)(b0 + bb) * 784 + r0) = o;
            }
        }
    }
}

// ---------------- launch ----------------
extern "C" void kernel_launch(void* const* d_in, const int* in_sizes, int n_in,
                              void* d_out, int out_size) {
    const float* x = (const float*)d_in[0];
    const float* w1 = (const float*)d_in[1];
    const float* b1 = (const float*)d_in[2];
    const float* w2 = (const float*)d_in[3];
    const float* b2 = (const float*)d_in[4];
    const float* W = (const float*)d_in[5];
    const float* d1w = (const float*)d_in[6];
    const float* d1b = (const float*)d_in[7];
    const float* d2b = (const float*)d_in[9];
    const float* d3b = (const float*)d_in[11];
    float* out = (float*)d_out;
    (void)in_sizes; (void)n_in; (void)out_size;

    cudaFuncSetAttribute(k_conv1mma, cudaFuncAttributeMaxDynamicSharedMemorySize, CONV1_SMEM);
    cudaFuncSetAttribute(k_conv2mma, cudaFuncAttributeMaxDynamicSharedMemorySize, CONV2_SMEM);
    cudaFuncSetAttribute(k_route2, cudaFuncAttributeMaxDynamicSharedMemorySize, ROUTE_SMEM);

    k_prep<<<20736, 256>>>(w1, w2, (const float*)d_in[8], (const float*)d_in[10]);
    k_im2col<<<512, 256>>>(x);
    k_conv1mma<<<1600, 512, CONV1_SMEM>>>(b1);
    k_conv2mma<<<dim3(8, 36), 256, CONV2_SMEM>>>(b2);
    k_squash2<<<1152, 512>>>();
    k_uhat<<<dim3(18, 10, 4), 256>>>(W);
    k_route2<<<dim3(10, 512), 256, ROUTE_SMEM>>>();
    k_dec<<<128, 256>>>(d1w, d1b, d2b, d3b, out);
}